// round 7
// baseline (speedup 1.0000x reference)
#include <cuda_runtime.h>
#include <cuda_fp16.h>
#include <cstdint>

#define SEQ   2048
#define HDIM  64
#define NHEAD 8
#define CDIM  512
#define NBH   16            // B*H
#define QKSCALE 0.125f
#define KP    24            // smem tile pitch in halfs (48B, ldmatrix conflict-free)
#define PLANE (64 * KP)     // halfs per 64x16 padded tile

constexpr int NQe = NBH * SEQ * HDIM;   // 2,097,152 elements per plane
constexpr int MROWS = 2 * SEQ;          // 4096 projection rows

// ---------------- scratch (device globals; no allocation) ----------------
__device__ __half g_In2[2 * MROWS * CDIM];        // split input (q/k/v/X reuse)
__device__ __half g_W2[2 * CDIM * CDIM];          // split weight (reused)
__device__ __half g_Qh2[2 * NBH * SEQ * HDIM];    // hi/lo fp16 planes
__device__ __half g_Kh2[2 * NBH * SEQ * HDIM];
__device__ __half g_Vt2[2 * NBH * HDIM * SEQ];    // V transposed [bh][d][s]
__device__ __half g_X2[2 * MROWS * CDIM];         // attention output, split
__device__ float g_S[(size_t)NBH * SEQ * SEQ];    // 268 MB
__device__ int   g_q2k[NBH * SEQ];
__device__ int   g_k2q[NBH * SEQ];
__device__ float g_madd[NBH * SEQ];
__device__ float g_rpv[NBH * 32 * SEQ];
__device__ int   g_rpi[NBH * 32 * SEQ];
__device__ float g_cpv[NBH * 32 * SEQ];
__device__ int   g_cpi[NBH * 32 * SEQ];

// fast exp on the FMA pipe. |rel err| ~1e-7.
__device__ __forceinline__ float fexp(float x) {
    float y = x * 1.4426950408889634f;
    y = fminf(fmaxf(y, -126.0f), 126.0f);
    float t = y + 12582912.0f;
    int   e = __float_as_int(t) - 0x4B400000;
    float r = t - 12582912.0f;
    float f = y - r;
    float p = 1.535336188319500e-4f;
    p = fmaf(p, f, 1.339887440266574e-3f);
    p = fmaf(p, f, 9.618437357674640e-3f);
    p = fmaf(p, f, 5.550332471162809e-2f);
    p = fmaf(p, f, 2.402264791363012e-1f);
    p = fmaf(p, f, 6.931472028550421e-1f);
    p = fmaf(p, f, 1.0f);
    return p * __int_as_float((e + 127) << 23);
}

#define MMA_F16(d, a, b0, b1)                                               \
    asm volatile("mma.sync.aligned.m16n8k16.row.col.f32.f16.f16.f32 "        \
                 "{%0,%1,%2,%3}, {%4,%5,%6,%7}, {%8,%9}, {%0,%1,%2,%3};"     \
                 : "+f"((d)[0]), "+f"((d)[1]), "+f"((d)[2]), "+f"((d)[3])    \
                 : "r"((a)[0]), "r"((a)[1]), "r"((a)[2]), "r"((a)[3]),       \
                   "r"(b0), "r"(b1))

#define LDM4(r, addr)                                                        \
    asm volatile("ldmatrix.sync.aligned.m8n8.x4.shared.b16 {%0,%1,%2,%3}, [%4];" \
                 : "=r"((r)[0]), "=r"((r)[1]), "=r"((r)[2]), "=r"((r)[3])    \
                 : "r"(addr))

__device__ __forceinline__ uint32_t pack_h2(float a, float b) {
    __half2 t;
    t.x = __float2half_rn(a);
    t.y = __float2half_rn(b);
    return *(uint32_t*)&t;
}

// ---------------- fp32 -> fp16 split-2 planes ----------------------------
__global__ void cvt_split_kernel(const float* __restrict__ in,
                                 __half* __restrict__ out, int n)
{
    int i = blockIdx.x * blockDim.x + threadIdx.x;
    if (i >= n) return;
    float x = in[i];
    __half h = __float2half_rn(x);
    out[i] = h;
    out[n + i] = __float2half_rn(x - __half2float(h));
}

// ---- projection GEMM via fp16 split-2 mma: C = A @ W^T ------------------
// mode 0/1: split-plane scatter into g_Qh2/g_Kh2 [b,h,n,d]
// mode 2:   split-plane scatter into g_Vt2 [b,h,d,n] (transposed)
// mode 3:   fp32 row-major outPlain [4096,512]
__global__ void __launch_bounds__(128) proj_mma_kernel(
    const __half* __restrict__ A2, const __half* __restrict__ W2,
    float* __restrict__ outPlain, int mode)
{
    __shared__ __align__(16) __half sAB[8 * PLANE];   // double-buffered 4 planes
    const int tid = threadIdx.x, lane = tid & 31, w = tid >> 5;
    const int wm = (w & 1) << 5, wn = (w >> 1) << 5;
    const int r0 = blockIdx.y << 6, c0 = blockIdx.x << 6;
    constexpr int MK = MROWS * CDIM;
    constexpr int NK = CDIM * CDIM;

    const __half* ap[2] = {
        A2 + (size_t)(r0 + (tid >> 1)) * CDIM + (tid & 1) * 8,
        A2 + MK + (size_t)(r0 + (tid >> 1)) * CDIM + (tid & 1) * 8 };
    const __half* wp[2] = {
        W2 + (size_t)(c0 + (tid >> 1)) * CDIM + (tid & 1) * 8,
        W2 + NK + (size_t)(c0 + (tid >> 1)) * CDIM + (tid & 1) * 8 };
    const int sts = (tid >> 1) * KP + (tid & 1) * 8;

    uint32_t sbase = (uint32_t)__cvta_generic_to_shared(sAB);
    const int lrow = (lane & 7) + ((lane >> 3) & 1) * 8;
    const int lk = (lane >> 4) * 8;
    uint32_t adA[2][2], adB[2][2];
#pragma unroll
    for (int p = 0; p < 2; p++)
#pragma unroll
        for (int t = 0; t < 2; t++) {
            adA[p][t] = sbase + 2 * (p * PLANE + (wm + 16 * t + lrow) * KP + lk);
            adB[p][t] = sbase + 2 * ((2 + p) * PLANE + (wn + 16 * t + lrow) * KP + lk);
        }
    const uint32_t bufB = 4 * PLANE * 2;   // bytes per buffer

    float acc[2][4][4] = {};
    uint4 avv[2], wvv[2];
#pragma unroll
    for (int p = 0; p < 2; p++) { avv[p] = *(const uint4*)ap[p]; wvv[p] = *(const uint4*)wp[p]; }

#pragma unroll 1
    for (int ks = 0; ks < 32; ks++) {
        const int buf = ks & 1;
        __half* sb = sAB + buf * 4 * PLANE;
        *(uint4*)&sb[0 * PLANE + sts] = avv[0];
        *(uint4*)&sb[1 * PLANE + sts] = avv[1];
        *(uint4*)&sb[2 * PLANE + sts] = wvv[0];
        *(uint4*)&sb[3 * PLANE + sts] = wvv[1];
        if (ks < 31) {
#pragma unroll
            for (int p = 0; p < 2; p++) {
                avv[p] = *(const uint4*)(ap[p] + (ks + 1) * 16);
                wvv[p] = *(const uint4*)(wp[p] + (ks + 1) * 16);
            }
        }
        __syncthreads();

        uint32_t afr[2][2][4], bfr[2][2][4];
#pragma unroll
        for (int p = 0; p < 2; p++)
#pragma unroll
            for (int t = 0; t < 2; t++) {
                LDM4(afr[p][t], adA[p][t] + buf * bufB);
                LDM4(bfr[p][t], adB[p][t] + buf * bufB);
            }

        const int pa[3] = {0, 0, 1};
        const int pb[3] = {0, 1, 0};
#pragma unroll
        for (int c = 0; c < 3; c++)
#pragma unroll
            for (int mt = 0; mt < 2; mt++)
#pragma unroll
                for (int nt = 0; nt < 4; nt++) {
                    int n2 = nt >> 1, j = nt & 1;
                    MMA_F16(acc[mt][nt], afr[pa[c]][mt], bfr[pb[c]][n2][j], bfr[pb[c]][n2][j + 2]);
                }
    }

    // epilogue
    __half* OH = (mode == 0) ? g_Qh2 : ((mode == 1) ? g_Kh2 : g_Vt2);
#pragma unroll
    for (int mt = 0; mt < 2; mt++)
#pragma unroll
        for (int nt = 0; nt < 4; nt++) {
#pragma unroll
            for (int half2nd = 0; half2nd < 2; half2nd++) {
                int row = r0 + wm + 16 * mt + (lane >> 2) + half2nd * 8;
                int col = c0 + wn + 8 * nt + 2 * (lane & 3);
                float v0 = acc[mt][nt][half2nd * 2];
                float v1 = acc[mt][nt][half2nd * 2 + 1];
                if (mode == 3) {
                    *(float2*)&outPlain[(size_t)row * CDIM + col] = make_float2(v0, v1);
                } else {
                    int b = row >> 11, n = row & 2047;
                    int hh = col >> 6, d = col & 63;
                    __half h0 = __float2half_rn(v0), h1 = __float2half_rn(v1);
                    __half l0 = __float2half_rn(v0 - __half2float(h0));
                    __half l1 = __float2half_rn(v1 - __half2float(h1));
                    if (mode == 2) {
                        size_t idx = ((size_t)((b << 3) + hh) * HDIM + d) * SEQ + n;
                        OH[idx] = h0; OH[idx + SEQ] = h1;
                        OH[NQe + idx] = l0; OH[NQe + idx + SEQ] = l1;
                    } else {
                        size_t idx = ((size_t)((b << 3) + hh) * SEQ + n) * HDIM + d;
                        __half2 hv; hv.x = h0; hv.y = h1;
                        __half2 lv; lv.x = l0; lv.y = l1;
                        *(__half2*)&OH[idx] = hv;
                        *(__half2*)&OH[NQe + idx] = lv;
                    }
                }
            }
        }
}

// ---- S = (Qh @ Kh^T)*SCALE via fp16 split-2 MMA + fused tile argmax -----
__global__ void __launch_bounds__(128) qk_mma_kernel()
{
    __shared__ __align__(16) unsigned char smraw[6 * PLANE * 2];  // 18432 B
    __half* sAB = (__half*)smraw;
    float* Ssm = (float*)smraw;                                   // 64x68 fp32 epilogue

    const int bh = blockIdx.z;
    const int r0 = blockIdx.y << 6, c0 = blockIdx.x << 6;
    const int tid = threadIdx.x, lane = tid & 31, w = tid >> 5;
    const int wm = (w & 1) << 5, wn = (w >> 1) << 5;

    const size_t qoff = (size_t)bh * SEQ * HDIM + (size_t)(r0 + (tid >> 1)) * HDIM + (tid & 1) * 8;
    const size_t koff = (size_t)bh * SEQ * HDIM + (size_t)(c0 + (tid >> 1)) * HDIM + (tid & 1) * 8;
    const __half* qp[2] = { g_Qh2 + qoff, g_Qh2 + (size_t)NQe + qoff };
    const __half* kp[2] = { g_Kh2 + koff, g_Kh2 + (size_t)NQe + koff };
    const int sts = (tid >> 1) * KP + (tid & 1) * 8;

    uint32_t sbase = (uint32_t)__cvta_generic_to_shared(sAB);
    const int lrow = (lane & 7) + ((lane >> 3) & 1) * 8;
    const int lk = (lane >> 4) * 8;
    uint32_t adA[2][2], adB[2][2];
#pragma unroll
    for (int p = 0; p < 2; p++)
#pragma unroll
        for (int t = 0; t < 2; t++) {
            adA[p][t] = sbase + 2 * (p * PLANE + (wm + 16 * t + lrow) * KP + lk);
            adB[p][t] = sbase + 2 * ((2 + p) * PLANE + (wn + 16 * t + lrow) * KP + lk);
        }

    float acc[2][4][4] = {};

#pragma unroll 1
    for (int ks = 0; ks < 4; ks++) {
        uint4 qv[2], kv[2];
#pragma unroll
        for (int p = 0; p < 2; p++) {
            qv[p] = *(const uint4*)(qp[p] + ks * 16);
            kv[p] = *(const uint4*)(kp[p] + ks * 16);
        }
        __syncthreads();
#pragma unroll
        for (int p = 0; p < 2; p++) {
            *(uint4*)&sAB[p * PLANE + sts] = qv[p];
            *(uint4*)&sAB[(2 + p) * PLANE + sts] = kv[p];
        }
        __syncthreads();

        uint32_t afr[2][2][4], bfr[2][2][4];
#pragma unroll
        for (int p = 0; p < 2; p++)
#pragma unroll
            for (int t = 0; t < 2; t++) { LDM4(afr[p][t], adA[p][t]); LDM4(bfr[p][t], adB[p][t]); }

        const int pa[3] = {0, 0, 1};
        const int pb[3] = {0, 1, 0};
#pragma unroll
        for (int c = 0; c < 3; c++)
#pragma unroll
            for (int mt = 0; mt < 2; mt++)
#pragma unroll
                for (int nt = 0; nt < 4; nt++) {
                    int n2 = nt >> 1, j = nt & 1;
                    MMA_F16(acc[mt][nt], afr[pa[c]][mt], bfr[pb[c]][n2][j], bfr[pb[c]][n2][j + 2]);
                }
    }

    __syncthreads();
#pragma unroll
    for (int mt = 0; mt < 2; mt++) {
        int row0 = wm + 16 * mt + (lane >> 2);
#pragma unroll
        for (int nt = 0; nt < 4; nt++) {
            int col = wn + 8 * nt + 2 * (lane & 3);
            *(float2*)&Ssm[row0 * 68 + col] =
                make_float2(acc[mt][nt][0] * QKSCALE, acc[mt][nt][1] * QKSCALE);
            *(float2*)&Ssm[(row0 + 8) * 68 + col] =
                make_float2(acc[mt][nt][2] * QKSCALE, acc[mt][nt][3] * QKSCALE);
        }
    }
    __syncthreads();

    float* Sp = g_S + (size_t)bh * SEQ * SEQ;
    {
        int row = tid >> 1, cb = (tid & 1) * 32;
#pragma unroll
        for (int i = 0; i < 8; i++)
            *(float4*)&Sp[(size_t)(r0 + row) * SEQ + c0 + cb + 4 * i] =
                *(const float4*)&Ssm[row * 68 + cb + 4 * i];
    }

    if (tid < 64) {
        float best = -3e38f; int bi = 0;
#pragma unroll
        for (int i = 0; i < 16; i++) {
            float4 v = *(const float4*)&Ssm[tid * 68 + 4 * i];
            if (v.x > best) { best = v.x; bi = 4 * i; }
            if (v.y > best) { best = v.y; bi = 4 * i + 1; }
            if (v.z > best) { best = v.z; bi = 4 * i + 2; }
            if (v.w > best) { best = v.w; bi = 4 * i + 3; }
        }
        size_t p = (size_t)((bh << 5) + blockIdx.x) * SEQ + r0 + tid;
        g_rpv[p] = best; g_rpi[p] = c0 + bi;
    } else {
        int c = tid - 64;
        float best = -3e38f; int bi = 0;
#pragma unroll 8
        for (int i = 0; i < 64; i++) {
            float v = Ssm[i * 68 + c];
            if (v > best) { best = v; bi = i; }
        }
        size_t p = (size_t)((bh << 5) + blockIdx.y) * SEQ + c0 + c;
        g_cpv[p] = best; g_cpi[p] = r0 + bi;
    }
}

// ---------------- reduce 32 partials -> q2k and k2q ----------------------
__global__ void argmax_reduce_kernel()
{
    int gid = blockIdx.x * blockDim.x + threadIdx.x;
    int which = gid >= NBH * SEQ;
    int i = gid & (NBH * SEQ - 1);
    int bh = i >> 11, n = i & 2047;
    const float* pv = which ? g_cpv : g_rpv;
    const int*   pi = which ? g_cpi : g_rpi;
    float v = -3e38f; int idx = 0;
#pragma unroll 8
    for (int t = 0; t < 32; t++) {
        size_t p = (size_t)((bh << 5) + t) * SEQ + n;
        float ov = pv[p];
        if (ov > v) { v = ov; idx = pi[p]; }
    }
    (which ? g_k2q : g_q2k)[i] = idx;
}

// ---------------- cycle consistency -> additive mask ---------------------
__global__ void asso_kernel(const int* __restrict__ smask,
                            const float* __restrict__ svalid)
{
    int i = blockIdx.x * blockDim.x + threadIdx.x;
    int bh = i >> 11, m = i & 2047;
    int b = bh >> 3;
    int kq = g_k2q[i];
    int remap = g_q2k[(bh << 11) + kq];
    float valid = (smask[(b << 11) + m] == smask[(b << 11) + remap])
                      ? svalid[(b << 11) + m] : 1.0f;
    g_madd[i] = valid * -10000.0f;
}

// ---- fused exp + online row-sum + P@V, single-sync double-buffered ------
// writes X as split fp16 planes g_X2
__global__ void __launch_bounds__(128) av_mma_kernel()
{
    __shared__ __align__(16) __half sAB[8 * PLANE];   // 2 buffers x (Ph,Pl,Vh,Vl)
    __shared__ float sL[64];

    const int bh = blockIdx.y;
    const int n0 = blockIdx.x << 6;
    const int b = bh >> 3, h = bh & 7;
    const int tid = threadIdx.x, lane = tid & 31, w = tid >> 5;
    const int wm = (w & 1) << 5, wn = (w >> 1) << 5;

    const float* Sp = g_S + (size_t)bh * SEQ * SEQ + (size_t)(n0 + (tid >> 1)) * SEQ + (tid & 1) * 8;
    const float* mp = g_madd + bh * SEQ + (tid & 1) * 8;
    const size_t voff = (size_t)bh * HDIM * SEQ + (size_t)(tid >> 1) * SEQ + (tid & 1) * 8;
    const __half* vp[2] = { g_Vt2 + voff, g_Vt2 + (size_t)NQe + voff };
    const int sts = (tid >> 1) * KP + (tid & 1) * 8;

    uint32_t sbase = (uint32_t)__cvta_generic_to_shared(sAB);
    const int lrow = (lane & 7) + ((lane >> 3) & 1) * 8;
    const int lk = (lane >> 4) * 8;
    uint32_t adA[2][2], adB[2][2];
#pragma unroll
    for (int p = 0; p < 2; p++)
#pragma unroll
        for (int t = 0; t < 2; t++) {
            adA[p][t] = sbase + 2 * (p * PLANE + (wm + 16 * t + lrow) * KP + lk);
            adB[p][t] = sbase + 2 * ((2 + p) * PLANE + (wn + 16 * t + lrow) * KP + lk);
        }
    const uint32_t bufB = 4 * PLANE * 2;

    float acc[2][4][4] = {};
    float runL = 0.0f;

#pragma unroll 1
    for (int ks = 0; ks < 128; ks++) {
        const int buf = ks & 1;
        float4 s0 = *(const float4*)(Sp + ks * 16);
        float4 s1 = *(const float4*)(Sp + ks * 16 + 4);
        float4 m0 = *(const float4*)(mp + ks * 16);
        float4 m1 = *(const float4*)(mp + ks * 16 + 4);
        uint4 v0 = *(const uint4*)(vp[0] + ks * 16);
        uint4 v1 = *(const uint4*)(vp[1] + ks * 16);

        float pv[8];
        pv[0] = fexp(s0.x + m0.x); pv[1] = fexp(s0.y + m0.y);
        pv[2] = fexp(s0.z + m0.z); pv[3] = fexp(s0.w + m0.w);
        pv[4] = fexp(s1.x + m1.x); pv[5] = fexp(s1.y + m1.y);
        pv[6] = fexp(s1.z + m1.z); pv[7] = fexp(s1.w + m1.w);
        runL += ((pv[0] + pv[1]) + (pv[2] + pv[3])) + ((pv[4] + pv[5]) + (pv[6] + pv[7]));

        uint4 ph, pl;
        float hs[8];
#pragma unroll
        for (int i = 0; i < 8; i++)
            hs[i] = __half2float(__float2half_rn(pv[i]));
        ph.x = pack_h2(pv[0], pv[1]); ph.y = pack_h2(pv[2], pv[3]);
        ph.z = pack_h2(pv[4], pv[5]); ph.w = pack_h2(pv[6], pv[7]);
        pl.x = pack_h2(pv[0] - hs[0], pv[1] - hs[1]);
        pl.y = pack_h2(pv[2] - hs[2], pv[3] - hs[3]);
        pl.z = pack_h2(pv[4] - hs[4], pv[5] - hs[5]);
        pl.w = pack_h2(pv[6] - hs[6], pv[7] - hs[7]);

        __half* sb = sAB + buf * 4 * PLANE;
        *(uint4*)&sb[0 * PLANE + sts] = ph;
        *(uint4*)&sb[1 * PLANE + sts] = pl;
        *(uint4*)&sb[2 * PLANE + sts] = v0;
        *(uint4*)&sb[3 * PLANE + sts] = v1;
        __syncthreads();

        uint32_t afr[2][2][4], bfr[2][2][4];
#pragma unroll
        for (int p = 0; p < 2; p++)
#pragma unroll
            for (int t = 0; t < 2; t++) {
                LDM4(afr[p][t], adA[p][t] + buf * bufB);
                LDM4(bfr[p][t], adB[p][t] + buf * bufB);
            }

        const int pa[3] = {0, 0, 1};
        const int pb[3] = {0, 1, 0};
#pragma unroll
        for (int c = 0; c < 3; c++)
#pragma unroll
            for (int mt = 0; mt < 2; mt++)
#pragma unroll
                for (int nt = 0; nt < 4; nt++) {
                    int n2 = nt >> 1, j = nt & 1;
                    MMA_F16(acc[mt][nt], afr[pa[c]][mt], bfr[pb[c]][n2][j], bfr[pb[c]][n2][j + 2]);
                }
    }

    runL += __shfl_xor_sync(0xffffffffu, runL, 1);
    if (!(tid & 1)) sL[tid >> 1] = runL;
    __syncthreads();

    constexpr int NX = MROWS * CDIM;
#pragma unroll
    for (int mt = 0; mt < 2; mt++) {
        int row0 = wm + 16 * mt + (lane >> 2);
        float inv0 = 1.0f / sL[row0];
        float inv1 = 1.0f / sL[row0 + 8];
#pragma unroll
        for (int nt = 0; nt < 4; nt++) {
            int col = wn + 8 * nt + 2 * (lane & 3);
            int n = n0 + row0;
            float x0 = acc[mt][nt][0] * inv0, x1 = acc[mt][nt][1] * inv0;
            float x2 = acc[mt][nt][2] * inv1, x3 = acc[mt][nt][3] * inv1;
            size_t i0 = (size_t)(b * SEQ + n) * CDIM + h * HDIM + col;
            size_t i1 = (size_t)(b * SEQ + n + 8) * CDIM + h * HDIM + col;
            __half h0 = __float2half_rn(x0), h1 = __float2half_rn(x1);
            __half h2 = __float2half_rn(x2), h3 = __float2half_rn(x3);
            *(uint32_t*)&g_X2[i0] = pack_h2(x0, x1);
            *(uint32_t*)&g_X2[i1] = pack_h2(x2, x3);
            *(uint32_t*)&g_X2[NX + i0] =
                pack_h2(x0 - __half2float(h0), x1 - __half2float(h1));
            *(uint32_t*)&g_X2[NX + i1] =
                pack_h2(x2 - __half2float(h2), x3 - __half2float(h3));
        }
    }
}

// ---------------- launcher ------------------------------------------------
extern "C" void kernel_launch(void* const* d_in, const int* in_sizes, int n_in,
                              void* d_out, int out_size)
{
    const float* q   = (const float*)d_in[0];
    const float* k   = (const float*)d_in[1];
    const float* v   = (const float*)d_in[2];
    const float* svm = (const float*)d_in[3];
    const int*   sm  = (const int*)d_in[4];
    const float* Wq  = (const float*)d_in[5];
    const float* Wk  = (const float*)d_in[6];
    const float* Wv  = (const float*)d_in[7];
    const float* Wp  = (const float*)d_in[8];
    float* out = (float*)d_out;

    __half *In2, *W2, *X2;
    cudaGetSymbolAddress((void**)&In2, g_In2);
    cudaGetSymbolAddress((void**)&W2, g_W2);
    cudaGetSymbolAddress((void**)&X2, g_X2);

    constexpr int NIN = MROWS * CDIM;      // 2,097,152
    constexpr int NW = CDIM * CDIM;        // 262,144
    dim3 gp(CDIM / 64, MROWS / 64);        // (8, 64)

    cvt_split_kernel<<<NIN / 256, 256>>>(q, In2, NIN);
    cvt_split_kernel<<<NW / 256, 256>>>(Wq, W2, NW);
    proj_mma_kernel<<<gp, 128>>>(In2, W2, nullptr, 0);

    cvt_split_kernel<<<NIN / 256, 256>>>(k, In2, NIN);
    cvt_split_kernel<<<NW / 256, 256>>>(Wk, W2, NW);
    proj_mma_kernel<<<gp, 128>>>(In2, W2, nullptr, 1);

    cvt_split_kernel<<<NIN / 256, 256>>>(v, In2, NIN);
    cvt_split_kernel<<<NW / 256, 256>>>(Wv, W2, NW);
    proj_mma_kernel<<<gp, 128>>>(In2, W2, nullptr, 2);

    qk_mma_kernel<<<dim3(SEQ / 64, SEQ / 64, NBH), 128>>>();

    argmax_reduce_kernel<<<(2 * NBH * SEQ) / 256, 256>>>();
    asso_kernel<<<(NBH * SEQ) / 256, 256>>>(sm, svm);

    av_mma_kernel<<<dim3(SEQ / 64, NBH), 128>>>();

    cvt_split_kernel<<<NW / 256, 256>>>(Wp, W2, NW);
    proj_mma_kernel<<<gp, 128>>>(X2, W2, out, 3);
}

// round 8
// speedup vs baseline: 1.2580x; 1.2580x over previous
#include <cuda_runtime.h>
#include <cuda_fp16.h>
#include <cstdint>

#define SEQ   2048
#define HDIM  64
#define NHEAD 8
#define CDIM  512
#define NBH   16            // B*H
#define QKSCALE 0.125f
#define KP    24            // smem tile pitch in halfs (48B, ldmatrix conflict-free)
#define PLANE (64 * KP)     // halfs per 64x16 padded tile

constexpr int NQe = NBH * SEQ * HDIM;   // 2,097,152 elements per plane

// ---------------- scratch (device globals; no allocation) ----------------
__device__ __half g_Qh2[2 * NBH * SEQ * HDIM];    // hi/lo fp16 planes
__device__ __half g_Kh2[2 * NBH * SEQ * HDIM];
__device__ __half g_Vt2[2 * NBH * HDIM * SEQ];    // V transposed [bh][d][s]
__device__ float g_X[2 * SEQ * CDIM];             // attention output fp32
__device__ float g_S[(size_t)NBH * SEQ * SEQ];    // 268 MB
__device__ int   g_q2k[NBH * SEQ];
__device__ int   g_k2q[NBH * SEQ];
__device__ float g_madd[NBH * SEQ];
__device__ float g_rpv[NBH * 32 * SEQ];
__device__ int   g_rpi[NBH * 32 * SEQ];
__device__ float g_cpv[NBH * 32 * SEQ];
__device__ int   g_cpi[NBH * 32 * SEQ];

// fast exp on the FMA pipe. |rel err| ~1e-7.
__device__ __forceinline__ float fexp(float x) {
    float y = x * 1.4426950408889634f;
    y = fminf(fmaxf(y, -126.0f), 126.0f);
    float t = y + 12582912.0f;
    int   e = __float_as_int(t) - 0x4B400000;
    float r = t - 12582912.0f;
    float f = y - r;
    float p = 1.535336188319500e-4f;
    p = fmaf(p, f, 1.339887440266574e-3f);
    p = fmaf(p, f, 9.618437357674640e-3f);
    p = fmaf(p, f, 5.550332471162809e-2f);
    p = fmaf(p, f, 2.402264791363012e-1f);
    p = fmaf(p, f, 6.931472028550421e-1f);
    p = fmaf(p, f, 1.0f);
    return p * __int_as_float((e + 127) << 23);
}

#define MMA_F16(d, a, b0, b1)                                               \
    asm volatile("mma.sync.aligned.m16n8k16.row.col.f32.f16.f16.f32 "        \
                 "{%0,%1,%2,%3}, {%4,%5,%6,%7}, {%8,%9}, {%0,%1,%2,%3};"     \
                 : "+f"((d)[0]), "+f"((d)[1]), "+f"((d)[2]), "+f"((d)[3])    \
                 : "r"((a)[0]), "r"((a)[1]), "r"((a)[2]), "r"((a)[3]),       \
                   "r"(b0), "r"(b1))

#define LDM4(r, addr)                                                        \
    asm volatile("ldmatrix.sync.aligned.m8n8.x4.shared.b16 {%0,%1,%2,%3}, [%4];" \
                 : "=r"((r)[0]), "=r"((r)[1]), "=r"((r)[2]), "=r"((r)[3])    \
                 : "r"(addr))

__device__ __forceinline__ uint32_t pack_h2(float a, float b) {
    __half2 t;
    t.x = __float2half_rn(a);
    t.y = __float2half_rn(b);
    return *(uint32_t*)&t;
}

#define FMA16(a, b, acc)                                                   \
    acc[0][0] = fmaf(a.x, b.x, acc[0][0]); acc[0][1] = fmaf(a.x, b.y, acc[0][1]); \
    acc[0][2] = fmaf(a.x, b.z, acc[0][2]); acc[0][3] = fmaf(a.x, b.w, acc[0][3]); \
    acc[1][0] = fmaf(a.y, b.x, acc[1][0]); acc[1][1] = fmaf(a.y, b.y, acc[1][1]); \
    acc[1][2] = fmaf(a.y, b.z, acc[1][2]); acc[1][3] = fmaf(a.y, b.w, acc[1][3]); \
    acc[2][0] = fmaf(a.z, b.x, acc[2][0]); acc[2][1] = fmaf(a.z, b.y, acc[2][1]); \
    acc[2][2] = fmaf(a.z, b.z, acc[2][2]); acc[2][3] = fmaf(a.z, b.w, acc[2][3]); \
    acc[3][0] = fmaf(a.w, b.x, acc[3][0]); acc[3][1] = fmaf(a.w, b.y, acc[3][1]); \
    acc[3][2] = fmaf(a.w, b.z, acc[3][2]); acc[3][3] = fmaf(a.w, b.w, acc[3][3]);

// ---------------- projection GEMM (FFMA), fused fp16 split epilogue ------
// mode 0/1: split planes -> g_Qh2/g_Kh2 [b,h,n,d]
// mode 2:   split planes -> g_Vt2 [b,h,d,n] (transposed)
// mode 3:   fp32 row-major outPlain
__global__ void proj_kernel(const float* __restrict__ A,
                            const float* __restrict__ W,
                            float* __restrict__ outPlain, int mode)
{
    __shared__ float As[16][68];
    __shared__ float Bs[16][68];
    const int tid = threadIdx.x;
    const int r0 = blockIdx.y << 6, c0 = blockIdx.x << 6;
    const int lr = tid >> 2;
    const int lc = (tid & 3) << 2;
    const float* Ap = A + (size_t)(r0 + lr) * CDIM + lc;
    const float* Wp = W + (size_t)(c0 + lr) * CDIM + lc;
    const int ty = tid >> 4, tx = tid & 15;
    float acc[4][4] = {};

    for (int k0 = 0; k0 < CDIM; k0 += 16) {
        float4 av = *(const float4*)(Ap + k0);
        float4 bv = *(const float4*)(Wp + k0);
        __syncthreads();
        As[lc + 0][lr] = av.x; As[lc + 1][lr] = av.y;
        As[lc + 2][lr] = av.z; As[lc + 3][lr] = av.w;
        Bs[lc + 0][lr] = bv.x; Bs[lc + 1][lr] = bv.y;
        Bs[lc + 2][lr] = bv.z; Bs[lc + 3][lr] = bv.w;
        __syncthreads();
#pragma unroll
        for (int k = 0; k < 16; k++) {
            float4 a = *(const float4*)&As[k][ty << 2];
            float4 b = *(const float4*)&Bs[k][tx << 2];
            FMA16(a, b, acc)
        }
    }

    if (mode == 3) {
#pragma unroll
        for (int i = 0; i < 4; i++) {
            int row = r0 + (ty << 2) + i;
            float4 o = make_float4(acc[i][0], acc[i][1], acc[i][2], acc[i][3]);
            *(float4*)&outPlain[(size_t)row * CDIM + c0 + (tx << 2)] = o;
        }
        return;
    }

    // split each acc element into fp16 hi/lo
    __half hi[4][4], lo[4][4];
#pragma unroll
    for (int i = 0; i < 4; i++)
#pragma unroll
        for (int j = 0; j < 4; j++) {
            float v = acc[i][j];
            __half h = __float2half_rn(v);
            hi[i][j] = h;
            lo[i][j] = __float2half_rn(v - __half2float(h));
        }

    if (mode == 2) {
#pragma unroll
        for (int i = 0; i < 4; i++) {
            int row = r0 + (ty << 2) + i;
            int b = row >> 11, n = row & 2047;
#pragma unroll
            for (int j = 0; j < 4; j++) {
                int col = c0 + (tx << 2) + j;
                int h = col >> 6, d = col & 63;
                size_t idx = ((size_t)((b << 3) + h) * HDIM + d) * SEQ + n;
                g_Vt2[idx] = hi[i][j];
                g_Vt2[NQe + idx] = lo[i][j];
            }
        }
    } else {
        __half* OH = (mode == 0) ? g_Qh2 : g_Kh2;
#pragma unroll
        for (int i = 0; i < 4; i++) {
            int row = r0 + (ty << 2) + i;
            int b = row >> 11, n = row & 2047;
            int col0 = c0 + (tx << 2);
            int h = col0 >> 6, d = col0 & 63;
            size_t idx = ((size_t)((b << 3) + h) * SEQ + n) * HDIM + d;
            __half2 h01; h01.x = hi[i][0]; h01.y = hi[i][1];
            __half2 h23; h23.x = hi[i][2]; h23.y = hi[i][3];
            __half2 l01; l01.x = lo[i][0]; l01.y = lo[i][1];
            __half2 l23; l23.x = lo[i][2]; l23.y = lo[i][3];
            *(__half2*)&OH[idx] = h01;
            *(__half2*)&OH[idx + 2] = h23;
            *(__half2*)&OH[NQe + idx] = l01;
            *(__half2*)&OH[NQe + idx + 2] = l23;
        }
    }
}

// ---- S = (Qh @ Kh^T)*SCALE via fp16 split-2 MMA + fused tile argmax -----
__global__ void __launch_bounds__(128) qk_mma_kernel()
{
    __shared__ __align__(16) unsigned char smraw[6 * PLANE * 2];  // 18432 B
    __half* sAB = (__half*)smraw;
    float* Ssm = (float*)smraw;                                   // 64x68 fp32 epilogue

    const int bh = blockIdx.z;
    const int r0 = blockIdx.y << 6, c0 = blockIdx.x << 6;
    const int tid = threadIdx.x, lane = tid & 31, w = tid >> 5;
    const int wm = (w & 1) << 5, wn = (w >> 1) << 5;

    const size_t qoff = (size_t)bh * SEQ * HDIM + (size_t)(r0 + (tid >> 1)) * HDIM + (tid & 1) * 8;
    const size_t koff = (size_t)bh * SEQ * HDIM + (size_t)(c0 + (tid >> 1)) * HDIM + (tid & 1) * 8;
    const __half* qp[2] = { g_Qh2 + qoff, g_Qh2 + (size_t)NQe + qoff };
    const __half* kp[2] = { g_Kh2 + koff, g_Kh2 + (size_t)NQe + koff };
    const int sts = (tid >> 1) * KP + (tid & 1) * 8;

    uint32_t sbase = (uint32_t)__cvta_generic_to_shared(sAB);
    const int lrow = (lane & 7) + ((lane >> 3) & 1) * 8;
    const int lk = (lane >> 4) * 8;
    uint32_t adA[2][2], adB[2][2];
#pragma unroll
    for (int p = 0; p < 2; p++)
#pragma unroll
        for (int t = 0; t < 2; t++) {
            adA[p][t] = sbase + 2 * (p * PLANE + (wm + 16 * t + lrow) * KP + lk);
            adB[p][t] = sbase + 2 * ((2 + p) * PLANE + (wn + 16 * t + lrow) * KP + lk);
        }

    float acc[2][4][4] = {};

#pragma unroll 1
    for (int ks = 0; ks < 4; ks++) {
        uint4 qv[2], kv[2];
#pragma unroll
        for (int p = 0; p < 2; p++) {
            qv[p] = *(const uint4*)(qp[p] + ks * 16);
            kv[p] = *(const uint4*)(kp[p] + ks * 16);
        }
        __syncthreads();
#pragma unroll
        for (int p = 0; p < 2; p++) {
            *(uint4*)&sAB[p * PLANE + sts] = qv[p];
            *(uint4*)&sAB[(2 + p) * PLANE + sts] = kv[p];
        }
        __syncthreads();

        uint32_t afr[2][2][4], bfr[2][2][4];
#pragma unroll
        for (int p = 0; p < 2; p++)
#pragma unroll
            for (int t = 0; t < 2; t++) { LDM4(afr[p][t], adA[p][t]); LDM4(bfr[p][t], adB[p][t]); }

        const int pa[3] = {0, 0, 1};
        const int pb[3] = {0, 1, 0};
#pragma unroll
        for (int c = 0; c < 3; c++)
#pragma unroll
            for (int mt = 0; mt < 2; mt++)
#pragma unroll
                for (int nt = 0; nt < 4; nt++) {
                    int n2 = nt >> 1, j = nt & 1;
                    MMA_F16(acc[mt][nt], afr[pa[c]][mt], bfr[pb[c]][n2][j], bfr[pb[c]][n2][j + 2]);
                }
    }

    __syncthreads();
#pragma unroll
    for (int mt = 0; mt < 2; mt++) {
        int row0 = wm + 16 * mt + (lane >> 2);
#pragma unroll
        for (int nt = 0; nt < 4; nt++) {
            int col = wn + 8 * nt + 2 * (lane & 3);
            *(float2*)&Ssm[row0 * 68 + col] =
                make_float2(acc[mt][nt][0] * QKSCALE, acc[mt][nt][1] * QKSCALE);
            *(float2*)&Ssm[(row0 + 8) * 68 + col] =
                make_float2(acc[mt][nt][2] * QKSCALE, acc[mt][nt][3] * QKSCALE);
        }
    }
    __syncthreads();

    float* Sp = g_S + (size_t)bh * SEQ * SEQ;
    {
        int row = tid >> 1, cb = (tid & 1) * 32;
#pragma unroll
        for (int i = 0; i < 8; i++)
            *(float4*)&Sp[(size_t)(r0 + row) * SEQ + c0 + cb + 4 * i] =
                *(const float4*)&Ssm[row * 68 + cb + 4 * i];
    }

    if (tid < 64) {
        float best = -3e38f; int bi = 0;
#pragma unroll
        for (int i = 0; i < 16; i++) {
            float4 v = *(const float4*)&Ssm[tid * 68 + 4 * i];
            if (v.x > best) { best = v.x; bi = 4 * i; }
            if (v.y > best) { best = v.y; bi = 4 * i + 1; }
            if (v.z > best) { best = v.z; bi = 4 * i + 2; }
            if (v.w > best) { best = v.w; bi = 4 * i + 3; }
        }
        size_t p = (size_t)((bh << 5) + blockIdx.x) * SEQ + r0 + tid;
        g_rpv[p] = best; g_rpi[p] = c0 + bi;
    } else {
        int c = tid - 64;
        float best = -3e38f; int bi = 0;
#pragma unroll 8
        for (int i = 0; i < 64; i++) {
            float v = Ssm[i * 68 + c];
            if (v > best) { best = v; bi = i; }
        }
        size_t p = (size_t)((bh << 5) + blockIdx.y) * SEQ + c0 + c;
        g_cpv[p] = best; g_cpi[p] = r0 + bi;
    }
}

// ---------------- reduce 32 partials -> q2k and k2q ----------------------
__global__ void argmax_reduce_kernel()
{
    int gid = blockIdx.x * blockDim.x + threadIdx.x;
    int which = gid >= NBH * SEQ;
    int i = gid & (NBH * SEQ - 1);
    int bh = i >> 11, n = i & 2047;
    const float* pv = which ? g_cpv : g_rpv;
    const int*   pi = which ? g_cpi : g_rpi;
    float v = -3e38f; int idx = 0;
#pragma unroll 8
    for (int t = 0; t < 32; t++) {
        size_t p = (size_t)((bh << 5) + t) * SEQ + n;
        float ov = pv[p];
        if (ov > v) { v = ov; idx = pi[p]; }
    }
    (which ? g_k2q : g_q2k)[i] = idx;
}

// ---------------- cycle consistency -> additive mask ---------------------
__global__ void asso_kernel(const int* __restrict__ smask,
                            const float* __restrict__ svalid)
{
    int i = blockIdx.x * blockDim.x + threadIdx.x;
    int bh = i >> 11, m = i & 2047;
    int b = bh >> 3;
    int kq = g_k2q[i];
    int remap = g_q2k[(bh << 11) + kq];
    float valid = (smask[(b << 11) + m] == smask[(b << 11) + remap])
                      ? svalid[(b << 11) + m] : 1.0f;
    g_madd[i] = valid * -10000.0f;
}

// ---- fused exp + online row-sum + P@V, single-sync double-buffered ------
__global__ void __launch_bounds__(128) av_mma_kernel()
{
    __shared__ __align__(16) __half sAB[8 * PLANE];   // 2 buffers x (Ph,Pl,Vh,Vl)
    __shared__ float sL[64];

    const int bh = blockIdx.y;
    const int n0 = blockIdx.x << 6;
    const int b = bh >> 3, h = bh & 7;
    const int tid = threadIdx.x, lane = tid & 31, w = tid >> 5;
    const int wm = (w & 1) << 5, wn = (w >> 1) << 5;

    const float* Sp = g_S + (size_t)bh * SEQ * SEQ + (size_t)(n0 + (tid >> 1)) * SEQ + (tid & 1) * 8;
    const float* mp = g_madd + bh * SEQ + (tid & 1) * 8;
    const size_t voff = (size_t)bh * HDIM * SEQ + (size_t)(tid >> 1) * SEQ + (tid & 1) * 8;
    const __half* vp[2] = { g_Vt2 + voff, g_Vt2 + (size_t)NQe + voff };
    const int sts = (tid >> 1) * KP + (tid & 1) * 8;

    uint32_t sbase = (uint32_t)__cvta_generic_to_shared(sAB);
    const int lrow = (lane & 7) + ((lane >> 3) & 1) * 8;
    const int lk = (lane >> 4) * 8;
    uint32_t adA[2][2], adB[2][2];
#pragma unroll
    for (int p = 0; p < 2; p++)
#pragma unroll
        for (int t = 0; t < 2; t++) {
            adA[p][t] = sbase + 2 * (p * PLANE + (wm + 16 * t + lrow) * KP + lk);
            adB[p][t] = sbase + 2 * ((2 + p) * PLANE + (wn + 16 * t + lrow) * KP + lk);
        }
    const uint32_t bufB = 4 * PLANE * 2;

    float acc[2][4][4] = {};
    float runL = 0.0f;

#pragma unroll 1
    for (int ks = 0; ks < 128; ks++) {
        const int buf = ks & 1;
        float4 s0 = *(const float4*)(Sp + ks * 16);
        float4 s1 = *(const float4*)(Sp + ks * 16 + 4);
        float4 m0 = *(const float4*)(mp + ks * 16);
        float4 m1 = *(const float4*)(mp + ks * 16 + 4);
        uint4 v0 = *(const uint4*)(vp[0] + ks * 16);
        uint4 v1 = *(const uint4*)(vp[1] + ks * 16);

        float pv[8];
        pv[0] = fexp(s0.x + m0.x); pv[1] = fexp(s0.y + m0.y);
        pv[2] = fexp(s0.z + m0.z); pv[3] = fexp(s0.w + m0.w);
        pv[4] = fexp(s1.x + m1.x); pv[5] = fexp(s1.y + m1.y);
        pv[6] = fexp(s1.z + m1.z); pv[7] = fexp(s1.w + m1.w);
        runL += ((pv[0] + pv[1]) + (pv[2] + pv[3])) + ((pv[4] + pv[5]) + (pv[6] + pv[7]));

        uint4 ph, pl;
        float hs[8];
#pragma unroll
        for (int i = 0; i < 8; i++)
            hs[i] = __half2float(__float2half_rn(pv[i]));
        ph.x = pack_h2(pv[0], pv[1]); ph.y = pack_h2(pv[2], pv[3]);
        ph.z = pack_h2(pv[4], pv[5]); ph.w = pack_h2(pv[6], pv[7]);
        pl.x = pack_h2(pv[0] - hs[0], pv[1] - hs[1]);
        pl.y = pack_h2(pv[2] - hs[2], pv[3] - hs[3]);
        pl.z = pack_h2(pv[4] - hs[4], pv[5] - hs[5]);
        pl.w = pack_h2(pv[6] - hs[6], pv[7] - hs[7]);

        __half* sb = sAB + buf * 4 * PLANE;
        *(uint4*)&sb[0 * PLANE + sts] = ph;
        *(uint4*)&sb[1 * PLANE + sts] = pl;
        *(uint4*)&sb[2 * PLANE + sts] = v0;
        *(uint4*)&sb[3 * PLANE + sts] = v1;
        __syncthreads();

        uint32_t afr[2][2][4], bfr[2][2][4];
#pragma unroll
        for (int p = 0; p < 2; p++)
#pragma unroll
            for (int t = 0; t < 2; t++) {
                LDM4(afr[p][t], adA[p][t] + buf * bufB);
                LDM4(bfr[p][t], adB[p][t] + buf * bufB);
            }

        const int pa[3] = {0, 0, 1};
        const int pb[3] = {0, 1, 0};
#pragma unroll
        for (int c = 0; c < 3; c++)
#pragma unroll
            for (int mt = 0; mt < 2; mt++)
#pragma unroll
                for (int nt = 0; nt < 4; nt++) {
                    int n2 = nt >> 1, j = nt & 1;
                    MMA_F16(acc[mt][nt], afr[pa[c]][mt], bfr[pb[c]][n2][j], bfr[pb[c]][n2][j + 2]);
                }
    }

    runL += __shfl_xor_sync(0xffffffffu, runL, 1);
    if (!(tid & 1)) sL[tid >> 1] = runL;
    __syncthreads();

#pragma unroll
    for (int mt = 0; mt < 2; mt++) {
        int row0 = wm + 16 * mt + (lane >> 2);
        float inv0 = 1.0f / sL[row0];
        float inv1 = 1.0f / sL[row0 + 8];
#pragma unroll
        for (int nt = 0; nt < 4; nt++) {
            int col = wn + 8 * nt + 2 * (lane & 3);
            int n = n0 + row0;
            *(float2*)&g_X[(size_t)(b * SEQ + n) * CDIM + h * HDIM + col] =
                make_float2(acc[mt][nt][0] * inv0, acc[mt][nt][1] * inv0);
            *(float2*)&g_X[(size_t)(b * SEQ + n + 8) * CDIM + h * HDIM + col] =
                make_float2(acc[mt][nt][2] * inv1, acc[mt][nt][3] * inv1);
        }
    }
}

// ---------------- launcher ------------------------------------------------
extern "C" void kernel_launch(void* const* d_in, const int* in_sizes, int n_in,
                              void* d_out, int out_size)
{
    const float* q   = (const float*)d_in[0];
    const float* k   = (const float*)d_in[1];
    const float* v   = (const float*)d_in[2];
    const float* svm = (const float*)d_in[3];
    const int*   sm  = (const int*)d_in[4];
    const float* Wq  = (const float*)d_in[5];
    const float* Wk  = (const float*)d_in[6];
    const float* Wv  = (const float*)d_in[7];
    const float* Wp  = (const float*)d_in[8];
    float* out = (float*)d_out;

    float* X;
    cudaGetSymbolAddress((void**)&X, g_X);

    dim3 gp(CDIM / 64, (2 * SEQ) / 64);      // (8, 64)
    proj_kernel<<<gp, 256>>>(q, Wq, nullptr, 0);
    proj_kernel<<<gp, 256>>>(k, Wk, nullptr, 1);
    proj_kernel<<<gp, 256>>>(v, Wv, nullptr, 2);

    qk_mma_kernel<<<dim3(SEQ / 64, SEQ / 64, NBH), 128>>>();

    argmax_reduce_kernel<<<(2 * NBH * SEQ) / 256, 256>>>();
    asso_kernel<<<(NBH * SEQ) / 256, 256>>>(sm, svm);

    av_mma_kernel<<<dim3(SEQ / 64, NBH), 128>>>();

    proj_kernel<<<gp, 256>>>(X, Wp, out, 3);
}

// round 9
// speedup vs baseline: 1.3837x; 1.0999x over previous
#include <cuda_runtime.h>
#include <cuda_fp16.h>
#include <cstdint>

#define SEQ   2048
#define HDIM  64
#define NHEAD 8
#define CDIM  512
#define NBH   16            // B*H
#define QKSCALE 0.125f
#define KP    24            // smem tile pitch in halfs (48B, ldmatrix conflict-free)
#define PLANE (64 * KP)     // halfs per 64x16 padded tile
#define KP2   72            // qk128 operand pitch in halfs (144B)
#define OPSZ  (128 * KP2)   // halfs per operand array (9216)
#define STP2  132           // qk128 staging pitch (floats)
#define QK_SMEM (4 * OPSZ * 2)   // 73728 B (staging 67584 B unions into it)

constexpr int NQe = NBH * SEQ * HDIM;   // 2,097,152 elements per plane

// ---------------- scratch (device globals; no allocation) ----------------
__device__ __half g_Qh2[2 * NBH * SEQ * HDIM];    // hi/lo fp16 planes
__device__ __half g_Kh2[2 * NBH * SEQ * HDIM];
__device__ __half g_Vt2[2 * NBH * HDIM * SEQ];    // V transposed [bh][d][s]
__device__ float g_X[2 * SEQ * CDIM];             // attention output fp32
__device__ float g_S[(size_t)NBH * SEQ * SEQ];    // 268 MB
__device__ int   g_q2k[NBH * SEQ];
__device__ int   g_k2q[NBH * SEQ];
__device__ float g_madd[NBH * SEQ];
__device__ float g_rpv[NBH * 16 * SEQ];           // 16 strips of 128
__device__ int   g_rpi[NBH * 16 * SEQ];
__device__ float g_cpv[NBH * 16 * SEQ];
__device__ int   g_cpi[NBH * 16 * SEQ];

// fast exp on the FMA pipe. |rel err| ~1e-7.
__device__ __forceinline__ float fexp(float x) {
    float y = x * 1.4426950408889634f;
    y = fminf(fmaxf(y, -126.0f), 126.0f);
    float t = y + 12582912.0f;
    int   e = __float_as_int(t) - 0x4B400000;
    float r = t - 12582912.0f;
    float f = y - r;
    float p = 1.535336188319500e-4f;
    p = fmaf(p, f, 1.339887440266574e-3f);
    p = fmaf(p, f, 9.618437357674640e-3f);
    p = fmaf(p, f, 5.550332471162809e-2f);
    p = fmaf(p, f, 2.402264791363012e-1f);
    p = fmaf(p, f, 6.931472028550421e-1f);
    p = fmaf(p, f, 1.0f);
    return p * __int_as_float((e + 127) << 23);
}

#define MMA_F16(d, a, b0, b1)                                               \
    asm volatile("mma.sync.aligned.m16n8k16.row.col.f32.f16.f16.f32 "        \
                 "{%0,%1,%2,%3}, {%4,%5,%6,%7}, {%8,%9}, {%0,%1,%2,%3};"     \
                 : "+f"((d)[0]), "+f"((d)[1]), "+f"((d)[2]), "+f"((d)[3])    \
                 : "r"((a)[0]), "r"((a)[1]), "r"((a)[2]), "r"((a)[3]),       \
                   "r"(b0), "r"(b1))

#define LDM4(r, addr)                                                        \
    asm volatile("ldmatrix.sync.aligned.m8n8.x4.shared.b16 {%0,%1,%2,%3}, [%4];" \
                 : "=r"((r)[0]), "=r"((r)[1]), "=r"((r)[2]), "=r"((r)[3])    \
                 : "r"(addr))

__device__ __forceinline__ uint32_t pack_h2(float a, float b) {
    __half2 t;
    t.x = __float2half_rn(a);
    t.y = __float2half_rn(b);
    return *(uint32_t*)&t;
}

#define FMA16(a, b, acc)                                                   \
    acc[0][0] = fmaf(a.x, b.x, acc[0][0]); acc[0][1] = fmaf(a.x, b.y, acc[0][1]); \
    acc[0][2] = fmaf(a.x, b.z, acc[0][2]); acc[0][3] = fmaf(a.x, b.w, acc[0][3]); \
    acc[1][0] = fmaf(a.y, b.x, acc[1][0]); acc[1][1] = fmaf(a.y, b.y, acc[1][1]); \
    acc[1][2] = fmaf(a.y, b.z, acc[1][2]); acc[1][3] = fmaf(a.y, b.w, acc[1][3]); \
    acc[2][0] = fmaf(a.z, b.x, acc[2][0]); acc[2][1] = fmaf(a.z, b.y, acc[2][1]); \
    acc[2][2] = fmaf(a.z, b.z, acc[2][2]); acc[2][3] = fmaf(a.z, b.w, acc[2][3]); \
    acc[3][0] = fmaf(a.w, b.x, acc[3][0]); acc[3][1] = fmaf(a.w, b.y, acc[3][1]); \
    acc[3][2] = fmaf(a.w, b.z, acc[3][2]); acc[3][3] = fmaf(a.w, b.w, acc[3][3]);

// ---------------- projection GEMM (FFMA), fused fp16 split epilogue ------
__global__ void proj_kernel(const float* __restrict__ A,
                            const float* __restrict__ W,
                            float* __restrict__ outPlain, int mode)
{
    __shared__ float As[16][68];
    __shared__ float Bs[16][68];
    const int tid = threadIdx.x;
    const int r0 = blockIdx.y << 6, c0 = blockIdx.x << 6;
    const int lr = tid >> 2;
    const int lc = (tid & 3) << 2;
    const float* Ap = A + (size_t)(r0 + lr) * CDIM + lc;
    const float* Wp = W + (size_t)(c0 + lr) * CDIM + lc;
    const int ty = tid >> 4, tx = tid & 15;
    float acc[4][4] = {};

    for (int k0 = 0; k0 < CDIM; k0 += 16) {
        float4 av = *(const float4*)(Ap + k0);
        float4 bv = *(const float4*)(Wp + k0);
        __syncthreads();
        As[lc + 0][lr] = av.x; As[lc + 1][lr] = av.y;
        As[lc + 2][lr] = av.z; As[lc + 3][lr] = av.w;
        Bs[lc + 0][lr] = bv.x; Bs[lc + 1][lr] = bv.y;
        Bs[lc + 2][lr] = bv.z; Bs[lc + 3][lr] = bv.w;
        __syncthreads();
#pragma unroll
        for (int k = 0; k < 16; k++) {
            float4 a = *(const float4*)&As[k][ty << 2];
            float4 b = *(const float4*)&Bs[k][tx << 2];
            FMA16(a, b, acc)
        }
    }

    if (mode == 3) {
#pragma unroll
        for (int i = 0; i < 4; i++) {
            int row = r0 + (ty << 2) + i;
            float4 o = make_float4(acc[i][0], acc[i][1], acc[i][2], acc[i][3]);
            *(float4*)&outPlain[(size_t)row * CDIM + c0 + (tx << 2)] = o;
        }
        return;
    }

    __half hi[4][4], lo[4][4];
#pragma unroll
    for (int i = 0; i < 4; i++)
#pragma unroll
        for (int j = 0; j < 4; j++) {
            float v = acc[i][j];
            __half h = __float2half_rn(v);
            hi[i][j] = h;
            lo[i][j] = __float2half_rn(v - __half2float(h));
        }

    if (mode == 2) {
#pragma unroll
        for (int i = 0; i < 4; i++) {
            int row = r0 + (ty << 2) + i;
            int b = row >> 11, n = row & 2047;
#pragma unroll
            for (int j = 0; j < 4; j++) {
                int col = c0 + (tx << 2) + j;
                int h = col >> 6, d = col & 63;
                size_t idx = ((size_t)((b << 3) + h) * HDIM + d) * SEQ + n;
                g_Vt2[idx] = hi[i][j];
                g_Vt2[NQe + idx] = lo[i][j];
            }
        }
    } else {
        __half* OH = (mode == 0) ? g_Qh2 : g_Kh2;
#pragma unroll
        for (int i = 0; i < 4; i++) {
            int row = r0 + (ty << 2) + i;
            int b = row >> 11, n = row & 2047;
            int col0 = c0 + (tx << 2);
            int h = col0 >> 6, d = col0 & 63;
            size_t idx = ((size_t)((b << 3) + h) * SEQ + n) * HDIM + d;
            __half2 h01; h01.x = hi[i][0]; h01.y = hi[i][1];
            __half2 h23; h23.x = hi[i][2]; h23.y = hi[i][3];
            __half2 l01; l01.x = lo[i][0]; l01.y = lo[i][1];
            __half2 l23; l23.x = lo[i][2]; l23.y = lo[i][3];
            *(__half2*)&OH[idx] = h01;
            *(__half2*)&OH[idx + 2] = h23;
            *(__half2*)&OH[NQe + idx] = l01;
            *(__half2*)&OH[NQe + idx + 2] = l23;
        }
    }
}

// ---- S = (Qh @ Kh^T)*SCALE: 128x128 tile, whole-K resident, fused argmax
__global__ void __launch_bounds__(256, 2) qk_mma_kernel()
{
    extern __shared__ __align__(16) unsigned char smraw[];
    __half* sOp = (__half*)smraw;      // 4 arrays: Qh, Ql, Kh, Kl (128x72 halfs)
    float* stag = (float*)smraw;       // reused after MMA phase (128x132 fp32)

    const int tid = threadIdx.x, lane = tid & 31, w = tid >> 5;
    const int bh = blockIdx.z;
    const int r0 = blockIdx.y << 7, c0 = blockIdx.x << 7;
    const int wm = (w & 1) << 6;       // 2 warps over m (64 each)
    const int wn = (w >> 1) << 5;      // 4 warps over n (32 each)

    // load operands once (whole K=64)
    const __half* bases[4] = {
        g_Qh2 + (size_t)bh * SEQ * HDIM, g_Qh2 + (size_t)NQe + (size_t)bh * SEQ * HDIM,
        g_Kh2 + (size_t)bh * SEQ * HDIM, g_Kh2 + (size_t)NQe + (size_t)bh * SEQ * HDIM };
#pragma unroll
    for (int idx = tid; idx < 4096; idx += 256) {
        int arr = idx >> 10, rem = idx & 1023, row = rem >> 3, c = rem & 7;
        int gr = ((arr < 2) ? r0 : c0) + row;
        uint4 v = *(const uint4*)(bases[arr] + (size_t)gr * HDIM + c * 8);
        *(uint4*)(sOp + arr * OPSZ + row * KP2 + c * 8) = v;
    }
    __syncthreads();

    uint32_t sb = (uint32_t)__cvta_generic_to_shared(sOp);
    const int lrow = (lane & 7) + ((lane >> 3) & 1) * 8;
    const int lk = (lane >> 4) * 8;
    uint32_t adA[2][4], adB[2][2];
#pragma unroll
    for (int p = 0; p < 2; p++) {
#pragma unroll
        for (int mt = 0; mt < 4; mt++)
            adA[p][mt] = sb + 2 * (p * OPSZ + (wm + 16 * mt + lrow) * KP2 + lk);
#pragma unroll
        for (int g = 0; g < 2; g++)
            adB[p][g] = sb + 2 * ((2 + p) * OPSZ + (wn + 16 * g + lrow) * KP2 + lk);
    }

    float acc[4][4][4] = {};
#pragma unroll
    for (int ks = 0; ks < 4; ks++) {
        uint32_t bfr[2][2][4];
#pragma unroll
        for (int p = 0; p < 2; p++)
#pragma unroll
            for (int g = 0; g < 2; g++) LDM4(bfr[p][g], adB[p][g] + ks * 32);
#pragma unroll
        for (int mt = 0; mt < 4; mt++) {
            uint32_t afr[2][4];
#pragma unroll
            for (int p = 0; p < 2; p++) LDM4(afr[p], adA[p][mt] + ks * 32);
#pragma unroll
            for (int nt = 0; nt < 4; nt++) {
                int n2 = nt >> 1, j = nt & 1;
                MMA_F16(acc[mt][nt], afr[0], bfr[0][n2][j], bfr[0][n2][j + 2]); // hh
                MMA_F16(acc[mt][nt], afr[0], bfr[1][n2][j], bfr[1][n2][j + 2]); // hl
                MMA_F16(acc[mt][nt], afr[1], bfr[0][n2][j], bfr[0][n2][j + 2]); // lh
            }
        }
    }
    __syncthreads();   // operands no longer needed; smem becomes staging

    // fragments -> staging (scaled)
#pragma unroll
    for (int mt = 0; mt < 4; mt++) {
        int row0 = wm + 16 * mt + (lane >> 2);
#pragma unroll
        for (int nt = 0; nt < 4; nt++) {
            int col = wn + 8 * nt + 2 * (lane & 3);
            *(float2*)&stag[row0 * STP2 + col] =
                make_float2(acc[mt][nt][0] * QKSCALE, acc[mt][nt][1] * QKSCALE);
            *(float2*)&stag[(row0 + 8) * STP2 + col] =
                make_float2(acc[mt][nt][2] * QKSCALE, acc[mt][nt][3] * QKSCALE);
        }
    }
    __syncthreads();

    // coalesced S store
    float* Sp = g_S + (size_t)bh * SEQ * SEQ;
    {
        int row = tid >> 1, cb = (tid & 1) * 64;
#pragma unroll
        for (int i = 0; i < 16; i++)
            *(float4*)&Sp[(size_t)(r0 + row) * SEQ + c0 + cb + 4 * i] =
                *(const float4*)&stag[row * STP2 + cb + 4 * i];
    }

    // first-occurrence row/col argmax partials
    if (tid < 128) {
        float best = -3e38f; int bi = 0;
#pragma unroll 8
        for (int i = 0; i < 128; i++) {
            float v = stag[tid * STP2 + i];
            if (v > best) { best = v; bi = i; }
        }
        size_t p = (size_t)(bh * 16 + blockIdx.x) * SEQ + r0 + tid;
        g_rpv[p] = best; g_rpi[p] = c0 + bi;
    } else {
        int c = tid - 128;
        float best = -3e38f; int bi = 0;
#pragma unroll 8
        for (int i = 0; i < 128; i++) {
            float v = stag[i * STP2 + c];
            if (v > best) { best = v; bi = i; }
        }
        size_t p = (size_t)(bh * 16 + blockIdx.y) * SEQ + c0 + c;
        g_cpv[p] = best; g_cpi[p] = r0 + bi;
    }
}

// ---------------- reduce 16 partials -> q2k and k2q ----------------------
__global__ void argmax_reduce_kernel()
{
    int gid = blockIdx.x * blockDim.x + threadIdx.x;
    int which = gid >= NBH * SEQ;
    int i = gid & (NBH * SEQ - 1);
    int bh = i >> 11, n = i & 2047;
    const float* pv = which ? g_cpv : g_rpv;
    const int*   pi = which ? g_cpi : g_rpi;
    float v = -3e38f; int idx = 0;
#pragma unroll
    for (int t = 0; t < 16; t++) {
        size_t p = (size_t)(bh * 16 + t) * SEQ + n;
        float ov = pv[p];
        if (ov > v) { v = ov; idx = pi[p]; }   // ascending tiles: first kept
    }
    (which ? g_k2q : g_q2k)[i] = idx;
}

// ---------------- cycle consistency -> additive mask ---------------------
__global__ void asso_kernel(const int* __restrict__ smask,
                            const float* __restrict__ svalid)
{
    int i = blockIdx.x * blockDim.x + threadIdx.x;
    int bh = i >> 11, m = i & 2047;
    int b = bh >> 3;
    int kq = g_k2q[i];
    int remap = g_q2k[(bh << 11) + kq];
    float valid = (smask[(b << 11) + m] == smask[(b << 11) + remap])
                      ? svalid[(b << 11) + m] : 1.0f;
    g_madd[i] = valid * -10000.0f;
}

// ---- fused exp + online row-sum + P@V, single-sync double-buffered ------
__global__ void __launch_bounds__(128) av_mma_kernel()
{
    __shared__ __align__(16) __half sAB[8 * PLANE];   // 2 buffers x (Ph,Pl,Vh,Vl)
    __shared__ float sL[64];

    const int bh = blockIdx.y;
    const int n0 = blockIdx.x << 6;
    const int b = bh >> 3, h = bh & 7;
    const int tid = threadIdx.x, lane = tid & 31, w = tid >> 5;
    const int wm = (w & 1) << 5, wn = (w >> 1) << 5;

    const float* Sp = g_S + (size_t)bh * SEQ * SEQ + (size_t)(n0 + (tid >> 1)) * SEQ + (tid & 1) * 8;
    const float* mp = g_madd + bh * SEQ + (tid & 1) * 8;
    const size_t voff = (size_t)bh * HDIM * SEQ + (size_t)(tid >> 1) * SEQ + (tid & 1) * 8;
    const __half* vp[2] = { g_Vt2 + voff, g_Vt2 + (size_t)NQe + voff };
    const int sts = (tid >> 1) * KP + (tid & 1) * 8;

    uint32_t sbase = (uint32_t)__cvta_generic_to_shared(sAB);
    const int lrow = (lane & 7) + ((lane >> 3) & 1) * 8;
    const int lk = (lane >> 4) * 8;
    uint32_t adA[2][2], adB[2][2];
#pragma unroll
    for (int p = 0; p < 2; p++)
#pragma unroll
        for (int t = 0; t < 2; t++) {
            adA[p][t] = sbase + 2 * (p * PLANE + (wm + 16 * t + lrow) * KP + lk);
            adB[p][t] = sbase + 2 * ((2 + p) * PLANE + (wn + 16 * t + lrow) * KP + lk);
        }
    const uint32_t bufB = 4 * PLANE * 2;

    float acc[2][4][4] = {};
    float runL = 0.0f;

#pragma unroll 1
    for (int ks = 0; ks < 128; ks++) {
        const int buf = ks & 1;
        float4 s0 = *(const float4*)(Sp + ks * 16);
        float4 s1 = *(const float4*)(Sp + ks * 16 + 4);
        float4 m0 = *(const float4*)(mp + ks * 16);
        float4 m1 = *(const float4*)(mp + ks * 16 + 4);
        uint4 v0 = *(const uint4*)(vp[0] + ks * 16);
        uint4 v1 = *(const uint4*)(vp[1] + ks * 16);

        float pv[8];
        pv[0] = fexp(s0.x + m0.x); pv[1] = fexp(s0.y + m0.y);
        pv[2] = fexp(s0.z + m0.z); pv[3] = fexp(s0.w + m0.w);
        pv[4] = fexp(s1.x + m1.x); pv[5] = fexp(s1.y + m1.y);
        pv[6] = fexp(s1.z + m1.z); pv[7] = fexp(s1.w + m1.w);
        runL += ((pv[0] + pv[1]) + (pv[2] + pv[3])) + ((pv[4] + pv[5]) + (pv[6] + pv[7]));

        uint4 ph, pl;
        float hs[8];
#pragma unroll
        for (int i = 0; i < 8; i++)
            hs[i] = __half2float(__float2half_rn(pv[i]));
        ph.x = pack_h2(pv[0], pv[1]); ph.y = pack_h2(pv[2], pv[3]);
        ph.z = pack_h2(pv[4], pv[5]); ph.w = pack_h2(pv[6], pv[7]);
        pl.x = pack_h2(pv[0] - hs[0], pv[1] - hs[1]);
        pl.y = pack_h2(pv[2] - hs[2], pv[3] - hs[3]);
        pl.z = pack_h2(pv[4] - hs[4], pv[5] - hs[5]);
        pl.w = pack_h2(pv[6] - hs[6], pv[7] - hs[7]);

        __half* sbuf = sAB + buf * 4 * PLANE;
        *(uint4*)&sbuf[0 * PLANE + sts] = ph;
        *(uint4*)&sbuf[1 * PLANE + sts] = pl;
        *(uint4*)&sbuf[2 * PLANE + sts] = v0;
        *(uint4*)&sbuf[3 * PLANE + sts] = v1;
        __syncthreads();

        uint32_t afr[2][2][4], bfr[2][2][4];
#pragma unroll
        for (int p = 0; p < 2; p++)
#pragma unroll
            for (int t = 0; t < 2; t++) {
                LDM4(afr[p][t], adA[p][t] + buf * bufB);
                LDM4(bfr[p][t], adB[p][t] + buf * bufB);
            }

        const int pa[3] = {0, 0, 1};
        const int pb[3] = {0, 1, 0};
#pragma unroll
        for (int c = 0; c < 3; c++)
#pragma unroll
            for (int mt = 0; mt < 2; mt++)
#pragma unroll
                for (int nt = 0; nt < 4; nt++) {
                    int n2 = nt >> 1, j = nt & 1;
                    MMA_F16(acc[mt][nt], afr[pa[c]][mt], bfr[pb[c]][n2][j], bfr[pb[c]][n2][j + 2]);
                }
    }

    runL += __shfl_xor_sync(0xffffffffu, runL, 1);
    if (!(tid & 1)) sL[tid >> 1] = runL;
    __syncthreads();

#pragma unroll
    for (int mt = 0; mt < 2; mt++) {
        int row0 = wm + 16 * mt + (lane >> 2);
        float inv0 = 1.0f / sL[row0];
        float inv1 = 1.0f / sL[row0 + 8];
#pragma unroll
        for (int nt = 0; nt < 4; nt++) {
            int col = wn + 8 * nt + 2 * (lane & 3);
            int n = n0 + row0;
            *(float2*)&g_X[(size_t)(b * SEQ + n) * CDIM + h * HDIM + col] =
                make_float2(acc[mt][nt][0] * inv0, acc[mt][nt][1] * inv0);
            *(float2*)&g_X[(size_t)(b * SEQ + n + 8) * CDIM + h * HDIM + col] =
                make_float2(acc[mt][nt][2] * inv1, acc[mt][nt][3] * inv1);
        }
    }
}

// ---------------- launcher ------------------------------------------------
extern "C" void kernel_launch(void* const* d_in, const int* in_sizes, int n_in,
                              void* d_out, int out_size)
{
    const float* q   = (const float*)d_in[0];
    const float* k   = (const float*)d_in[1];
    const float* v   = (const float*)d_in[2];
    const float* svm = (const float*)d_in[3];
    const int*   sm  = (const int*)d_in[4];
    const float* Wq  = (const float*)d_in[5];
    const float* Wk  = (const float*)d_in[6];
    const float* Wv  = (const float*)d_in[7];
    const float* Wp  = (const float*)d_in[8];
    float* out = (float*)d_out;

    float* X;
    cudaGetSymbolAddress((void**)&X, g_X);

    cudaFuncSetAttribute(qk_mma_kernel,
                         cudaFuncAttributeMaxDynamicSharedMemorySize, QK_SMEM);

    dim3 gp(CDIM / 64, (2 * SEQ) / 64);      // (8, 64)
    proj_kernel<<<gp, 256>>>(q, Wq, nullptr, 0);
    proj_kernel<<<gp, 256>>>(k, Wk, nullptr, 1);
    proj_kernel<<<gp, 256>>>(v, Wv, nullptr, 2);

    qk_mma_kernel<<<dim3(SEQ / 128, SEQ / 128, NBH), 256, QK_SMEM>>>();

    argmax_reduce_kernel<<<(2 * NBH * SEQ) / 256, 256>>>();
    asso_kernel<<<(NBH * SEQ) / 256, 256>>>(sm, svm);

    av_mma_kernel<<<dim3(SEQ / 64, NBH), 128>>>();

    proj_kernel<<<gp, 256>>>(X, Wp, out, 3);
}

// round 10
// speedup vs baseline: 1.7190x; 1.2423x over previous
#include <cuda_runtime.h>
#include <cuda_fp16.h>
#include <cstdint>

#define SEQ   2048
#define HDIM  64
#define NHEAD 8
#define CDIM  512
#define NBH   16            // B*H
#define QKSCALE 0.125f
#define KP    24            // smem tile pitch in halfs (48B, ldmatrix conflict-free)
#define PLANE (64 * KP)     // halfs per 64x16 padded tile
#define KP2   72            // qk128 operand pitch in halfs (144B)
#define OPSZ  (128 * KP2)   // halfs per operand array (9216)
#define STP2  132           // qk128 staging pitch (floats)
#define QK_SMEM (4 * OPSZ * 2)   // 73728 B
#define PKP   24            // proj smem pitch (halfs)
#define PPLANE (128 * PKP)  // 3072 halfs per 128x16 plane

constexpr int NQe = NBH * SEQ * HDIM;   // 2,097,152 elements per plane

// ---------------- scratch (device globals; no allocation) ----------------
__device__ __half g_Qh2[2 * NBH * SEQ * HDIM];    // hi/lo fp16 planes
__device__ __half g_Kh2[2 * NBH * SEQ * HDIM];
__device__ __half g_Vt2[2 * NBH * HDIM * SEQ];    // V transposed [bh][d][s]
__device__ float g_X[2 * SEQ * CDIM];             // attention output fp32
__device__ float g_S[(size_t)NBH * SEQ * SEQ];    // 268 MB
__device__ int   g_q2k[NBH * SEQ];
__device__ int   g_k2q[NBH * SEQ];
__device__ float g_madd[NBH * SEQ];
__device__ float g_rpv[NBH * 16 * SEQ];
__device__ int   g_rpi[NBH * 16 * SEQ];
__device__ float g_cpv[NBH * 16 * SEQ];
__device__ int   g_cpi[NBH * 16 * SEQ];

// fast exp on the FMA pipe. |rel err| ~1e-7.
__device__ __forceinline__ float fexp(float x) {
    float y = x * 1.4426950408889634f;
    y = fminf(fmaxf(y, -126.0f), 126.0f);
    float t = y + 12582912.0f;
    int   e = __float_as_int(t) - 0x4B400000;
    float r = t - 12582912.0f;
    float f = y - r;
    float p = 1.535336188319500e-4f;
    p = fmaf(p, f, 1.339887440266574e-3f);
    p = fmaf(p, f, 9.618437357674640e-3f);
    p = fmaf(p, f, 5.550332471162809e-2f);
    p = fmaf(p, f, 2.402264791363012e-1f);
    p = fmaf(p, f, 6.931472028550421e-1f);
    p = fmaf(p, f, 1.0f);
    return p * __int_as_float((e + 127) << 23);
}

#define MMA_F16(d, a, b0, b1)                                               \
    asm volatile("mma.sync.aligned.m16n8k16.row.col.f32.f16.f16.f32 "        \
                 "{%0,%1,%2,%3}, {%4,%5,%6,%7}, {%8,%9}, {%0,%1,%2,%3};"     \
                 : "+f"((d)[0]), "+f"((d)[1]), "+f"((d)[2]), "+f"((d)[3])    \
                 : "r"((a)[0]), "r"((a)[1]), "r"((a)[2]), "r"((a)[3]),       \
                   "r"(b0), "r"(b1))

#define LDM4(r, addr)                                                        \
    asm volatile("ldmatrix.sync.aligned.m8n8.x4.shared.b16 {%0,%1,%2,%3}, [%4];" \
                 : "=r"((r)[0]), "=r"((r)[1]), "=r"((r)[2]), "=r"((r)[3])    \
                 : "r"(addr))

__device__ __forceinline__ uint32_t pack_h2(float a, float b) {
    __half2 t;
    t.x = __float2half_rn(a);
    t.y = __float2half_rn(b);
    return *(uint32_t*)&t;
}

// split 8 fp32 values into hi/lo fp16 packs
__device__ __forceinline__ void split8(const float4& v0, const float4& v1,
                                       uint4& hi, uint4& lo) {
    float f[8] = { v0.x, v0.y, v0.z, v0.w, v1.x, v1.y, v1.z, v1.w };
    float h[8];
#pragma unroll
    for (int i = 0; i < 8; i++) h[i] = __half2float(__float2half_rn(f[i]));
    hi.x = pack_h2(f[0], f[1]); hi.y = pack_h2(f[2], f[3]);
    hi.z = pack_h2(f[4], f[5]); hi.w = pack_h2(f[6], f[7]);
    lo.x = pack_h2(f[0] - h[0], f[1] - h[1]);
    lo.y = pack_h2(f[2] - h[2], f[3] - h[3]);
    lo.z = pack_h2(f[4] - h[4], f[5] - h[5]);
    lo.w = pack_h2(f[6] - h[6], f[7] - h[7]);
}

// ---- projection GEMM via fp16 split-2 mma, 128x128 tile, fused cvt ------
// mode 0/1: split planes -> g_Qh2/g_Kh2 [b,h,n,d]
// mode 2:   split planes -> g_Vt2 [b,h,d,n] (transposed)
// mode 3:   fp32 row-major outPlain
__global__ void __launch_bounds__(256, 2) proj_mma_kernel(
    const float* __restrict__ A, const float* __restrict__ W,
    float* __restrict__ outPlain, int mode)
{
    __shared__ __align__(16) __half sP[2 * 4 * PPLANE];   // 49152 B
    const int tid = threadIdx.x, lane = tid & 31, w = tid >> 5;
    const int r0 = blockIdx.y << 7, c0 = blockIdx.x << 7;
    const int wm = (w & 1) << 6, wn = (w >> 1) << 5;

    const float* Ap = A + (size_t)(r0 + (tid >> 1)) * CDIM + (tid & 1) * 8;
    const float* Wp = W + (size_t)(c0 + (tid >> 1)) * CDIM + (tid & 1) * 8;
    const int sts = (tid >> 1) * PKP + (tid & 1) * 8;

    uint32_t sb = (uint32_t)__cvta_generic_to_shared(sP);
    const int lrow = (lane & 7) + ((lane >> 3) & 1) * 8;
    const int lk = (lane >> 4) * 8;
    uint32_t adA[2][4], adB[2][2];
#pragma unroll
    for (int p = 0; p < 2; p++) {
#pragma unroll
        for (int mt = 0; mt < 4; mt++)
            adA[p][mt] = sb + 2 * (p * PPLANE + (wm + 16 * mt + lrow) * PKP + lk);
#pragma unroll
        for (int g = 0; g < 2; g++)
            adB[p][g] = sb + 2 * ((2 + p) * PPLANE + (wn + 16 * g + lrow) * PKP + lk);
    }
    const uint32_t bufB = 4 * PPLANE * 2;

    float acc[4][4][4] = {};

#pragma unroll 1
    for (int ks = 0; ks < 32; ks++) {
        const int buf = ks & 1;
        float4 a0 = *(const float4*)(Ap + ks * 16);
        float4 a1 = *(const float4*)(Ap + ks * 16 + 4);
        float4 w0 = *(const float4*)(Wp + ks * 16);
        float4 w1 = *(const float4*)(Wp + ks * 16 + 4);
        uint4 ahi, alo, whi, wlo;
        split8(a0, a1, ahi, alo);
        split8(w0, w1, whi, wlo);

        __half* sbuf = sP + buf * 4 * PPLANE;
        *(uint4*)&sbuf[0 * PPLANE + sts] = ahi;
        *(uint4*)&sbuf[1 * PPLANE + sts] = alo;
        *(uint4*)&sbuf[2 * PPLANE + sts] = whi;
        *(uint4*)&sbuf[3 * PPLANE + sts] = wlo;
        __syncthreads();

        uint32_t bfr[2][2][4];
#pragma unroll
        for (int p = 0; p < 2; p++)
#pragma unroll
            for (int g = 0; g < 2; g++) LDM4(bfr[p][g], adB[p][g] + buf * bufB);
#pragma unroll
        for (int mt = 0; mt < 4; mt++) {
            uint32_t afr[2][4];
#pragma unroll
            for (int p = 0; p < 2; p++) LDM4(afr[p], adA[p][mt] + buf * bufB);
#pragma unroll
            for (int nt = 0; nt < 4; nt++) {
                int n2 = nt >> 1, j = nt & 1;
                MMA_F16(acc[mt][nt], afr[0], bfr[0][n2][j], bfr[0][n2][j + 2]); // hh
                MMA_F16(acc[mt][nt], afr[0], bfr[1][n2][j], bfr[1][n2][j + 2]); // hl
                MMA_F16(acc[mt][nt], afr[1], bfr[0][n2][j], bfr[0][n2][j + 2]); // lh
            }
        }
    }

    // epilogue
#pragma unroll
    for (int mt = 0; mt < 4; mt++)
#pragma unroll
        for (int nt = 0; nt < 4; nt++)
#pragma unroll
            for (int hf = 0; hf < 2; hf++) {
                int row = r0 + wm + 16 * mt + (lane >> 2) + hf * 8;
                int col = c0 + wn + 8 * nt + 2 * (lane & 3);
                float v0 = acc[mt][nt][hf * 2];
                float v1 = acc[mt][nt][hf * 2 + 1];
                if (mode == 3) {
                    *(float2*)&outPlain[(size_t)row * CDIM + col] = make_float2(v0, v1);
                } else {
                    int b = row >> 11, n = row & 2047;
                    int hh = col >> 6, d = col & 63;
                    __half h0 = __float2half_rn(v0), h1 = __float2half_rn(v1);
                    __half l0 = __float2half_rn(v0 - __half2float(h0));
                    __half l1 = __float2half_rn(v1 - __half2float(h1));
                    if (mode == 2) {
                        size_t idx = ((size_t)((b << 3) + hh) * HDIM + d) * SEQ + n;
                        g_Vt2[idx] = h0; g_Vt2[idx + SEQ] = h1;
                        g_Vt2[NQe + idx] = l0; g_Vt2[NQe + idx + SEQ] = l1;
                    } else {
                        __half* OH = (mode == 0) ? g_Qh2 : g_Kh2;
                        size_t idx = ((size_t)((b << 3) + hh) * SEQ + n) * HDIM + d;
                        __half2 hv; hv.x = h0; hv.y = h1;
                        __half2 lv; lv.x = l0; lv.y = l1;
                        *(__half2*)&OH[idx] = hv;
                        *(__half2*)&OH[NQe + idx] = lv;
                    }
                }
            }
}

// ---- S = (Qh @ Kh^T)*SCALE: 128x128 tile, whole-K resident, fused argmax
__global__ void __launch_bounds__(256, 2) qk_mma_kernel()
{
    extern __shared__ __align__(16) unsigned char smraw[];
    __half* sOp = (__half*)smraw;
    float* stag = (float*)smraw;

    const int tid = threadIdx.x, lane = tid & 31, w = tid >> 5;
    const int bh = blockIdx.z;
    const int r0 = blockIdx.y << 7, c0 = blockIdx.x << 7;
    const int wm = (w & 1) << 6;
    const int wn = (w >> 1) << 5;

    const __half* bases[4] = {
        g_Qh2 + (size_t)bh * SEQ * HDIM, g_Qh2 + (size_t)NQe + (size_t)bh * SEQ * HDIM,
        g_Kh2 + (size_t)bh * SEQ * HDIM, g_Kh2 + (size_t)NQe + (size_t)bh * SEQ * HDIM };
#pragma unroll
    for (int idx = tid; idx < 4096; idx += 256) {
        int arr = idx >> 10, rem = idx & 1023, row = rem >> 3, c = rem & 7;
        int gr = ((arr < 2) ? r0 : c0) + row;
        uint4 v = *(const uint4*)(bases[arr] + (size_t)gr * HDIM + c * 8);
        *(uint4*)(sOp + arr * OPSZ + row * KP2 + c * 8) = v;
    }
    __syncthreads();

    uint32_t sb = (uint32_t)__cvta_generic_to_shared(sOp);
    const int lrow = (lane & 7) + ((lane >> 3) & 1) * 8;
    const int lk = (lane >> 4) * 8;
    uint32_t adA[2][4], adB[2][2];
#pragma unroll
    for (int p = 0; p < 2; p++) {
#pragma unroll
        for (int mt = 0; mt < 4; mt++)
            adA[p][mt] = sb + 2 * (p * OPSZ + (wm + 16 * mt + lrow) * KP2 + lk);
#pragma unroll
        for (int g = 0; g < 2; g++)
            adB[p][g] = sb + 2 * ((2 + p) * OPSZ + (wn + 16 * g + lrow) * KP2 + lk);
    }

    float acc[4][4][4] = {};
#pragma unroll
    for (int ks = 0; ks < 4; ks++) {
        uint32_t bfr[2][2][4];
#pragma unroll
        for (int p = 0; p < 2; p++)
#pragma unroll
            for (int g = 0; g < 2; g++) LDM4(bfr[p][g], adB[p][g] + ks * 32);
#pragma unroll
        for (int mt = 0; mt < 4; mt++) {
            uint32_t afr[2][4];
#pragma unroll
            for (int p = 0; p < 2; p++) LDM4(afr[p], adA[p][mt] + ks * 32);
#pragma unroll
            for (int nt = 0; nt < 4; nt++) {
                int n2 = nt >> 1, j = nt & 1;
                MMA_F16(acc[mt][nt], afr[0], bfr[0][n2][j], bfr[0][n2][j + 2]);
                MMA_F16(acc[mt][nt], afr[0], bfr[1][n2][j], bfr[1][n2][j + 2]);
                MMA_F16(acc[mt][nt], afr[1], bfr[0][n2][j], bfr[0][n2][j + 2]);
            }
        }
    }
    __syncthreads();

#pragma unroll
    for (int mt = 0; mt < 4; mt++) {
        int row0 = wm + 16 * mt + (lane >> 2);
#pragma unroll
        for (int nt = 0; nt < 4; nt++) {
            int col = wn + 8 * nt + 2 * (lane & 3);
            *(float2*)&stag[row0 * STP2 + col] =
                make_float2(acc[mt][nt][0] * QKSCALE, acc[mt][nt][1] * QKSCALE);
            *(float2*)&stag[(row0 + 8) * STP2 + col] =
                make_float2(acc[mt][nt][2] * QKSCALE, acc[mt][nt][3] * QKSCALE);
        }
    }
    __syncthreads();

    float* Sp = g_S + (size_t)bh * SEQ * SEQ;
    {
        int row = tid >> 1, cb = (tid & 1) * 64;
#pragma unroll
        for (int i = 0; i < 16; i++)
            *(float4*)&Sp[(size_t)(r0 + row) * SEQ + c0 + cb + 4 * i] =
                *(const float4*)&stag[row * STP2 + cb + 4 * i];
    }

    if (tid < 128) {
        float best = -3e38f; int bi = 0;
#pragma unroll 8
        for (int i = 0; i < 128; i++) {
            float v = stag[tid * STP2 + i];
            if (v > best) { best = v; bi = i; }
        }
        size_t p = (size_t)(bh * 16 + blockIdx.x) * SEQ + r0 + tid;
        g_rpv[p] = best; g_rpi[p] = c0 + bi;
    } else {
        int c = tid - 128;
        float best = -3e38f; int bi = 0;
#pragma unroll 8
        for (int i = 0; i < 128; i++) {
            float v = stag[i * STP2 + c];
            if (v > best) { best = v; bi = i; }
        }
        size_t p = (size_t)(bh * 16 + blockIdx.y) * SEQ + c0 + c;
        g_cpv[p] = best; g_cpi[p] = r0 + bi;
    }
}

// ---------------- reduce 16 partials -> q2k and k2q ----------------------
__global__ void argmax_reduce_kernel()
{
    int gid = blockIdx.x * blockDim.x + threadIdx.x;
    int which = gid >= NBH * SEQ;
    int i = gid & (NBH * SEQ - 1);
    int bh = i >> 11, n = i & 2047;
    const float* pv = which ? g_cpv : g_rpv;
    const int*   pi = which ? g_cpi : g_rpi;
    float v = -3e38f; int idx = 0;
#pragma unroll
    for (int t = 0; t < 16; t++) {
        size_t p = (size_t)(bh * 16 + t) * SEQ + n;
        float ov = pv[p];
        if (ov > v) { v = ov; idx = pi[p]; }
    }
    (which ? g_k2q : g_q2k)[i] = idx;
}

// ---------------- cycle consistency -> additive mask ---------------------
__global__ void asso_kernel(const int* __restrict__ smask,
                            const float* __restrict__ svalid)
{
    int i = blockIdx.x * blockDim.x + threadIdx.x;
    int bh = i >> 11, m = i & 2047;
    int b = bh >> 3;
    int kq = g_k2q[i];
    int remap = g_q2k[(bh << 11) + kq];
    float valid = (smask[(b << 11) + m] == smask[(b << 11) + remap])
                      ? svalid[(b << 11) + m] : 1.0f;
    g_madd[i] = valid * -10000.0f;
}

// ---- fused exp + online row-sum + P@V, single-sync double-buffered ------
__global__ void __launch_bounds__(128) av_mma_kernel()
{
    __shared__ __align__(16) __half sAB[8 * PLANE];
    __shared__ float sL[64];

    const int bh = blockIdx.y;
    const int n0 = blockIdx.x << 6;
    const int b = bh >> 3, h = bh & 7;
    const int tid = threadIdx.x, lane = tid & 31, w = tid >> 5;
    const int wm = (w & 1) << 5, wn = (w >> 1) << 5;

    const float* Sp = g_S + (size_t)bh * SEQ * SEQ + (size_t)(n0 + (tid >> 1)) * SEQ + (tid & 1) * 8;
    const float* mp = g_madd + bh * SEQ + (tid & 1) * 8;
    const size_t voff = (size_t)bh * HDIM * SEQ + (size_t)(tid >> 1) * SEQ + (tid & 1) * 8;
    const __half* vp[2] = { g_Vt2 + voff, g_Vt2 + (size_t)NQe + voff };
    const int sts = (tid >> 1) * KP + (tid & 1) * 8;

    uint32_t sbase = (uint32_t)__cvta_generic_to_shared(sAB);
    const int lrow = (lane & 7) + ((lane >> 3) & 1) * 8;
    const int lk = (lane >> 4) * 8;
    uint32_t adA[2][2], adB[2][2];
#pragma unroll
    for (int p = 0; p < 2; p++)
#pragma unroll
        for (int t = 0; t < 2; t++) {
            adA[p][t] = sbase + 2 * (p * PLANE + (wm + 16 * t + lrow) * KP + lk);
            adB[p][t] = sbase + 2 * ((2 + p) * PLANE + (wn + 16 * t + lrow) * KP + lk);
        }
    const uint32_t bufB = 4 * PLANE * 2;

    float acc[2][4][4] = {};
    float runL = 0.0f;

#pragma unroll 1
    for (int ks = 0; ks < 128; ks++) {
        const int buf = ks & 1;
        float4 s0 = *(const float4*)(Sp + ks * 16);
        float4 s1 = *(const float4*)(Sp + ks * 16 + 4);
        float4 m0 = *(const float4*)(mp + ks * 16);
        float4 m1 = *(const float4*)(mp + ks * 16 + 4);
        uint4 v0 = *(const uint4*)(vp[0] + ks * 16);
        uint4 v1 = *(const uint4*)(vp[1] + ks * 16);

        float pv[8];
        pv[0] = fexp(s0.x + m0.x); pv[1] = fexp(s0.y + m0.y);
        pv[2] = fexp(s0.z + m0.z); pv[3] = fexp(s0.w + m0.w);
        pv[4] = fexp(s1.x + m1.x); pv[5] = fexp(s1.y + m1.y);
        pv[6] = fexp(s1.z + m1.z); pv[7] = fexp(s1.w + m1.w);
        runL += ((pv[0] + pv[1]) + (pv[2] + pv[3])) + ((pv[4] + pv[5]) + (pv[6] + pv[7]));

        uint4 ph, pl;
        float hs[8];
#pragma unroll
        for (int i = 0; i < 8; i++)
            hs[i] = __half2float(__float2half_rn(pv[i]));
        ph.x = pack_h2(pv[0], pv[1]); ph.y = pack_h2(pv[2], pv[3]);
        ph.z = pack_h2(pv[4], pv[5]); ph.w = pack_h2(pv[6], pv[7]);
        pl.x = pack_h2(pv[0] - hs[0], pv[1] - hs[1]);
        pl.y = pack_h2(pv[2] - hs[2], pv[3] - hs[3]);
        pl.z = pack_h2(pv[4] - hs[4], pv[5] - hs[5]);
        pl.w = pack_h2(pv[6] - hs[6], pv[7] - hs[7]);

        __half* sbuf = sAB + buf * 4 * PLANE;
        *(uint4*)&sbuf[0 * PLANE + sts] = ph;
        *(uint4*)&sbuf[1 * PLANE + sts] = pl;
        *(uint4*)&sbuf[2 * PLANE + sts] = v0;
        *(uint4*)&sbuf[3 * PLANE + sts] = v1;
        __syncthreads();

        uint32_t afr[2][2][4], bfr[2][2][4];
#pragma unroll
        for (int p = 0; p < 2; p++)
#pragma unroll
            for (int t = 0; t < 2; t++) {
                LDM4(afr[p][t], adA[p][t] + buf * bufB);
                LDM4(bfr[p][t], adB[p][t] + buf * bufB);
            }

        const int pa[3] = {0, 0, 1};
        const int pb[3] = {0, 1, 0};
#pragma unroll
        for (int c = 0; c < 3; c++)
#pragma unroll
            for (int mt = 0; mt < 2; mt++)
#pragma unroll
                for (int nt = 0; nt < 4; nt++) {
                    int n2 = nt >> 1, j = nt & 1;
                    MMA_F16(acc[mt][nt], afr[pa[c]][mt], bfr[pb[c]][n2][j], bfr[pb[c]][n2][j + 2]);
                }
    }

    runL += __shfl_xor_sync(0xffffffffu, runL, 1);
    if (!(tid & 1)) sL[tid >> 1] = runL;
    __syncthreads();

#pragma unroll
    for (int mt = 0; mt < 2; mt++) {
        int row0 = wm + 16 * mt + (lane >> 2);
        float inv0 = 1.0f / sL[row0];
        float inv1 = 1.0f / sL[row0 + 8];
#pragma unroll
        for (int nt = 0; nt < 4; nt++) {
            int col = wn + 8 * nt + 2 * (lane & 3);
            int n = n0 + row0;
            *(float2*)&g_X[(size_t)(b * SEQ + n) * CDIM + h * HDIM + col] =
                make_float2(acc[mt][nt][0] * inv0, acc[mt][nt][1] * inv0);
            *(float2*)&g_X[(size_t)(b * SEQ + n + 8) * CDIM + h * HDIM + col] =
                make_float2(acc[mt][nt][2] * inv1, acc[mt][nt][3] * inv1);
        }
    }
}

// ---------------- launcher ------------------------------------------------
extern "C" void kernel_launch(void* const* d_in, const int* in_sizes, int n_in,
                              void* d_out, int out_size)
{
    const float* q   = (const float*)d_in[0];
    const float* k   = (const float*)d_in[1];
    const float* v   = (const float*)d_in[2];
    const float* svm = (const float*)d_in[3];
    const int*   sm  = (const int*)d_in[4];
    const float* Wq  = (const float*)d_in[5];
    const float* Wk  = (const float*)d_in[6];
    const float* Wv  = (const float*)d_in[7];
    const float* Wp  = (const float*)d_in[8];
    float* out = (float*)d_out;

    float* X;
    cudaGetSymbolAddress((void**)&X, g_X);

    cudaFuncSetAttribute(qk_mma_kernel,
                         cudaFuncAttributeMaxDynamicSharedMemorySize, QK_SMEM);

    dim3 gp(CDIM / 128, (2 * SEQ) / 128);   // (4, 32)
    proj_mma_kernel<<<gp, 256>>>(q, Wq, nullptr, 0);
    proj_mma_kernel<<<gp, 256>>>(k, Wk, nullptr, 1);
    proj_mma_kernel<<<gp, 256>>>(v, Wv, nullptr, 2);

    qk_mma_kernel<<<dim3(SEQ / 128, SEQ / 128, NBH), 256, QK_SMEM>>>();

    argmax_reduce_kernel<<<(2 * NBH * SEQ) / 256, 256>>>();
    asso_kernel<<<(NBH * SEQ) / 256, 256>>>(sm, svm);

    av_mma_kernel<<<dim3(SEQ / 64, NBH), 128>>>();

    proj_mma_kernel<<<gp, 256>>>(X, Wp, out, 3);
}

// round 11
// speedup vs baseline: 1.9095x; 1.1108x over previous
#include <cuda_runtime.h>
#include <cuda_fp16.h>
#include <cstdint>

#define SEQ   2048
#define HDIM  64
#define NHEAD 8
#define CDIM  512
#define NBH   16            // B*H
#define QKSCALE 0.125f
#define KP    24            // smem tile pitch in halfs (48B, ldmatrix conflict-free)
#define PLANE (64 * KP)     // halfs per 64x16 padded tile
#define KP2   72            // qk128 operand pitch in halfs (144B)
#define OPSZ  (128 * KP2)   // halfs per operand array (9216)
#define STP2  132           // qk128 staging pitch (floats)
#define QK_SMEM (4 * OPSZ * 2)   // 73728 B
#define PKP   24            // proj smem pitch (halfs)
#define PPLANE (128 * PKP)  // 3072 halfs per 128x16 plane

constexpr int NQe = NBH * SEQ * HDIM;   // 2,097,152 elements per plane

// ---------------- scratch (device globals; no allocation) ----------------
__device__ __half g_Qh2[2 * NBH * SEQ * HDIM];    // hi/lo fp16 planes
__device__ __half g_Kh2[2 * NBH * SEQ * HDIM];
__device__ __half g_Vt2[2 * NBH * HDIM * SEQ];    // V transposed [bh][d][s]
__device__ float g_X[2 * SEQ * CDIM];             // attention output fp32
__device__ __half g_S[(size_t)NBH * SEQ * SEQ];   // scores, fp16 (134 MB)
__device__ int   g_q2k[NBH * SEQ];
__device__ int   g_k2q[NBH * SEQ];
__device__ float g_madd[NBH * SEQ];
__device__ float g_rpv[NBH * 16 * SEQ];
__device__ int   g_rpi[NBH * 16 * SEQ];
__device__ float g_cpv[NBH * 16 * SEQ];
__device__ int   g_cpi[NBH * 16 * SEQ];

// fast exp on the FMA pipe. |rel err| ~1e-7.
__device__ __forceinline__ float fexp(float x) {
    float y = x * 1.4426950408889634f;
    y = fminf(fmaxf(y, -126.0f), 126.0f);
    float t = y + 12582912.0f;
    int   e = __float_as_int(t) - 0x4B400000;
    float r = t - 12582912.0f;
    float f = y - r;
    float p = 1.535336188319500e-4f;
    p = fmaf(p, f, 1.339887440266574e-3f);
    p = fmaf(p, f, 9.618437357674640e-3f);
    p = fmaf(p, f, 5.550332471162809e-2f);
    p = fmaf(p, f, 2.402264791363012e-1f);
    p = fmaf(p, f, 6.931472028550421e-1f);
    p = fmaf(p, f, 1.0f);
    return p * __int_as_float((e + 127) << 23);
}

#define MMA_F16(d, a, b0, b1)                                               \
    asm volatile("mma.sync.aligned.m16n8k16.row.col.f32.f16.f16.f32 "        \
                 "{%0,%1,%2,%3}, {%4,%5,%6,%7}, {%8,%9}, {%0,%1,%2,%3};"     \
                 : "+f"((d)[0]), "+f"((d)[1]), "+f"((d)[2]), "+f"((d)[3])    \
                 : "r"((a)[0]), "r"((a)[1]), "r"((a)[2]), "r"((a)[3]),       \
                   "r"(b0), "r"(b1))

#define LDM4(r, addr)                                                        \
    asm volatile("ldmatrix.sync.aligned.m8n8.x4.shared.b16 {%0,%1,%2,%3}, [%4];" \
                 : "=r"((r)[0]), "=r"((r)[1]), "=r"((r)[2]), "=r"((r)[3])    \
                 : "r"(addr))

__device__ __forceinline__ uint32_t pack_h2(float a, float b) {
    __half2 t;
    t.x = __float2half_rn(a);
    t.y = __float2half_rn(b);
    return *(uint32_t*)&t;
}

// split 8 fp32 values into hi/lo fp16 packs
__device__ __forceinline__ void split8(const float4& v0, const float4& v1,
                                       uint4& hi, uint4& lo) {
    float f[8] = { v0.x, v0.y, v0.z, v0.w, v1.x, v1.y, v1.z, v1.w };
    float h[8];
#pragma unroll
    for (int i = 0; i < 8; i++) h[i] = __half2float(__float2half_rn(f[i]));
    hi.x = pack_h2(f[0], f[1]); hi.y = pack_h2(f[2], f[3]);
    hi.z = pack_h2(f[4], f[5]); hi.w = pack_h2(f[6], f[7]);
    lo.x = pack_h2(f[0] - h[0], f[1] - h[1]);
    lo.y = pack_h2(f[2] - h[2], f[3] - h[3]);
    lo.z = pack_h2(f[4] - h[4], f[5] - h[5]);
    lo.w = pack_h2(f[6] - h[6], f[7] - h[7]);
}

// ---- projection GEMM via fp16 split-2 mma, 128x128 tile, fused cvt ------
__global__ void __launch_bounds__(256, 2) proj_mma_kernel(
    const float* __restrict__ A, const float* __restrict__ W,
    float* __restrict__ outPlain, int mode)
{
    __shared__ __align__(16) __half sP[2 * 4 * PPLANE];   // 49152 B
    const int tid = threadIdx.x, lane = tid & 31, w = tid >> 5;
    const int r0 = blockIdx.y << 7, c0 = blockIdx.x << 7;
    const int wm = (w & 1) << 6, wn = (w >> 1) << 5;

    const float* Ap = A + (size_t)(r0 + (tid >> 1)) * CDIM + (tid & 1) * 8;
    const float* Wp = W + (size_t)(c0 + (tid >> 1)) * CDIM + (tid & 1) * 8;
    const int sts = (tid >> 1) * PKP + (tid & 1) * 8;

    uint32_t sb = (uint32_t)__cvta_generic_to_shared(sP);
    const int lrow = (lane & 7) + ((lane >> 3) & 1) * 8;
    const int lk = (lane >> 4) * 8;
    uint32_t adA[2][4], adB[2][2];
#pragma unroll
    for (int p = 0; p < 2; p++) {
#pragma unroll
        for (int mt = 0; mt < 4; mt++)
            adA[p][mt] = sb + 2 * (p * PPLANE + (wm + 16 * mt + lrow) * PKP + lk);
#pragma unroll
        for (int g = 0; g < 2; g++)
            adB[p][g] = sb + 2 * ((2 + p) * PPLANE + (wn + 16 * g + lrow) * PKP + lk);
    }
    const uint32_t bufB = 4 * PPLANE * 2;

    float acc[4][4][4] = {};

#pragma unroll 1
    for (int ks = 0; ks < 32; ks++) {
        const int buf = ks & 1;
        float4 a0 = *(const float4*)(Ap + ks * 16);
        float4 a1 = *(const float4*)(Ap + ks * 16 + 4);
        float4 w0 = *(const float4*)(Wp + ks * 16);
        float4 w1 = *(const float4*)(Wp + ks * 16 + 4);
        uint4 ahi, alo, whi, wlo;
        split8(a0, a1, ahi, alo);
        split8(w0, w1, whi, wlo);

        __half* sbuf = sP + buf * 4 * PPLANE;
        *(uint4*)&sbuf[0 * PPLANE + sts] = ahi;
        *(uint4*)&sbuf[1 * PPLANE + sts] = alo;
        *(uint4*)&sbuf[2 * PPLANE + sts] = whi;
        *(uint4*)&sbuf[3 * PPLANE + sts] = wlo;
        __syncthreads();

        uint32_t bfr[2][2][4];
#pragma unroll
        for (int p = 0; p < 2; p++)
#pragma unroll
            for (int g = 0; g < 2; g++) LDM4(bfr[p][g], adB[p][g] + buf * bufB);
#pragma unroll
        for (int mt = 0; mt < 4; mt++) {
            uint32_t afr[2][4];
#pragma unroll
            for (int p = 0; p < 2; p++) LDM4(afr[p], adA[p][mt] + buf * bufB);
#pragma unroll
            for (int nt = 0; nt < 4; nt++) {
                int n2 = nt >> 1, j = nt & 1;
                MMA_F16(acc[mt][nt], afr[0], bfr[0][n2][j], bfr[0][n2][j + 2]); // hh
                MMA_F16(acc[mt][nt], afr[0], bfr[1][n2][j], bfr[1][n2][j + 2]); // hl
                MMA_F16(acc[mt][nt], afr[1], bfr[0][n2][j], bfr[0][n2][j + 2]); // lh
            }
        }
    }

    // epilogue
#pragma unroll
    for (int mt = 0; mt < 4; mt++)
#pragma unroll
        for (int nt = 0; nt < 4; nt++)
#pragma unroll
            for (int hf = 0; hf < 2; hf++) {
                int row = r0 + wm + 16 * mt + (lane >> 2) + hf * 8;
                int col = c0 + wn + 8 * nt + 2 * (lane & 3);
                float v0 = acc[mt][nt][hf * 2];
                float v1 = acc[mt][nt][hf * 2 + 1];
                if (mode == 3) {
                    *(float2*)&outPlain[(size_t)row * CDIM + col] = make_float2(v0, v1);
                } else {
                    int b = row >> 11, n = row & 2047;
                    int hh = col >> 6, d = col & 63;
                    __half h0 = __float2half_rn(v0), h1 = __float2half_rn(v1);
                    __half l0 = __float2half_rn(v0 - __half2float(h0));
                    __half l1 = __float2half_rn(v1 - __half2float(h1));
                    if (mode == 2) {
                        size_t idx = ((size_t)((b << 3) + hh) * HDIM + d) * SEQ + n;
                        g_Vt2[idx] = h0; g_Vt2[idx + SEQ] = h1;
                        g_Vt2[NQe + idx] = l0; g_Vt2[NQe + idx + SEQ] = l1;
                    } else {
                        __half* OH = (mode == 0) ? g_Qh2 : g_Kh2;
                        size_t idx = ((size_t)((b << 3) + hh) * SEQ + n) * HDIM + d;
                        __half2 hv; hv.x = h0; hv.y = h1;
                        __half2 lv; lv.x = l0; lv.y = l1;
                        *(__half2*)&OH[idx] = hv;
                        *(__half2*)&OH[NQe + idx] = lv;
                    }
                }
            }
}

// ---- S = (Qh @ Kh^T)*SCALE: 128x128 tile, fp16 S store, fused argmax ----
__global__ void __launch_bounds__(256, 2) qk_mma_kernel()
{
    extern __shared__ __align__(16) unsigned char smraw[];
    __half* sOp = (__half*)smraw;
    float* stag = (float*)smraw;

    const int tid = threadIdx.x, lane = tid & 31, w = tid >> 5;
    const int bh = blockIdx.z;
    const int r0 = blockIdx.y << 7, c0 = blockIdx.x << 7;
    const int wm = (w & 1) << 6;
    const int wn = (w >> 1) << 5;

    const __half* bases[4] = {
        g_Qh2 + (size_t)bh * SEQ * HDIM, g_Qh2 + (size_t)NQe + (size_t)bh * SEQ * HDIM,
        g_Kh2 + (size_t)bh * SEQ * HDIM, g_Kh2 + (size_t)NQe + (size_t)bh * SEQ * HDIM };
#pragma unroll
    for (int idx = tid; idx < 4096; idx += 256) {
        int arr = idx >> 10, rem = idx & 1023, row = rem >> 3, c = rem & 7;
        int gr = ((arr < 2) ? r0 : c0) + row;
        uint4 v = *(const uint4*)(bases[arr] + (size_t)gr * HDIM + c * 8);
        *(uint4*)(sOp + arr * OPSZ + row * KP2 + c * 8) = v;
    }
    __syncthreads();

    uint32_t sb = (uint32_t)__cvta_generic_to_shared(sOp);
    const int lrow = (lane & 7) + ((lane >> 3) & 1) * 8;
    const int lk = (lane >> 4) * 8;
    uint32_t adA[2][4], adB[2][2];
#pragma unroll
    for (int p = 0; p < 2; p++) {
#pragma unroll
        for (int mt = 0; mt < 4; mt++)
            adA[p][mt] = sb + 2 * (p * OPSZ + (wm + 16 * mt + lrow) * KP2 + lk);
#pragma unroll
        for (int g = 0; g < 2; g++)
            adB[p][g] = sb + 2 * ((2 + p) * OPSZ + (wn + 16 * g + lrow) * KP2 + lk);
    }

    float acc[4][4][4] = {};
#pragma unroll
    for (int ks = 0; ks < 4; ks++) {
        uint32_t bfr[2][2][4];
#pragma unroll
        for (int p = 0; p < 2; p++)
#pragma unroll
            for (int g = 0; g < 2; g++) LDM4(bfr[p][g], adB[p][g] + ks * 32);
#pragma unroll
        for (int mt = 0; mt < 4; mt++) {
            uint32_t afr[2][4];
#pragma unroll
            for (int p = 0; p < 2; p++) LDM4(afr[p], adA[p][mt] + ks * 32);
#pragma unroll
            for (int nt = 0; nt < 4; nt++) {
                int n2 = nt >> 1, j = nt & 1;
                MMA_F16(acc[mt][nt], afr[0], bfr[0][n2][j], bfr[0][n2][j + 2]);
                MMA_F16(acc[mt][nt], afr[0], bfr[1][n2][j], bfr[1][n2][j + 2]);
                MMA_F16(acc[mt][nt], afr[1], bfr[0][n2][j], bfr[0][n2][j + 2]);
            }
        }
    }
    __syncthreads();

#pragma unroll
    for (int mt = 0; mt < 4; mt++) {
        int row0 = wm + 16 * mt + (lane >> 2);
#pragma unroll
        for (int nt = 0; nt < 4; nt++) {
            int col = wn + 8 * nt + 2 * (lane & 3);
            *(float2*)&stag[row0 * STP2 + col] =
                make_float2(acc[mt][nt][0] * QKSCALE, acc[mt][nt][1] * QKSCALE);
            *(float2*)&stag[(row0 + 8) * STP2 + col] =
                make_float2(acc[mt][nt][2] * QKSCALE, acc[mt][nt][3] * QKSCALE);
        }
    }
    __syncthreads();

    // coalesced fp16 S store
    __half* Sp = g_S + (size_t)bh * SEQ * SEQ;
    {
        int row = tid >> 1, cb = (tid & 1) * 64;
#pragma unroll
        for (int i = 0; i < 8; i++) {
            float4 f0 = *(const float4*)&stag[row * STP2 + cb + 8 * i];
            float4 f1 = *(const float4*)&stag[row * STP2 + cb + 8 * i + 4];
            uint4 o;
            o.x = pack_h2(f0.x, f0.y); o.y = pack_h2(f0.z, f0.w);
            o.z = pack_h2(f1.x, f1.y); o.w = pack_h2(f1.z, f1.w);
            *(uint4*)&Sp[(size_t)(r0 + row) * SEQ + c0 + cb + 8 * i] = o;
        }
    }

    // first-occurrence row/col argmax partials
    if (tid < 128) {
        float best = -3e38f; int bi = 0;
#pragma unroll 8
        for (int i = 0; i < 32; i++) {
            float4 v = *(const float4*)&stag[tid * STP2 + 4 * i];
            if (v.x > best) { best = v.x; bi = 4 * i; }
            if (v.y > best) { best = v.y; bi = 4 * i + 1; }
            if (v.z > best) { best = v.z; bi = 4 * i + 2; }
            if (v.w > best) { best = v.w; bi = 4 * i + 3; }
        }
        size_t p = (size_t)(bh * 16 + blockIdx.x) * SEQ + r0 + tid;
        g_rpv[p] = best; g_rpi[p] = c0 + bi;
    } else {
        int c = tid - 128;
        float best = -3e38f; int bi = 0;
#pragma unroll 8
        for (int i = 0; i < 128; i++) {
            float v = stag[i * STP2 + c];
            if (v > best) { best = v; bi = i; }
        }
        size_t p = (size_t)(bh * 16 + blockIdx.y) * SEQ + c0 + c;
        g_cpv[p] = best; g_cpi[p] = r0 + bi;
    }
}

// ---------------- reduce 16 partials -> q2k and k2q ----------------------
__global__ void argmax_reduce_kernel()
{
    int gid = blockIdx.x * blockDim.x + threadIdx.x;
    int which = gid >= NBH * SEQ;
    int i = gid & (NBH * SEQ - 1);
    int bh = i >> 11, n = i & 2047;
    const float* pv = which ? g_cpv : g_rpv;
    const int*   pi = which ? g_cpi : g_rpi;
    float v = -3e38f; int idx = 0;
#pragma unroll
    for (int t = 0; t < 16; t++) {
        size_t p = (size_t)(bh * 16 + t) * SEQ + n;
        float ov = pv[p];
        if (ov > v) { v = ov; idx = pi[p]; }
    }
    (which ? g_k2q : g_q2k)[i] = idx;
}

// ---------------- cycle consistency -> additive mask ---------------------
__global__ void asso_kernel(const int* __restrict__ smask,
                            const float* __restrict__ svalid)
{
    int i = blockIdx.x * blockDim.x + threadIdx.x;
    int bh = i >> 11, m = i & 2047;
    int b = bh >> 3;
    int kq = g_k2q[i];
    int remap = g_q2k[(bh << 11) + kq];
    float valid = (smask[(b << 11) + m] == smask[(b << 11) + remap])
                      ? svalid[(b << 11) + m] : 1.0f;
    g_madd[i] = valid * -10000.0f;
}

// ---- fused exp + online row-sum + P@V, fp16 S read ----------------------
__global__ void __launch_bounds__(128) av_mma_kernel()
{
    __shared__ __align__(16) __half sAB[8 * PLANE];
    __shared__ float sL[64];

    const int bh = blockIdx.y;
    const int n0 = blockIdx.x << 6;
    const int b = bh >> 3, h = bh & 7;
    const int tid = threadIdx.x, lane = tid & 31, w = tid >> 5;
    const int wm = (w & 1) << 5, wn = (w >> 1) << 5;

    const __half* Sp = g_S + (size_t)bh * SEQ * SEQ + (size_t)(n0 + (tid >> 1)) * SEQ + (tid & 1) * 8;
    const float* mp = g_madd + bh * SEQ + (tid & 1) * 8;
    const size_t voff = (size_t)bh * HDIM * SEQ + (size_t)(tid >> 1) * SEQ + (tid & 1) * 8;
    const __half* vp[2] = { g_Vt2 + voff, g_Vt2 + (size_t)NQe + voff };
    const int sts = (tid >> 1) * KP + (tid & 1) * 8;

    uint32_t sbase = (uint32_t)__cvta_generic_to_shared(sAB);
    const int lrow = (lane & 7) + ((lane >> 3) & 1) * 8;
    const int lk = (lane >> 4) * 8;
    uint32_t adA[2][2], adB[2][2];
#pragma unroll
    for (int p = 0; p < 2; p++)
#pragma unroll
        for (int t = 0; t < 2; t++) {
            adA[p][t] = sbase + 2 * (p * PLANE + (wm + 16 * t + lrow) * KP + lk);
            adB[p][t] = sbase + 2 * ((2 + p) * PLANE + (wn + 16 * t + lrow) * KP + lk);
        }
    const uint32_t bufB = 4 * PLANE * 2;

    float acc[2][4][4] = {};
    float runL = 0.0f;

#pragma unroll 1
    for (int ks = 0; ks < 128; ks++) {
        const int buf = ks & 1;
        uint4 sv = *(const uint4*)(Sp + ks * 16);        // 8 halfs
        float4 m0 = *(const float4*)(mp + ks * 16);
        float4 m1 = *(const float4*)(mp + ks * 16 + 4);
        uint4 v0 = *(const uint4*)(vp[0] + ks * 16);
        uint4 v1 = *(const uint4*)(vp[1] + ks * 16);

        float2 s01 = __half22float2(*(__half2*)&sv.x);
        float2 s23 = __half22float2(*(__half2*)&sv.y);
        float2 s45 = __half22float2(*(__half2*)&sv.z);
        float2 s67 = __half22float2(*(__half2*)&sv.w);

        float pv[8];
        pv[0] = fexp(s01.x + m0.x); pv[1] = fexp(s01.y + m0.y);
        pv[2] = fexp(s23.x + m0.z); pv[3] = fexp(s23.y + m0.w);
        pv[4] = fexp(s45.x + m1.x); pv[5] = fexp(s45.y + m1.y);
        pv[6] = fexp(s67.x + m1.z); pv[7] = fexp(s67.y + m1.w);
        runL += ((pv[0] + pv[1]) + (pv[2] + pv[3])) + ((pv[4] + pv[5]) + (pv[6] + pv[7]));

        uint4 ph, pl;
        float hs[8];
#pragma unroll
        for (int i = 0; i < 8; i++)
            hs[i] = __half2float(__float2half_rn(pv[i]));
        ph.x = pack_h2(pv[0], pv[1]); ph.y = pack_h2(pv[2], pv[3]);
        ph.z = pack_h2(pv[4], pv[5]); ph.w = pack_h2(pv[6], pv[7]);
        pl.x = pack_h2(pv[0] - hs[0], pv[1] - hs[1]);
        pl.y = pack_h2(pv[2] - hs[2], pv[3] - hs[3]);
        pl.z = pack_h2(pv[4] - hs[4], pv[5] - hs[5]);
        pl.w = pack_h2(pv[6] - hs[6], pv[7] - hs[7]);

        __half* sbuf = sAB + buf * 4 * PLANE;
        *(uint4*)&sbuf[0 * PLANE + sts] = ph;
        *(uint4*)&sbuf[1 * PLANE + sts] = pl;
        *(uint4*)&sbuf[2 * PLANE + sts] = v0;
        *(uint4*)&sbuf[3 * PLANE + sts] = v1;
        __syncthreads();

        uint32_t afr[2][2][4], bfr[2][2][4];
#pragma unroll
        for (int p = 0; p < 2; p++)
#pragma unroll
            for (int t = 0; t < 2; t++) {
                LDM4(afr[p][t], adA[p][t] + buf * bufB);
                LDM4(bfr[p][t], adB[p][t] + buf * bufB);
            }

        const int pa[3] = {0, 0, 1};
        const int pb[3] = {0, 1, 0};
#pragma unroll
        for (int c = 0; c < 3; c++)
#pragma unroll
            for (int mt = 0; mt < 2; mt++)
#pragma unroll
                for (int nt = 0; nt < 4; nt++) {
                    int n2 = nt >> 1, j = nt & 1;
                    MMA_F16(acc[mt][nt], afr[pa[c]][mt], bfr[pb[c]][n2][j], bfr[pb[c]][n2][j + 2]);
                }
    }

    runL += __shfl_xor_sync(0xffffffffu, runL, 1);
    if (!(tid & 1)) sL[tid >> 1] = runL;
    __syncthreads();

#pragma unroll
    for (int mt = 0; mt < 2; mt++) {
        int row0 = wm + 16 * mt + (lane >> 2);
        float inv0 = 1.0f / sL[row0];
        float inv1 = 1.0f / sL[row0 + 8];
#pragma unroll
        for (int nt = 0; nt < 4; nt++) {
            int col = wn + 8 * nt + 2 * (lane & 3);
            int n = n0 + row0;
            *(float2*)&g_X[(size_t)(b * SEQ + n) * CDIM + h * HDIM + col] =
                make_float2(acc[mt][nt][0] * inv0, acc[mt][nt][1] * inv0);
            *(float2*)&g_X[(size_t)(b * SEQ + n + 8) * CDIM + h * HDIM + col] =
                make_float2(acc[mt][nt][2] * inv1, acc[mt][nt][3] * inv1);
        }
    }
}

// ---------------- launcher ------------------------------------------------
extern "C" void kernel_launch(void* const* d_in, const int* in_sizes, int n_in,
                              void* d_out, int out_size)
{
    const float* q   = (const float*)d_in[0];
    const float* k   = (const float*)d_in[1];
    const float* v   = (const float*)d_in[2];
    const float* svm = (const float*)d_in[3];
    const int*   sm  = (const int*)d_in[4];
    const float* Wq  = (const float*)d_in[5];
    const float* Wk  = (const float*)d_in[6];
    const float* Wv  = (const float*)d_in[7];
    const float* Wp  = (const float*)d_in[8];
    float* out = (float*)d_out;

    float* X;
    cudaGetSymbolAddress((void**)&X, g_X);

    cudaFuncSetAttribute(qk_mma_kernel,
                         cudaFuncAttributeMaxDynamicSharedMemorySize, QK_SMEM);

    dim3 gp(CDIM / 128, (2 * SEQ) / 128);   // (4, 32)
    proj_mma_kernel<<<gp, 256>>>(q, Wq, nullptr, 0);
    proj_mma_kernel<<<gp, 256>>>(k, Wk, nullptr, 1);
    proj_mma_kernel<<<gp, 256>>>(v, Wv, nullptr, 2);

    qk_mma_kernel<<<dim3(SEQ / 128, SEQ / 128, NBH), 256, QK_SMEM>>>();

    argmax_reduce_kernel<<<(2 * NBH * SEQ) / 256, 256>>>();
    asso_kernel<<<(NBH * SEQ) / 256, 256>>>(sm, svm);

    av_mma_kernel<<<dim3(SEQ / 64, NBH), 128>>>();

    proj_mma_kernel<<<gp, 256>>>(X, Wp, out, 3);
}

// round 12
// speedup vs baseline: 1.9678x; 1.0305x over previous
#include <cuda_runtime.h>
#include <cuda_fp16.h>
#include <cstdint>

#define SEQ   2048
#define HDIM  64
#define NHEAD 8
#define CDIM  512
#define NBH   16            // B*H
#define QKSCALE 0.125f
#define KP    24            // smem tile pitch in halfs (48B, ldmatrix conflict-free)
#define PLANE (64 * KP)     // halfs per 64x16 padded tile
#define KP2   72            // qk128 operand pitch in halfs (144B)
#define OPSZ  (128 * KP2)   // halfs per operand array (9216)
#define SHP   136           // qk fp16 staging pitch in halfs (272B, conflict-free u32)
#define QK_SMEM (4 * OPSZ * 2)   // 73728 B
#define PKP   24            // proj smem pitch (halfs)
#define PPLANE (128 * PKP)  // 3072 halfs per 128x16 plane

constexpr int NQe = NBH * SEQ * HDIM;   // 2,097,152 elements per plane

// ---------------- scratch (device globals; no allocation) ----------------
__device__ __half g_Qh2[2 * NBH * SEQ * HDIM];    // hi/lo fp16 planes
__device__ __half g_Kh2[2 * NBH * SEQ * HDIM];
__device__ __half g_Vt2[2 * NBH * HDIM * SEQ];    // V transposed [bh][d][s]
__device__ float g_X[2 * SEQ * CDIM];             // attention output fp32
__device__ __half g_S[(size_t)NBH * SEQ * SEQ];   // scores, fp16 (134 MB)
__device__ int   g_q2k[NBH * SEQ];
__device__ int   g_k2q[NBH * SEQ];
__device__ float g_madd[NBH * SEQ];
__device__ float g_rpv[NBH * 16 * SEQ];
__device__ int   g_rpi[NBH * 16 * SEQ];
__device__ float g_cpv[NBH * 16 * SEQ];
__device__ int   g_cpi[NBH * 16 * SEQ];

// fast exp on the FMA pipe. |rel err| ~1e-7.
__device__ __forceinline__ float fexp(float x) {
    float y = x * 1.4426950408889634f;
    y = fminf(fmaxf(y, -126.0f), 126.0f);
    float t = y + 12582912.0f;
    int   e = __float_as_int(t) - 0x4B400000;
    float r = t - 12582912.0f;
    float f = y - r;
    float p = 1.535336188319500e-4f;
    p = fmaf(p, f, 1.339887440266574e-3f);
    p = fmaf(p, f, 9.618437357674640e-3f);
    p = fmaf(p, f, 5.550332471162809e-2f);
    p = fmaf(p, f, 2.402264791363012e-1f);
    p = fmaf(p, f, 6.931472028550421e-1f);
    p = fmaf(p, f, 1.0f);
    return p * __int_as_float((e + 127) << 23);
}

#define MMA_F16(d, a, b0, b1)                                               \
    asm volatile("mma.sync.aligned.m16n8k16.row.col.f32.f16.f16.f32 "        \
                 "{%0,%1,%2,%3}, {%4,%5,%6,%7}, {%8,%9}, {%0,%1,%2,%3};"     \
                 : "+f"((d)[0]), "+f"((d)[1]), "+f"((d)[2]), "+f"((d)[3])    \
                 : "r"((a)[0]), "r"((a)[1]), "r"((a)[2]), "r"((a)[3]),       \
                   "r"(b0), "r"(b1))

#define LDM4(r, addr)                                                        \
    asm volatile("ldmatrix.sync.aligned.m8n8.x4.shared.b16 {%0,%1,%2,%3}, [%4];" \
                 : "=r"((r)[0]), "=r"((r)[1]), "=r"((r)[2]), "=r"((r)[3])    \
                 : "r"(addr))

__device__ __forceinline__ uint32_t pack_h2(float a, float b) {
    __half2 t;
    t.x = __float2half_rn(a);
    t.y = __float2half_rn(b);
    return *(uint32_t*)&t;
}

// split 8 fp32 values into hi/lo fp16 packs
__device__ __forceinline__ void split8(const float4& v0, const float4& v1,
                                       uint4& hi, uint4& lo) {
    float f[8] = { v0.x, v0.y, v0.z, v0.w, v1.x, v1.y, v1.z, v1.w };
    float h[8];
#pragma unroll
    for (int i = 0; i < 8; i++) h[i] = __half2float(__float2half_rn(f[i]));
    hi.x = pack_h2(f[0], f[1]); hi.y = pack_h2(f[2], f[3]);
    hi.z = pack_h2(f[4], f[5]); hi.w = pack_h2(f[6], f[7]);
    lo.x = pack_h2(f[0] - h[0], f[1] - h[1]);
    lo.y = pack_h2(f[2] - h[2], f[3] - h[3]);
    lo.z = pack_h2(f[4] - h[4], f[5] - h[5]);
    lo.w = pack_h2(f[6] - h[6], f[7] - h[7]);
}

// ---- projection GEMM via fp16 split-2 mma, 128x128 tile, fused cvt ------
__global__ void __launch_bounds__(256, 2) proj_mma_kernel(
    const float* __restrict__ A, const float* __restrict__ W,
    float* __restrict__ outPlain, int mode)
{
    __shared__ __align__(16) __half sP[2 * 4 * PPLANE];   // 49152 B
    const int tid = threadIdx.x, lane = tid & 31, w = tid >> 5;
    const int r0 = blockIdx.y << 7, c0 = blockIdx.x << 7;
    const int wm = (w & 1) << 6, wn = (w >> 1) << 5;

    const float* Ap = A + (size_t)(r0 + (tid >> 1)) * CDIM + (tid & 1) * 8;
    const float* Wp = W + (size_t)(c0 + (tid >> 1)) * CDIM + (tid & 1) * 8;
    const int sts = (tid >> 1) * PKP + (tid & 1) * 8;

    uint32_t sb = (uint32_t)__cvta_generic_to_shared(sP);
    const int lrow = (lane & 7) + ((lane >> 3) & 1) * 8;
    const int lk = (lane >> 4) * 8;
    uint32_t adA[2][4], adB[2][2];
#pragma unroll
    for (int p = 0; p < 2; p++) {
#pragma unroll
        for (int mt = 0; mt < 4; mt++)
            adA[p][mt] = sb + 2 * (p * PPLANE + (wm + 16 * mt + lrow) * PKP + lk);
#pragma unroll
        for (int g = 0; g < 2; g++)
            adB[p][g] = sb + 2 * ((2 + p) * PPLANE + (wn + 16 * g + lrow) * PKP + lk);
    }
    const uint32_t bufB = 4 * PPLANE * 2;

    float acc[4][4][4] = {};

#pragma unroll 1
    for (int ks = 0; ks < 32; ks++) {
        const int buf = ks & 1;
        float4 a0 = *(const float4*)(Ap + ks * 16);
        float4 a1 = *(const float4*)(Ap + ks * 16 + 4);
        float4 w0 = *(const float4*)(Wp + ks * 16);
        float4 w1 = *(const float4*)(Wp + ks * 16 + 4);
        uint4 ahi, alo, whi, wlo;
        split8(a0, a1, ahi, alo);
        split8(w0, w1, whi, wlo);

        __half* sbuf = sP + buf * 4 * PPLANE;
        *(uint4*)&sbuf[0 * PPLANE + sts] = ahi;
        *(uint4*)&sbuf[1 * PPLANE + sts] = alo;
        *(uint4*)&sbuf[2 * PPLANE + sts] = whi;
        *(uint4*)&sbuf[3 * PPLANE + sts] = wlo;
        __syncthreads();

        uint32_t bfr[2][2][4];
#pragma unroll
        for (int p = 0; p < 2; p++)
#pragma unroll
            for (int g = 0; g < 2; g++) LDM4(bfr[p][g], adB[p][g] + buf * bufB);
#pragma unroll
        for (int mt = 0; mt < 4; mt++) {
            uint32_t afr[2][4];
#pragma unroll
            for (int p = 0; p < 2; p++) LDM4(afr[p], adA[p][mt] + buf * bufB);
#pragma unroll
            for (int nt = 0; nt < 4; nt++) {
                int n2 = nt >> 1, j = nt & 1;
                MMA_F16(acc[mt][nt], afr[0], bfr[0][n2][j], bfr[0][n2][j + 2]); // hh
                MMA_F16(acc[mt][nt], afr[0], bfr[1][n2][j], bfr[1][n2][j + 2]); // hl
                MMA_F16(acc[mt][nt], afr[1], bfr[0][n2][j], bfr[0][n2][j + 2]); // lh
            }
        }
    }

    // epilogue
#pragma unroll
    for (int mt = 0; mt < 4; mt++)
#pragma unroll
        for (int nt = 0; nt < 4; nt++)
#pragma unroll
            for (int hf = 0; hf < 2; hf++) {
                int row = r0 + wm + 16 * mt + (lane >> 2) + hf * 8;
                int col = c0 + wn + 8 * nt + 2 * (lane & 3);
                float v0 = acc[mt][nt][hf * 2];
                float v1 = acc[mt][nt][hf * 2 + 1];
                if (mode == 3) {
                    *(float2*)&outPlain[(size_t)row * CDIM + col] = make_float2(v0, v1);
                } else {
                    int b = row >> 11, n = row & 2047;
                    int hh = col >> 6, d = col & 63;
                    __half h0 = __float2half_rn(v0), h1 = __float2half_rn(v1);
                    __half l0 = __float2half_rn(v0 - __half2float(h0));
                    __half l1 = __float2half_rn(v1 - __half2float(h1));
                    if (mode == 2) {
                        size_t idx = ((size_t)((b << 3) + hh) * HDIM + d) * SEQ + n;
                        g_Vt2[idx] = h0; g_Vt2[idx + SEQ] = h1;
                        g_Vt2[NQe + idx] = l0; g_Vt2[NQe + idx + SEQ] = l1;
                    } else {
                        __half* OH = (mode == 0) ? g_Qh2 : g_Kh2;
                        size_t idx = ((size_t)((b << 3) + hh) * SEQ + n) * HDIM + d;
                        __half2 hv; hv.x = h0; hv.y = h1;
                        __half2 lv; lv.x = l0; lv.y = l1;
                        *(__half2*)&OH[idx] = hv;
                        *(__half2*)&OH[NQe + idx] = lv;
                    }
                }
            }
}

// ---- S = (Qh @ Kh^T)*SCALE: 128x128 tile, fp16 S, register argmax -------
__global__ void __launch_bounds__(256, 2) qk_mma_kernel()
{
    extern __shared__ __align__(16) unsigned char smraw[];
    __half* sOp = (__half*)smraw;
    __half* shS = (__half*)smraw;                       // fp16 staging (34816 B)
    float* rv = (float*)(smraw + 35840);                // [4][128]
    int*   ri = (int*)(smraw + 35840 + 2048);
    float* cv = (float*)(smraw + 35840 + 4096);         // [2][128]
    int*   ci = (int*)(smraw + 35840 + 5120);

    const int tid = threadIdx.x, lane = tid & 31, w = tid >> 5;
    const int bh = blockIdx.z;
    const int r0 = blockIdx.y << 7, c0 = blockIdx.x << 7;
    const int wm = (w & 1) << 6;
    const int wn = (w >> 1) << 5;
    const int q4 = lane >> 2, l4 = lane & 3;

    const __half* bases[4] = {
        g_Qh2 + (size_t)bh * SEQ * HDIM, g_Qh2 + (size_t)NQe + (size_t)bh * SEQ * HDIM,
        g_Kh2 + (size_t)bh * SEQ * HDIM, g_Kh2 + (size_t)NQe + (size_t)bh * SEQ * HDIM };
#pragma unroll
    for (int idx = tid; idx < 4096; idx += 256) {
        int arr = idx >> 10, rem = idx & 1023, row = rem >> 3, c = rem & 7;
        int gr = ((arr < 2) ? r0 : c0) + row;
        uint4 v = *(const uint4*)(bases[arr] + (size_t)gr * HDIM + c * 8);
        *(uint4*)(sOp + arr * OPSZ + row * KP2 + c * 8) = v;
    }
    __syncthreads();

    uint32_t sb = (uint32_t)__cvta_generic_to_shared(sOp);
    const int lrow = (lane & 7) + ((lane >> 3) & 1) * 8;
    const int lk = (lane >> 4) * 8;
    uint32_t adA[2][4], adB[2][2];
#pragma unroll
    for (int p = 0; p < 2; p++) {
#pragma unroll
        for (int mt = 0; mt < 4; mt++)
            adA[p][mt] = sb + 2 * (p * OPSZ + (wm + 16 * mt + lrow) * KP2 + lk);
#pragma unroll
        for (int g = 0; g < 2; g++)
            adB[p][g] = sb + 2 * ((2 + p) * OPSZ + (wn + 16 * g + lrow) * KP2 + lk);
    }

    float acc[4][4][4] = {};
#pragma unroll
    for (int ks = 0; ks < 4; ks++) {
        uint32_t bfr[2][2][4];
#pragma unroll
        for (int p = 0; p < 2; p++)
#pragma unroll
            for (int g = 0; g < 2; g++) LDM4(bfr[p][g], adB[p][g] + ks * 32);
#pragma unroll
        for (int mt = 0; mt < 4; mt++) {
            uint32_t afr[2][4];
#pragma unroll
            for (int p = 0; p < 2; p++) LDM4(afr[p], adA[p][mt] + ks * 32);
#pragma unroll
            for (int nt = 0; nt < 4; nt++) {
                int n2 = nt >> 1, j = nt & 1;
                MMA_F16(acc[mt][nt], afr[0], bfr[0][n2][j], bfr[0][n2][j + 2]);
                MMA_F16(acc[mt][nt], afr[0], bfr[1][n2][j], bfr[1][n2][j + 2]);
                MMA_F16(acc[mt][nt], afr[1], bfr[0][n2][j], bfr[0][n2][j + 2]);
            }
        }
    }

    // scale once
#pragma unroll
    for (int mt = 0; mt < 4; mt++)
#pragma unroll
        for (int nt = 0; nt < 4; nt++)
#pragma unroll
            for (int e = 0; e < 4; e++) acc[mt][nt][e] *= QKSCALE;

    __syncthreads();   // operands dead; smem becomes staging + argmax buffers

    // fp16 staging (conflict-free u32 stores, pitch 136)
#pragma unroll
    for (int mt = 0; mt < 4; mt++)
#pragma unroll
        for (int nt = 0; nt < 4; nt++)
#pragma unroll
            for (int hf = 0; hf < 2; hf++) {
                int row = wm + 16 * mt + q4 + 8 * hf;
                int col = wn + 8 * nt + 2 * l4;
                *(uint32_t*)&shS[row * SHP + col] =
                    pack_h2(acc[mt][nt][hf * 2], acc[mt][nt][hf * 2 + 1]);
            }

    // ---- row argmax in registers (cols ascending in-thread) ----
    {
        float rbv[8]; int rbi[8];
#pragma unroll
        for (int mt = 0; mt < 4; mt++)
#pragma unroll
            for (int hf = 0; hf < 2; hf++) {
                float best = -3e38f; int bi = 0;
#pragma unroll
                for (int nt = 0; nt < 4; nt++)
#pragma unroll
                    for (int j = 0; j < 2; j++) {
                        float v = acc[mt][nt][hf * 2 + j];
                        int idx = wn + 8 * nt + 2 * l4 + j;
                        if (v > best) { best = v; bi = idx; }
                    }
                rbv[mt * 2 + hf] = best; rbi[mt * 2 + hf] = bi;
            }
#pragma unroll
        for (int o = 1; o < 4; o <<= 1)
#pragma unroll
            for (int r = 0; r < 8; r++) {
                float ov = __shfl_xor_sync(0xffffffffu, rbv[r], o);
                int   oi = __shfl_xor_sync(0xffffffffu, rbi[r], o);
                if (ov > rbv[r] || (ov == rbv[r] && oi < rbi[r])) { rbv[r] = ov; rbi[r] = oi; }
            }
        if (l4 == 0) {
#pragma unroll
            for (int r = 0; r < 8; r++) {
                int row = wm + 16 * (r >> 1) + q4 + 8 * (r & 1);
                rv[(w >> 1) * 128 + row] = rbv[r];
                ri[(w >> 1) * 128 + row] = rbi[r];
            }
        }
    }

    // ---- col argmax in registers (rows ascending in-thread) ----
    {
        float cbv[8]; int cbi[8];
#pragma unroll
        for (int nt = 0; nt < 4; nt++)
#pragma unroll
            for (int j = 0; j < 2; j++) {
                float best = -3e38f; int bi = 0;
#pragma unroll
                for (int mt = 0; mt < 4; mt++)
#pragma unroll
                    for (int hf = 0; hf < 2; hf++) {
                        float v = acc[mt][nt][hf * 2 + j];
                        int row = wm + 16 * mt + q4 + 8 * hf;
                        if (v > best) { best = v; bi = row; }
                    }
                cbv[nt * 2 + j] = best; cbi[nt * 2 + j] = bi;
            }
#pragma unroll
        for (int o = 4; o < 32; o <<= 1)
#pragma unroll
            for (int cc = 0; cc < 8; cc++) {
                float ov = __shfl_xor_sync(0xffffffffu, cbv[cc], o);
                int   oi = __shfl_xor_sync(0xffffffffu, cbi[cc], o);
                if (ov > cbv[cc] || (ov == cbv[cc] && oi < cbi[cc])) { cbv[cc] = ov; cbi[cc] = oi; }
            }
        if (lane < 4) {
#pragma unroll
            for (int cc = 0; cc < 8; cc++) {
                int col = wn + 8 * (cc >> 1) + 2 * lane + (cc & 1);
                cv[(w & 1) * 128 + col] = cbv[cc];
                ci[(w & 1) * 128 + col] = cbi[cc];
            }
        }
    }
    __syncthreads();

    // coalesced fp16 S store
    __half* Sp = g_S + (size_t)bh * SEQ * SEQ;
    {
        int row = tid >> 1, cb = (tid & 1) * 64;
#pragma unroll
        for (int i = 0; i < 8; i++)
            *(uint4*)&Sp[(size_t)(r0 + row) * SEQ + c0 + cb + 8 * i] =
                *(const uint4*)&shS[row * SHP + cb + 8 * i];
    }

    // final partial writes
    if (tid < 128) {
        float best = rv[tid]; int bi = ri[tid];
#pragma unroll
        for (int g = 1; g < 4; g++) {
            float ov = rv[g * 128 + tid]; int oi = ri[g * 128 + tid];
            if (ov > best || (ov == best && oi < bi)) { best = ov; bi = oi; }
        }
        size_t p = (size_t)(bh * 16 + blockIdx.x) * SEQ + r0 + tid;
        g_rpv[p] = best; g_rpi[p] = c0 + bi;
    } else {
        int c = tid - 128;
        float best = cv[c]; int bi = ci[c];
        float ov = cv[128 + c]; int oi = ci[128 + c];
        if (ov > best || (ov == best && oi < bi)) { best = ov; bi = oi; }
        size_t p = (size_t)(bh * 16 + blockIdx.y) * SEQ + c0 + c;
        g_cpv[p] = best; g_cpi[p] = r0 + bi;
    }
}

// ---------------- reduce 16 partials -> q2k and k2q ----------------------
__global__ void argmax_reduce_kernel()
{
    int gid = blockIdx.x * blockDim.x + threadIdx.x;
    int which = gid >= NBH * SEQ;
    int i = gid & (NBH * SEQ - 1);
    int bh = i >> 11, n = i & 2047;
    const float* pv = which ? g_cpv : g_rpv;
    const int*   pi = which ? g_cpi : g_rpi;
    float v = -3e38f; int idx = 0;
#pragma unroll
    for (int t = 0; t < 16; t++) {
        size_t p = (size_t)(bh * 16 + t) * SEQ + n;
        float ov = pv[p];
        if (ov > v) { v = ov; idx = pi[p]; }
    }
    (which ? g_k2q : g_q2k)[i] = idx;
}

// ---------------- cycle consistency -> additive mask ---------------------
__global__ void asso_kernel(const int* __restrict__ smask,
                            const float* __restrict__ svalid)
{
    int i = blockIdx.x * blockDim.x + threadIdx.x;
    int bh = i >> 11, m = i & 2047;
    int b = bh >> 3;
    int kq = g_k2q[i];
    int remap = g_q2k[(bh << 11) + kq];
    float valid = (smask[(b << 11) + m] == smask[(b << 11) + remap])
                      ? svalid[(b << 11) + m] : 1.0f;
    g_madd[i] = valid * -10000.0f;
}

// ---- fused exp + online row-sum + P@V, fp16 S read ----------------------
__global__ void __launch_bounds__(128) av_mma_kernel()
{
    __shared__ __align__(16) __half sAB[8 * PLANE];
    __shared__ float sL[64];

    const int bh = blockIdx.y;
    const int n0 = blockIdx.x << 6;
    const int b = bh >> 3, h = bh & 7;
    const int tid = threadIdx.x, lane = tid & 31, w = tid >> 5;
    const int wm = (w & 1) << 5, wn = (w >> 1) << 5;

    const __half* Sp = g_S + (size_t)bh * SEQ * SEQ + (size_t)(n0 + (tid >> 1)) * SEQ + (tid & 1) * 8;
    const float* mp = g_madd + bh * SEQ + (tid & 1) * 8;
    const size_t voff = (size_t)bh * HDIM * SEQ + (size_t)(tid >> 1) * SEQ + (tid & 1) * 8;
    const __half* vp[2] = { g_Vt2 + voff, g_Vt2 + (size_t)NQe + voff };
    const int sts = (tid >> 1) * KP + (tid & 1) * 8;

    uint32_t sbase = (uint32_t)__cvta_generic_to_shared(sAB);
    const int lrow = (lane & 7) + ((lane >> 3) & 1) * 8;
    const int lk = (lane >> 4) * 8;
    uint32_t adA[2][2], adB[2][2];
#pragma unroll
    for (int p = 0; p < 2; p++)
#pragma unroll
        for (int t = 0; t < 2; t++) {
            adA[p][t] = sbase + 2 * (p * PLANE + (wm + 16 * t + lrow) * KP + lk);
            adB[p][t] = sbase + 2 * ((2 + p) * PLANE + (wn + 16 * t + lrow) * KP + lk);
        }
    const uint32_t bufB = 4 * PLANE * 2;

    float acc[2][4][4] = {};
    float runL = 0.0f;

#pragma unroll 1
    for (int ks = 0; ks < 128; ks++) {
        const int buf = ks & 1;
        uint4 sv = *(const uint4*)(Sp + ks * 16);
        float4 m0 = *(const float4*)(mp + ks * 16);
        float4 m1 = *(const float4*)(mp + ks * 16 + 4);
        uint4 v0 = *(const uint4*)(vp[0] + ks * 16);
        uint4 v1 = *(const uint4*)(vp[1] + ks * 16);

        float2 s01 = __half22float2(*(__half2*)&sv.x);
        float2 s23 = __half22float2(*(__half2*)&sv.y);
        float2 s45 = __half22float2(*(__half2*)&sv.z);
        float2 s67 = __half22float2(*(__half2*)&sv.w);

        float pv[8];
        pv[0] = fexp(s01.x + m0.x); pv[1] = fexp(s01.y + m0.y);
        pv[2] = fexp(s23.x + m0.z); pv[3] = fexp(s23.y + m0.w);
        pv[4] = fexp(s45.x + m1.x); pv[5] = fexp(s45.y + m1.y);
        pv[6] = fexp(s67.x + m1.z); pv[7] = fexp(s67.y + m1.w);
        runL += ((pv[0] + pv[1]) + (pv[2] + pv[3])) + ((pv[4] + pv[5]) + (pv[6] + pv[7]));

        uint4 ph, pl;
        float hs[8];
#pragma unroll
        for (int i = 0; i < 8; i++)
            hs[i] = __half2float(__float2half_rn(pv[i]));
        ph.x = pack_h2(pv[0], pv[1]); ph.y = pack_h2(pv[2], pv[3]);
        ph.z = pack_h2(pv[4], pv[5]); ph.w = pack_h2(pv[6], pv[7]);
        pl.x = pack_h2(pv[0] - hs[0], pv[1] - hs[1]);
        pl.y = pack_h2(pv[2] - hs[2], pv[3] - hs[3]);
        pl.z = pack_h2(pv[4] - hs[4], pv[5] - hs[5]);
        pl.w = pack_h2(pv[6] - hs[6], pv[7] - hs[7]);

        __half* sbuf = sAB + buf * 4 * PLANE;
        *(uint4*)&sbuf[0 * PLANE + sts] = ph;
        *(uint4*)&sbuf[1 * PLANE + sts] = pl;
        *(uint4*)&sbuf[2 * PLANE + sts] = v0;
        *(uint4*)&sbuf[3 * PLANE + sts] = v1;
        __syncthreads();

        uint32_t afr[2][2][4], bfr[2][2][4];
#pragma unroll
        for (int p = 0; p < 2; p++)
#pragma unroll
            for (int t = 0; t < 2; t++) {
                LDM4(afr[p][t], adA[p][t] + buf * bufB);
                LDM4(bfr[p][t], adB[p][t] + buf * bufB);
            }

        const int pa[3] = {0, 0, 1};
        const int pb[3] = {0, 1, 0};
#pragma unroll
        for (int c = 0; c < 3; c++)
#pragma unroll
            for (int mt = 0; mt < 2; mt++)
#pragma unroll
                for (int nt = 0; nt < 4; nt++) {
                    int n2 = nt >> 1, j = nt & 1;
                    MMA_F16(acc[mt][nt], afr[pa[c]][mt], bfr[pb[c]][n2][j], bfr[pb[c]][n2][j + 2]);
                }
    }

    runL += __shfl_xor_sync(0xffffffffu, runL, 1);
    if (!(tid & 1)) sL[tid >> 1] = runL;
    __syncthreads();

#pragma unroll
    for (int mt = 0; mt < 2; mt++) {
        int row0 = wm + 16 * mt + (lane >> 2);
        float inv0 = 1.0f / sL[row0];
        float inv1 = 1.0f / sL[row0 + 8];
#pragma unroll
        for (int nt = 0; nt < 4; nt++) {
            int col = wn + 8 * nt + 2 * (lane & 3);
            int n = n0 + row0;
            *(float2*)&g_X[(size_t)(b * SEQ + n) * CDIM + h * HDIM + col] =
                make_float2(acc[mt][nt][0] * inv0, acc[mt][nt][1] * inv0);
            *(float2*)&g_X[(size_t)(b * SEQ + n + 8) * CDIM + h * HDIM + col] =
                make_float2(acc[mt][nt][2] * inv1, acc[mt][nt][3] * inv1);
        }
    }
}

// ---------------- launcher ------------------------------------------------
extern "C" void kernel_launch(void* const* d_in, const int* in_sizes, int n_in,
                              void* d_out, int out_size)
{
    const float* q   = (const float*)d_in[0];
    const float* k   = (const float*)d_in[1];
    const float* v   = (const float*)d_in[2];
    const float* svm = (const float*)d_in[3];
    const int*   sm  = (const int*)d_in[4];
    const float* Wq  = (const float*)d_in[5];
    const float* Wk  = (const float*)d_in[6];
    const float* Wv  = (const float*)d_in[7];
    const float* Wp  = (const float*)d_in[8];
    float* out = (float*)d_out;

    float* X;
    cudaGetSymbolAddress((void**)&X, g_X);

    cudaFuncSetAttribute(qk_mma_kernel,
                         cudaFuncAttributeMaxDynamicSharedMemorySize, QK_SMEM);

    dim3 gp(CDIM / 128, (2 * SEQ) / 128);   // (4, 32)
    proj_mma_kernel<<<gp, 256>>>(q, Wq, nullptr, 0);
    proj_mma_kernel<<<gp, 256>>>(k, Wk, nullptr, 1);
    proj_mma_kernel<<<gp, 256>>>(v, Wv, nullptr, 2);

    qk_mma_kernel<<<dim3(SEQ / 128, SEQ / 128, NBH), 256, QK_SMEM>>>();

    argmax_reduce_kernel<<<(2 * NBH * SEQ) / 256, 256>>>();
    asso_kernel<<<(NBH * SEQ) / 256, 256>>>(sm, svm);

    av_mma_kernel<<<dim3(SEQ / 64, NBH), 128>>>();

    proj_mma_kernel<<<gp, 256>>>(X, Wp, out, 3);
}

// round 13
// speedup vs baseline: 2.0055x; 1.0192x over previous
#include <cuda_runtime.h>
#include <cuda_fp16.h>
#include <cstdint>

#define SEQ   2048
#define HDIM  64
#define NHEAD 8
#define CDIM  512
#define NBH   16            // B*H
#define QKSCALE 0.125f
#define KP    24            // smem tile pitch in halfs (48B, ldmatrix conflict-free)
#define KP2   72            // qk128 operand pitch in halfs (144B)
#define OPSZ  (128 * KP2)   // halfs per operand array (9216)
#define SHP   136           // qk fp16 staging pitch in halfs
#define QK_SMEM (4 * OPSZ * 2)   // 73728 B
#define PKP   24            // proj smem pitch (halfs)
#define PPLANE (128 * PKP)  // 3072 halfs per 128x16 plane
// av (128-row) smem layout, halfs per buffer:
#define AV_P  (128 * KP)    // 3072 per P plane
#define AV_V  (64 * KP)     // 1536 per V plane
#define AV_BUF (2 * AV_P + 2 * AV_V)   // 9216 halfs = 18432 B

constexpr int NQe = NBH * SEQ * HDIM;   // 2,097,152 elements per plane

// ---------------- scratch (device globals; no allocation) ----------------
__device__ __half g_Qh2[2 * NBH * SEQ * HDIM];    // hi/lo fp16 planes (Q pre-scaled)
__device__ __half g_Kh2[2 * NBH * SEQ * HDIM];
__device__ __half g_Vt2[2 * NBH * HDIM * SEQ];    // V transposed [bh][d][s]
__device__ float g_X[2 * SEQ * CDIM];             // attention output fp32
__device__ __half g_S[(size_t)NBH * SEQ * SEQ];   // scores, fp16 (134 MB)
__device__ int   g_q2k[NBH * SEQ];
__device__ int   g_k2q[NBH * SEQ];
__device__ float g_madd[NBH * SEQ];
__device__ float g_rpv[NBH * 16 * SEQ];
__device__ int   g_rpi[NBH * 16 * SEQ];
__device__ float g_cpv[NBH * 16 * SEQ];
__device__ int   g_cpi[NBH * 16 * SEQ];

// fast exp on the FMA pipe. |rel err| ~1e-7.
__device__ __forceinline__ float fexp(float x) {
    float y = x * 1.4426950408889634f;
    y = fminf(fmaxf(y, -126.0f), 126.0f);
    float t = y + 12582912.0f;
    int   e = __float_as_int(t) - 0x4B400000;
    float r = t - 12582912.0f;
    float f = y - r;
    float p = 1.535336188319500e-4f;
    p = fmaf(p, f, 1.339887440266574e-3f);
    p = fmaf(p, f, 9.618437357674640e-3f);
    p = fmaf(p, f, 5.550332471162809e-2f);
    p = fmaf(p, f, 2.402264791363012e-1f);
    p = fmaf(p, f, 6.931472028550421e-1f);
    p = fmaf(p, f, 1.0f);
    return p * __int_as_float((e + 127) << 23);
}

#define MMA_F16(d, a, b0, b1)                                               \
    asm volatile("mma.sync.aligned.m16n8k16.row.col.f32.f16.f16.f32 "        \
                 "{%0,%1,%2,%3}, {%4,%5,%6,%7}, {%8,%9}, {%0,%1,%2,%3};"     \
                 : "+f"((d)[0]), "+f"((d)[1]), "+f"((d)[2]), "+f"((d)[3])    \
                 : "r"((a)[0]), "r"((a)[1]), "r"((a)[2]), "r"((a)[3]),       \
                   "r"(b0), "r"(b1))

#define LDM4(r, addr)                                                        \
    asm volatile("ldmatrix.sync.aligned.m8n8.x4.shared.b16 {%0,%1,%2,%3}, [%4];" \
                 : "=r"((r)[0]), "=r"((r)[1]), "=r"((r)[2]), "=r"((r)[3])    \
                 : "r"(addr))

__device__ __forceinline__ uint32_t pack_h2(float a, float b) {
    __half2 t;
    t.x = __float2half_rn(a);
    t.y = __float2half_rn(b);
    return *(uint32_t*)&t;
}

// split 8 fp32 values into hi/lo fp16 packs
__device__ __forceinline__ void split8(const float4& v0, const float4& v1,
                                       uint4& hi, uint4& lo) {
    float f[8] = { v0.x, v0.y, v0.z, v0.w, v1.x, v1.y, v1.z, v1.w };
    float h[8];
#pragma unroll
    for (int i = 0; i < 8; i++) h[i] = __half2float(__float2half_rn(f[i]));
    hi.x = pack_h2(f[0], f[1]); hi.y = pack_h2(f[2], f[3]);
    hi.z = pack_h2(f[4], f[5]); hi.w = pack_h2(f[6], f[7]);
    lo.x = pack_h2(f[0] - h[0], f[1] - h[1]);
    lo.y = pack_h2(f[2] - h[2], f[3] - h[3]);
    lo.z = pack_h2(f[4] - h[4], f[5] - h[5]);
    lo.w = pack_h2(f[6] - h[6], f[7] - h[7]);
}

// ---- projection GEMM via fp16 split-2 mma, 128x128 tile, fused cvt ------
// mode 0 folds QKSCALE into Q (exact: power-of-two scale).
__global__ void __launch_bounds__(256, 2) proj_mma_kernel(
    const float* __restrict__ A, const float* __restrict__ W,
    float* __restrict__ outPlain, int mode)
{
    __shared__ __align__(16) __half sP[2 * 4 * PPLANE];   // 49152 B
    const int tid = threadIdx.x, lane = tid & 31, w = tid >> 5;
    const int r0 = blockIdx.y << 7, c0 = blockIdx.x << 7;
    const int wm = (w & 1) << 6, wn = (w >> 1) << 5;

    const float* Ap = A + (size_t)(r0 + (tid >> 1)) * CDIM + (tid & 1) * 8;
    const float* Wp = W + (size_t)(c0 + (tid >> 1)) * CDIM + (tid & 1) * 8;
    const int sts = (tid >> 1) * PKP + (tid & 1) * 8;

    uint32_t sb = (uint32_t)__cvta_generic_to_shared(sP);
    const int lrow = (lane & 7) + ((lane >> 3) & 1) * 8;
    const int lk = (lane >> 4) * 8;
    uint32_t adA[2][4], adB[2][2];
#pragma unroll
    for (int p = 0; p < 2; p++) {
#pragma unroll
        for (int mt = 0; mt < 4; mt++)
            adA[p][mt] = sb + 2 * (p * PPLANE + (wm + 16 * mt + lrow) * PKP + lk);
#pragma unroll
        for (int g = 0; g < 2; g++)
            adB[p][g] = sb + 2 * ((2 + p) * PPLANE + (wn + 16 * g + lrow) * PKP + lk);
    }
    const uint32_t bufB = 4 * PPLANE * 2;

    float acc[4][4][4] = {};

#pragma unroll 1
    for (int ks = 0; ks < 32; ks++) {
        const int buf = ks & 1;
        float4 a0 = *(const float4*)(Ap + ks * 16);
        float4 a1 = *(const float4*)(Ap + ks * 16 + 4);
        float4 w0 = *(const float4*)(Wp + ks * 16);
        float4 w1 = *(const float4*)(Wp + ks * 16 + 4);
        uint4 ahi, alo, whi, wlo;
        split8(a0, a1, ahi, alo);
        split8(w0, w1, whi, wlo);

        __half* sbuf = sP + buf * 4 * PPLANE;
        *(uint4*)&sbuf[0 * PPLANE + sts] = ahi;
        *(uint4*)&sbuf[1 * PPLANE + sts] = alo;
        *(uint4*)&sbuf[2 * PPLANE + sts] = whi;
        *(uint4*)&sbuf[3 * PPLANE + sts] = wlo;
        __syncthreads();

        uint32_t bfr[2][2][4];
#pragma unroll
        for (int p = 0; p < 2; p++)
#pragma unroll
            for (int g = 0; g < 2; g++) LDM4(bfr[p][g], adB[p][g] + buf * bufB);
#pragma unroll
        for (int mt = 0; mt < 4; mt++) {
            uint32_t afr[2][4];
#pragma unroll
            for (int p = 0; p < 2; p++) LDM4(afr[p], adA[p][mt] + buf * bufB);
#pragma unroll
            for (int nt = 0; nt < 4; nt++) {
                int n2 = nt >> 1, j = nt & 1;
                MMA_F16(acc[mt][nt], afr[0], bfr[0][n2][j], bfr[0][n2][j + 2]); // hh
                MMA_F16(acc[mt][nt], afr[0], bfr[1][n2][j], bfr[1][n2][j + 2]); // hl
                MMA_F16(acc[mt][nt], afr[1], bfr[0][n2][j], bfr[0][n2][j + 2]); // lh
            }
        }
    }

    // fold QKSCALE into Q projection (exact power-of-two scale)
    if (mode == 0) {
#pragma unroll
        for (int mt = 0; mt < 4; mt++)
#pragma unroll
            for (int nt = 0; nt < 4; nt++)
#pragma unroll
                for (int e = 0; e < 4; e++) acc[mt][nt][e] *= QKSCALE;
    }

    // epilogue
#pragma unroll
    for (int mt = 0; mt < 4; mt++)
#pragma unroll
        for (int nt = 0; nt < 4; nt++)
#pragma unroll
            for (int hf = 0; hf < 2; hf++) {
                int row = r0 + wm + 16 * mt + (lane >> 2) + hf * 8;
                int col = c0 + wn + 8 * nt + 2 * (lane & 3);
                float v0 = acc[mt][nt][hf * 2];
                float v1 = acc[mt][nt][hf * 2 + 1];
                if (mode == 3) {
                    *(float2*)&outPlain[(size_t)row * CDIM + col] = make_float2(v0, v1);
                } else {
                    int b = row >> 11, n = row & 2047;
                    int hh = col >> 6, d = col & 63;
                    __half h0 = __float2half_rn(v0), h1 = __float2half_rn(v1);
                    __half l0 = __float2half_rn(v0 - __half2float(h0));
                    __half l1 = __float2half_rn(v1 - __half2float(h1));
                    if (mode == 2) {
                        size_t idx = ((size_t)((b << 3) + hh) * HDIM + d) * SEQ + n;
                        g_Vt2[idx] = h0; g_Vt2[idx + SEQ] = h1;
                        g_Vt2[NQe + idx] = l0; g_Vt2[NQe + idx + SEQ] = l1;
                    } else {
                        __half* OH = (mode == 0) ? g_Qh2 : g_Kh2;
                        size_t idx = ((size_t)((b << 3) + hh) * SEQ + n) * HDIM + d;
                        __half2 hv; hv.x = h0; hv.y = h1;
                        __half2 lv; lv.x = l0; lv.y = l1;
                        *(__half2*)&OH[idx] = hv;
                        *(__half2*)&OH[NQe + idx] = lv;
                    }
                }
            }
}

// ---- S = Qh @ Kh^T (scale pre-folded): 128x128 tile, register argmax ----
__global__ void __launch_bounds__(256, 2) qk_mma_kernel()
{
    extern __shared__ __align__(16) unsigned char smraw[];
    __half* sOp = (__half*)smraw;
    __half* shS = (__half*)smraw;                       // fp16 staging (34816 B)
    float* rv = (float*)(smraw + 35840);                // [4][128]
    int*   ri = (int*)(smraw + 35840 + 2048);
    float* cv = (float*)(smraw + 35840 + 4096);         // [2][128]
    int*   ci = (int*)(smraw + 35840 + 5120);

    const int tid = threadIdx.x, lane = tid & 31, w = tid >> 5;
    const int bh = blockIdx.z;
    const int r0 = blockIdx.y << 7, c0 = blockIdx.x << 7;
    const int wm = (w & 1) << 6;
    const int wn = (w >> 1) << 5;
    const int q4 = lane >> 2, l4 = lane & 3;

    const __half* bases[4] = {
        g_Qh2 + (size_t)bh * SEQ * HDIM, g_Qh2 + (size_t)NQe + (size_t)bh * SEQ * HDIM,
        g_Kh2 + (size_t)bh * SEQ * HDIM, g_Kh2 + (size_t)NQe + (size_t)bh * SEQ * HDIM };
#pragma unroll
    for (int idx = tid; idx < 4096; idx += 256) {
        int arr = idx >> 10, rem = idx & 1023, row = rem >> 3, c = rem & 7;
        int gr = ((arr < 2) ? r0 : c0) + row;
        uint4 v = *(const uint4*)(bases[arr] + (size_t)gr * HDIM + c * 8);
        *(uint4*)(sOp + arr * OPSZ + row * KP2 + c * 8) = v;
    }
    __syncthreads();

    uint32_t sb = (uint32_t)__cvta_generic_to_shared(sOp);
    const int lrow = (lane & 7) + ((lane >> 3) & 1) * 8;
    const int lk = (lane >> 4) * 8;
    uint32_t adA[2][4], adB[2][2];
#pragma unroll
    for (int p = 0; p < 2; p++) {
#pragma unroll
        for (int mt = 0; mt < 4; mt++)
            adA[p][mt] = sb + 2 * (p * OPSZ + (wm + 16 * mt + lrow) * KP2 + lk);
#pragma unroll
        for (int g = 0; g < 2; g++)
            adB[p][g] = sb + 2 * ((2 + p) * OPSZ + (wn + 16 * g + lrow) * KP2 + lk);
    }

    float acc[4][4][4] = {};
#pragma unroll
    for (int ks = 0; ks < 4; ks++) {
        uint32_t bfr[2][2][4];
#pragma unroll
        for (int p = 0; p < 2; p++)
#pragma unroll
            for (int g = 0; g < 2; g++) LDM4(bfr[p][g], adB[p][g] + ks * 32);
#pragma unroll
        for (int mt = 0; mt < 4; mt++) {
            uint32_t afr[2][4];
#pragma unroll
            for (int p = 0; p < 2; p++) LDM4(afr[p], adA[p][mt] + ks * 32);
#pragma unroll
            for (int nt = 0; nt < 4; nt++) {
                int n2 = nt >> 1, j = nt & 1;
                MMA_F16(acc[mt][nt], afr[0], bfr[0][n2][j], bfr[0][n2][j + 2]);
                MMA_F16(acc[mt][nt], afr[0], bfr[1][n2][j], bfr[1][n2][j + 2]);
                MMA_F16(acc[mt][nt], afr[1], bfr[0][n2][j], bfr[0][n2][j + 2]);
            }
        }
    }

    __syncthreads();   // operands dead; smem becomes staging + argmax buffers

    // fp16 staging (conflict-free u32 stores, pitch 136)
#pragma unroll
    for (int mt = 0; mt < 4; mt++)
#pragma unroll
        for (int nt = 0; nt < 4; nt++)
#pragma unroll
            for (int hf = 0; hf < 2; hf++) {
                int row = wm + 16 * mt + q4 + 8 * hf;
                int col = wn + 8 * nt + 2 * l4;
                *(uint32_t*)&shS[row * SHP + col] =
                    pack_h2(acc[mt][nt][hf * 2], acc[mt][nt][hf * 2 + 1]);
            }

    // ---- row argmax in registers ----
    {
        float rbv[8]; int rbi[8];
#pragma unroll
        for (int mt = 0; mt < 4; mt++)
#pragma unroll
            for (int hf = 0; hf < 2; hf++) {
                float best = -3e38f; int bi = 0;
#pragma unroll
                for (int nt = 0; nt < 4; nt++)
#pragma unroll
                    for (int j = 0; j < 2; j++) {
                        float v = acc[mt][nt][hf * 2 + j];
                        int idx = wn + 8 * nt + 2 * l4 + j;
                        if (v > best) { best = v; bi = idx; }
                    }
                rbv[mt * 2 + hf] = best; rbi[mt * 2 + hf] = bi;
            }
#pragma unroll
        for (int o = 1; o < 4; o <<= 1)
#pragma unroll
            for (int r = 0; r < 8; r++) {
                float ov = __shfl_xor_sync(0xffffffffu, rbv[r], o);
                int   oi = __shfl_xor_sync(0xffffffffu, rbi[r], o);
                if (ov > rbv[r] || (ov == rbv[r] && oi < rbi[r])) { rbv[r] = ov; rbi[r] = oi; }
            }
        if (l4 == 0) {
#pragma unroll
            for (int r = 0; r < 8; r++) {
                int row = wm + 16 * (r >> 1) + q4 + 8 * (r & 1);
                rv[(w >> 1) * 128 + row] = rbv[r];
                ri[(w >> 1) * 128 + row] = rbi[r];
            }
        }
    }

    // ---- col argmax in registers ----
    {
        float cbv[8]; int cbi[8];
#pragma unroll
        for (int nt = 0; nt < 4; nt++)
#pragma unroll
            for (int j = 0; j < 2; j++) {
                float best = -3e38f; int bi = 0;
#pragma unroll
                for (int mt = 0; mt < 4; mt++)
#pragma unroll
                    for (int hf = 0; hf < 2; hf++) {
                        float v = acc[mt][nt][hf * 2 + j];
                        int row = wm + 16 * mt + q4 + 8 * hf;
                        if (v > best) { best = v; bi = row; }
                    }
                cbv[nt * 2 + j] = best; cbi[nt * 2 + j] = bi;
            }
#pragma unroll
        for (int o = 4; o < 32; o <<= 1)
#pragma unroll
            for (int cc = 0; cc < 8; cc++) {
                float ov = __shfl_xor_sync(0xffffffffu, cbv[cc], o);
                int   oi = __shfl_xor_sync(0xffffffffu, cbi[cc], o);
                if (ov > cbv[cc] || (ov == cbv[cc] && oi < cbi[cc])) { cbv[cc] = ov; cbi[cc] = oi; }
            }
        if (lane < 4) {
#pragma unroll
            for (int cc = 0; cc < 8; cc++) {
                int col = wn + 8 * (cc >> 1) + 2 * lane + (cc & 1);
                cv[(w & 1) * 128 + col] = cbv[cc];
                ci[(w & 1) * 128 + col] = cbi[cc];
            }
        }
    }
    __syncthreads();

    // coalesced fp16 S store
    __half* Sp = g_S + (size_t)bh * SEQ * SEQ;
    {
        int row = tid >> 1, cb = (tid & 1) * 64;
#pragma unroll
        for (int i = 0; i < 8; i++)
            *(uint4*)&Sp[(size_t)(r0 + row) * SEQ + c0 + cb + 8 * i] =
                *(const uint4*)&shS[row * SHP + cb + 8 * i];
    }

    // final partial writes
    if (tid < 128) {
        float best = rv[tid]; int bi = ri[tid];
#pragma unroll
        for (int g = 1; g < 4; g++) {
            float ov = rv[g * 128 + tid]; int oi = ri[g * 128 + tid];
            if (ov > best || (ov == best && oi < bi)) { best = ov; bi = oi; }
        }
        size_t p = (size_t)(bh * 16 + blockIdx.x) * SEQ + r0 + tid;
        g_rpv[p] = best; g_rpi[p] = c0 + bi;
    } else {
        int c = tid - 128;
        float best = cv[c]; int bi = ci[c];
        float ov = cv[128 + c]; int oi = ci[128 + c];
        if (ov > best || (ov == best && oi < bi)) { best = ov; bi = oi; }
        size_t p = (size_t)(bh * 16 + blockIdx.y) * SEQ + c0 + c;
        g_cpv[p] = best; g_cpi[p] = r0 + bi;
    }
}

// ---------------- reduce 16 partials -> q2k and k2q ----------------------
__global__ void argmax_reduce_kernel()
{
    int gid = blockIdx.x * blockDim.x + threadIdx.x;
    int which = gid >= NBH * SEQ;
    int i = gid & (NBH * SEQ - 1);
    int bh = i >> 11, n = i & 2047;
    const float* pv = which ? g_cpv : g_rpv;
    const int*   pi = which ? g_cpi : g_rpi;
    float v = -3e38f; int idx = 0;
#pragma unroll
    for (int t = 0; t < 16; t++) {
        size_t p = (size_t)(bh * 16 + t) * SEQ + n;
        float ov = pv[p];
        if (ov > v) { v = ov; idx = pi[p]; }
    }
    (which ? g_k2q : g_q2k)[i] = idx;
}

// ---------------- cycle consistency -> additive mask ---------------------
__global__ void asso_kernel(const int* __restrict__ smask,
                            const float* __restrict__ svalid)
{
    int i = blockIdx.x * blockDim.x + threadIdx.x;
    int bh = i >> 11, m = i & 2047;
    int b = bh >> 3;
    int kq = g_k2q[i];
    int remap = g_q2k[(bh << 11) + kq];
    float valid = (smask[(b << 11) + m] == smask[(b << 11) + remap])
                      ? svalid[(b << 11) + m] : 1.0f;
    g_madd[i] = valid * -10000.0f;
}

// ---- fused exp + online row-sum + P@V, 128-row tile, 256 threads --------
__global__ void __launch_bounds__(256, 2) av_mma_kernel()
{
    __shared__ __align__(16) __half sAB[2 * AV_BUF];   // 36864 B
    __shared__ float sL[128];

    const int bh = blockIdx.y;
    const int n0 = blockIdx.x << 7;
    const int b = bh >> 3, h = bh & 7;
    const int tid = threadIdx.x, lane = tid & 31, w = tid >> 5;
    const int wm = (w & 3) << 5;       // 4 warps over 128 rows
    const int wn = (w >> 2) << 5;      // 2 warps over 64 cols

    const __half* Sp = g_S + (size_t)bh * SEQ * SEQ
                     + (size_t)(n0 + (tid >> 1)) * SEQ + (tid & 1) * 8;
    const float* mp = g_madd + bh * SEQ + (tid & 1) * 8;
    // V load role: vrow = tid>>2 (0..63), plane = (tid>>1)&1, colhalf = tid&1
    const int vrow = tid >> 2, vpl = (tid >> 1) & 1, vch = tid & 1;
    const __half* Vp = g_Vt2 + (size_t)vpl * NQe + (size_t)bh * HDIM * SEQ
                     + (size_t)vrow * SEQ + vch * 8;
    const int stsP = (tid >> 1) * KP + (tid & 1) * 8;       // P store
    const int stsV = 2 * AV_P + vpl * AV_V + vrow * KP + vch * 8;  // V store

    uint32_t sbase = (uint32_t)__cvta_generic_to_shared(sAB);
    const int lrow = (lane & 7) + ((lane >> 3) & 1) * 8;
    const int lk = (lane >> 4) * 8;
    uint32_t adA[2][2], adB[2][2];
#pragma unroll
    for (int p = 0; p < 2; p++)
#pragma unroll
        for (int t = 0; t < 2; t++) {
            adA[p][t] = sbase + 2 * (p * AV_P + (wm + 16 * t + lrow) * KP + lk);
            adB[p][t] = sbase + 2 * (2 * AV_P + p * AV_V + (wn + 16 * t + lrow) * KP + lk);
        }
    const uint32_t bufB = AV_BUF * 2;

    float acc[2][4][4] = {};
    float runL = 0.0f;

#pragma unroll 1
    for (int ks = 0; ks < 128; ks++) {
        const int buf = ks & 1;
        uint4 sv = *(const uint4*)(Sp + ks * 16);
        float4 m0 = *(const float4*)(mp + ks * 16);
        float4 m1 = *(const float4*)(mp + ks * 16 + 4);
        uint4 vv = *(const uint4*)(Vp + ks * 16);

        float2 s01 = __half22float2(*(__half2*)&sv.x);
        float2 s23 = __half22float2(*(__half2*)&sv.y);
        float2 s45 = __half22float2(*(__half2*)&sv.z);
        float2 s67 = __half22float2(*(__half2*)&sv.w);

        float pv[8];
        pv[0] = fexp(s01.x + m0.x); pv[1] = fexp(s01.y + m0.y);
        pv[2] = fexp(s23.x + m0.z); pv[3] = fexp(s23.y + m0.w);
        pv[4] = fexp(s45.x + m1.x); pv[5] = fexp(s45.y + m1.y);
        pv[6] = fexp(s67.x + m1.z); pv[7] = fexp(s67.y + m1.w);
        runL += ((pv[0] + pv[1]) + (pv[2] + pv[3])) + ((pv[4] + pv[5]) + (pv[6] + pv[7]));

        uint4 ph, pl;
        float hs[8];
#pragma unroll
        for (int i = 0; i < 8; i++)
            hs[i] = __half2float(__float2half_rn(pv[i]));
        ph.x = pack_h2(pv[0], pv[1]); ph.y = pack_h2(pv[2], pv[3]);
        ph.z = pack_h2(pv[4], pv[5]); ph.w = pack_h2(pv[6], pv[7]);
        pl.x = pack_h2(pv[0] - hs[0], pv[1] - hs[1]);
        pl.y = pack_h2(pv[2] - hs[2], pv[3] - hs[3]);
        pl.z = pack_h2(pv[4] - hs[4], pv[5] - hs[5]);
        pl.w = pack_h2(pv[6] - hs[6], pv[7] - hs[7]);

        __half* sbuf = sAB + buf * AV_BUF;
        *(uint4*)&sbuf[0 * AV_P + stsP] = ph;
        *(uint4*)&sbuf[1 * AV_P + stsP] = pl;
        *(uint4*)&sbuf[stsV] = vv;
        __syncthreads();

        uint32_t afr[2][2][4], bfr[2][2][4];
#pragma unroll
        for (int p = 0; p < 2; p++)
#pragma unroll
            for (int t = 0; t < 2; t++) {
                LDM4(afr[p][t], adA[p][t] + buf * bufB);
                LDM4(bfr[p][t], adB[p][t] + buf * bufB);
            }

        const int pa[3] = {0, 0, 1};
        const int pb[3] = {0, 1, 0};
#pragma unroll
        for (int c = 0; c < 3; c++)
#pragma unroll
            for (int mt = 0; mt < 2; mt++)
#pragma unroll
                for (int nt = 0; nt < 4; nt++) {
                    int n2 = nt >> 1, j = nt & 1;
                    MMA_F16(acc[mt][nt], afr[pa[c]][mt], bfr[pb[c]][n2][j], bfr[pb[c]][n2][j + 2]);
                }
    }

    runL += __shfl_xor_sync(0xffffffffu, runL, 1);
    if (!(tid & 1)) sL[tid >> 1] = runL;
    __syncthreads();

#pragma unroll
    for (int mt = 0; mt < 2; mt++) {
        int row0 = wm + 16 * mt + (lane >> 2);
        float inv0 = 1.0f / sL[row0];
        float inv1 = 1.0f / sL[row0 + 8];
#pragma unroll
        for (int nt = 0; nt < 4; nt++) {
            int col = wn + 8 * nt + 2 * (lane & 3);
            int n = n0 + row0;
            *(float2*)&g_X[(size_t)(b * SEQ + n) * CDIM + h * HDIM + col] =
                make_float2(acc[mt][nt][0] * inv0, acc[mt][nt][1] * inv0);
            *(float2*)&g_X[(size_t)(b * SEQ + n + 8) * CDIM + h * HDIM + col] =
                make_float2(acc[mt][nt][2] * inv1, acc[mt][nt][3] * inv1);
        }
    }
}

// ---------------- launcher ------------------------------------------------
extern "C" void kernel_launch(void* const* d_in, const int* in_sizes, int n_in,
                              void* d_out, int out_size)
{
    const float* q   = (const float*)d_in[0];
    const float* k   = (const float*)d_in[1];
    const float* v   = (const float*)d_in[2];
    const float* svm = (const float*)d_in[3];
    const int*   sm  = (const int*)d_in[4];
    const float* Wq  = (const float*)d_in[5];
    const float* Wk  = (const float*)d_in[6];
    const float* Wv  = (const float*)d_in[7];
    const float* Wp  = (const float*)d_in[8];
    float* out = (float*)d_out;

    float* X;
    cudaGetSymbolAddress((void**)&X, g_X);

    cudaFuncSetAttribute(qk_mma_kernel,
                         cudaFuncAttributeMaxDynamicSharedMemorySize, QK_SMEM);

    dim3 gp(CDIM / 128, (2 * SEQ) / 128);   // (4, 32)
    proj_mma_kernel<<<gp, 256>>>(q, Wq, nullptr, 0);
    proj_mma_kernel<<<gp, 256>>>(k, Wk, nullptr, 1);
    proj_mma_kernel<<<gp, 256>>>(v, Wv, nullptr, 2);

    qk_mma_kernel<<<dim3(SEQ / 128, SEQ / 128, NBH), 256, QK_SMEM>>>();

    argmax_reduce_kernel<<<(2 * NBH * SEQ) / 256, 256>>>();
    asso_kernel<<<(NBH * SEQ) / 256, 256>>>(sm, svm);

    av_mma_kernel<<<dim3(SEQ / 128, NBH), 256>>>();

    proj_mma_kernel<<<gp, 256>>>(X, Wp, out, 3);
}

// round 14
// speedup vs baseline: 2.2115x; 1.1027x over previous
#include <cuda_runtime.h>
#include <cuda_fp16.h>
#include <cstdint>

#define SEQ   2048
#define HDIM  64
#define NHEAD 8
#define CDIM  512
#define NBH   16            // B*H
#define QKSCALE 0.125f
#define KP    24            // smem tile pitch in halfs (48B, ldmatrix conflict-free)
#define KP2   72            // qk128 operand pitch in halfs (144B)
#define OPSZ  (128 * KP2)   // halfs per operand array (9216)
#define SHP   136           // qk fp16 staging pitch in halfs
#define QK_SMEM (4 * OPSZ * 2)   // 73728 B
#define PKP   24            // proj smem pitch (halfs)
#define PPLANE (128 * PKP)  // 3072 halfs per 128x16 plane
// av smem: single P plane (128x16) + single V plane (64x16) per buffer
#define AV_P  (128 * KP)    // 3072 halfs
#define AV_V  (64 * KP)     // 1536 halfs
#define AV_BUF (AV_P + AV_V)   // 4608 halfs = 9216 B

constexpr int NQe = NBH * SEQ * HDIM;   // 2,097,152 elements per plane

// ---------------- scratch (device globals; no allocation) ----------------
__device__ __half g_Qh2[2 * NBH * SEQ * HDIM];    // hi/lo fp16 planes (Q pre-scaled)
__device__ __half g_Kh2[2 * NBH * SEQ * HDIM];
__device__ __half g_Vt[NBH * HDIM * SEQ];         // V transposed, single fp16 plane
__device__ float g_X[2 * SEQ * CDIM];             // attention output fp32
__device__ __half g_S[(size_t)NBH * SEQ * SEQ];   // scores, fp16 (134 MB)
__device__ int   g_q2k[NBH * SEQ];
__device__ int   g_k2q[NBH * SEQ];
__device__ float g_madd[NBH * SEQ];
__device__ float g_rpv[NBH * 16 * SEQ];
__device__ int   g_rpi[NBH * 16 * SEQ];
__device__ float g_cpv[NBH * 16 * SEQ];
__device__ int   g_cpi[NBH * 16 * SEQ];

// fast exp on the FMA pipe. |rel err| ~1e-7.
__device__ __forceinline__ float fexp(float x) {
    float y = x * 1.4426950408889634f;
    y = fminf(fmaxf(y, -126.0f), 126.0f);
    float t = y + 12582912.0f;
    int   e = __float_as_int(t) - 0x4B400000;
    float r = t - 12582912.0f;
    float f = y - r;
    float p = 1.535336188319500e-4f;
    p = fmaf(p, f, 1.339887440266574e-3f);
    p = fmaf(p, f, 9.618437357674640e-3f);
    p = fmaf(p, f, 5.550332471162809e-2f);
    p = fmaf(p, f, 2.402264791363012e-1f);
    p = fmaf(p, f, 6.931472028550421e-1f);
    p = fmaf(p, f, 1.0f);
    return p * __int_as_float((e + 127) << 23);
}

#define MMA_F16(d, a, b0, b1)                                               \
    asm volatile("mma.sync.aligned.m16n8k16.row.col.f32.f16.f16.f32 "        \
                 "{%0,%1,%2,%3}, {%4,%5,%6,%7}, {%8,%9}, {%0,%1,%2,%3};"     \
                 : "+f"((d)[0]), "+f"((d)[1]), "+f"((d)[2]), "+f"((d)[3])    \
                 : "r"((a)[0]), "r"((a)[1]), "r"((a)[2]), "r"((a)[3]),       \
                   "r"(b0), "r"(b1))

#define LDM4(r, addr)                                                        \
    asm volatile("ldmatrix.sync.aligned.m8n8.x4.shared.b16 {%0,%1,%2,%3}, [%4];" \
                 : "=r"((r)[0]), "=r"((r)[1]), "=r"((r)[2]), "=r"((r)[3])    \
                 : "r"(addr))

__device__ __forceinline__ uint32_t pack_h2(float a, float b) {
    __half2 t;
    t.x = __float2half_rn(a);
    t.y = __float2half_rn(b);
    return *(uint32_t*)&t;
}

// split 8 fp32 values into hi/lo fp16 packs
__device__ __forceinline__ void split8(const float4& v0, const float4& v1,
                                       uint4& hi, uint4& lo) {
    float f[8] = { v0.x, v0.y, v0.z, v0.w, v1.x, v1.y, v1.z, v1.w };
    float h[8];
#pragma unroll
    for (int i = 0; i < 8; i++) h[i] = __half2float(__float2half_rn(f[i]));
    hi.x = pack_h2(f[0], f[1]); hi.y = pack_h2(f[2], f[3]);
    hi.z = pack_h2(f[4], f[5]); hi.w = pack_h2(f[6], f[7]);
    lo.x = pack_h2(f[0] - h[0], f[1] - h[1]);
    lo.y = pack_h2(f[2] - h[2], f[3] - h[3]);
    lo.z = pack_h2(f[4] - h[4], f[5] - h[5]);
    lo.w = pack_h2(f[6] - h[6], f[7] - h[7]);
}

// ---- projection GEMM via fp16 split-2 mma, 128x128 tile, fused cvt ------
// mode 0 folds QKSCALE into Q (exact: power-of-two scale).
// mode 2 writes single-plane fp16 V (transposed).
__global__ void __launch_bounds__(256, 2) proj_mma_kernel(
    const float* __restrict__ A, const float* __restrict__ W,
    float* __restrict__ outPlain, int mode)
{
    __shared__ __align__(16) __half sP[2 * 4 * PPLANE];   // 49152 B
    const int tid = threadIdx.x, lane = tid & 31, w = tid >> 5;
    const int r0 = blockIdx.y << 7, c0 = blockIdx.x << 7;
    const int wm = (w & 1) << 6, wn = (w >> 1) << 5;

    const float* Ap = A + (size_t)(r0 + (tid >> 1)) * CDIM + (tid & 1) * 8;
    const float* Wp = W + (size_t)(c0 + (tid >> 1)) * CDIM + (tid & 1) * 8;
    const int sts = (tid >> 1) * PKP + (tid & 1) * 8;

    uint32_t sb = (uint32_t)__cvta_generic_to_shared(sP);
    const int lrow = (lane & 7) + ((lane >> 3) & 1) * 8;
    const int lk = (lane >> 4) * 8;
    uint32_t adA[2][4], adB[2][2];
#pragma unroll
    for (int p = 0; p < 2; p++) {
#pragma unroll
        for (int mt = 0; mt < 4; mt++)
            adA[p][mt] = sb + 2 * (p * PPLANE + (wm + 16 * mt + lrow) * PKP + lk);
#pragma unroll
        for (int g = 0; g < 2; g++)
            adB[p][g] = sb + 2 * ((2 + p) * PPLANE + (wn + 16 * g + lrow) * PKP + lk);
    }
    const uint32_t bufB = 4 * PPLANE * 2;

    float acc[4][4][4] = {};

#pragma unroll 1
    for (int ks = 0; ks < 32; ks++) {
        const int buf = ks & 1;
        float4 a0 = *(const float4*)(Ap + ks * 16);
        float4 a1 = *(const float4*)(Ap + ks * 16 + 4);
        float4 w0 = *(const float4*)(Wp + ks * 16);
        float4 w1 = *(const float4*)(Wp + ks * 16 + 4);
        uint4 ahi, alo, whi, wlo;
        split8(a0, a1, ahi, alo);
        split8(w0, w1, whi, wlo);

        __half* sbuf = sP + buf * 4 * PPLANE;
        *(uint4*)&sbuf[0 * PPLANE + sts] = ahi;
        *(uint4*)&sbuf[1 * PPLANE + sts] = alo;
        *(uint4*)&sbuf[2 * PPLANE + sts] = whi;
        *(uint4*)&sbuf[3 * PPLANE + sts] = wlo;
        __syncthreads();

        uint32_t bfr[2][2][4];
#pragma unroll
        for (int p = 0; p < 2; p++)
#pragma unroll
            for (int g = 0; g < 2; g++) LDM4(bfr[p][g], adB[p][g] + buf * bufB);
#pragma unroll
        for (int mt = 0; mt < 4; mt++) {
            uint32_t afr[2][4];
#pragma unroll
            for (int p = 0; p < 2; p++) LDM4(afr[p], adA[p][mt] + buf * bufB);
#pragma unroll
            for (int nt = 0; nt < 4; nt++) {
                int n2 = nt >> 1, j = nt & 1;
                MMA_F16(acc[mt][nt], afr[0], bfr[0][n2][j], bfr[0][n2][j + 2]); // hh
                MMA_F16(acc[mt][nt], afr[0], bfr[1][n2][j], bfr[1][n2][j + 2]); // hl
                MMA_F16(acc[mt][nt], afr[1], bfr[0][n2][j], bfr[0][n2][j + 2]); // lh
            }
        }
    }

    if (mode == 0) {
#pragma unroll
        for (int mt = 0; mt < 4; mt++)
#pragma unroll
            for (int nt = 0; nt < 4; nt++)
#pragma unroll
                for (int e = 0; e < 4; e++) acc[mt][nt][e] *= QKSCALE;
    }

    // epilogue
#pragma unroll
    for (int mt = 0; mt < 4; mt++)
#pragma unroll
        for (int nt = 0; nt < 4; nt++)
#pragma unroll
            for (int hf = 0; hf < 2; hf++) {
                int row = r0 + wm + 16 * mt + (lane >> 2) + hf * 8;
                int col = c0 + wn + 8 * nt + 2 * (lane & 3);
                float v0 = acc[mt][nt][hf * 2];
                float v1 = acc[mt][nt][hf * 2 + 1];
                if (mode == 3) {
                    *(float2*)&outPlain[(size_t)row * CDIM + col] = make_float2(v0, v1);
                } else if (mode == 2) {
                    int b = row >> 11, n = row & 2047;
                    int hh = col >> 6, d = col & 63;
                    size_t idx = ((size_t)((b << 3) + hh) * HDIM + d) * SEQ + n;
                    g_Vt[idx] = __float2half_rn(v0);
                    g_Vt[idx + SEQ] = __float2half_rn(v1);
                } else {
                    int b = row >> 11, n = row & 2047;
                    int hh = col >> 6, d = col & 63;
                    __half h0 = __float2half_rn(v0), h1 = __float2half_rn(v1);
                    __half l0 = __float2half_rn(v0 - __half2float(h0));
                    __half l1 = __float2half_rn(v1 - __half2float(h1));
                    __half* OH = (mode == 0) ? g_Qh2 : g_Kh2;
                    size_t idx = ((size_t)((b << 3) + hh) * SEQ + n) * HDIM + d;
                    __half2 hv; hv.x = h0; hv.y = h1;
                    __half2 lv; lv.x = l0; lv.y = l1;
                    *(__half2*)&OH[idx] = hv;
                    *(__half2*)&OH[NQe + idx] = lv;
                }
            }
}

// ---- S = Qh @ Kh^T (scale pre-folded): 128x128 tile, register argmax ----
__global__ void __launch_bounds__(256, 2) qk_mma_kernel()
{
    extern __shared__ __align__(16) unsigned char smraw[];
    __half* sOp = (__half*)smraw;
    __half* shS = (__half*)smraw;                       // fp16 staging (34816 B)
    float* rv = (float*)(smraw + 35840);                // [4][128]
    int*   ri = (int*)(smraw + 35840 + 2048);
    float* cv = (float*)(smraw + 35840 + 4096);         // [2][128]
    int*   ci = (int*)(smraw + 35840 + 5120);

    const int tid = threadIdx.x, lane = tid & 31, w = tid >> 5;
    const int bh = blockIdx.z;
    const int r0 = blockIdx.y << 7, c0 = blockIdx.x << 7;
    const int wm = (w & 1) << 6;
    const int wn = (w >> 1) << 5;
    const int q4 = lane >> 2, l4 = lane & 3;

    const __half* bases[4] = {
        g_Qh2 + (size_t)bh * SEQ * HDIM, g_Qh2 + (size_t)NQe + (size_t)bh * SEQ * HDIM,
        g_Kh2 + (size_t)bh * SEQ * HDIM, g_Kh2 + (size_t)NQe + (size_t)bh * SEQ * HDIM };
#pragma unroll
    for (int idx = tid; idx < 4096; idx += 256) {
        int arr = idx >> 10, rem = idx & 1023, row = rem >> 3, c = rem & 7;
        int gr = ((arr < 2) ? r0 : c0) + row;
        uint4 v = *(const uint4*)(bases[arr] + (size_t)gr * HDIM + c * 8);
        *(uint4*)(sOp + arr * OPSZ + row * KP2 + c * 8) = v;
    }
    __syncthreads();

    uint32_t sb = (uint32_t)__cvta_generic_to_shared(sOp);
    const int lrow = (lane & 7) + ((lane >> 3) & 1) * 8;
    const int lk = (lane >> 4) * 8;
    uint32_t adA[2][4], adB[2][2];
#pragma unroll
    for (int p = 0; p < 2; p++) {
#pragma unroll
        for (int mt = 0; mt < 4; mt++)
            adA[p][mt] = sb + 2 * (p * OPSZ + (wm + 16 * mt + lrow) * KP2 + lk);
#pragma unroll
        for (int g = 0; g < 2; g++)
            adB[p][g] = sb + 2 * ((2 + p) * OPSZ + (wn + 16 * g + lrow) * KP2 + lk);
    }

    float acc[4][4][4] = {};
#pragma unroll
    for (int ks = 0; ks < 4; ks++) {
        uint32_t bfr[2][2][4];
#pragma unroll
        for (int p = 0; p < 2; p++)
#pragma unroll
            for (int g = 0; g < 2; g++) LDM4(bfr[p][g], adB[p][g] + ks * 32);
#pragma unroll
        for (int mt = 0; mt < 4; mt++) {
            uint32_t afr[2][4];
#pragma unroll
            for (int p = 0; p < 2; p++) LDM4(afr[p], adA[p][mt] + ks * 32);
#pragma unroll
            for (int nt = 0; nt < 4; nt++) {
                int n2 = nt >> 1, j = nt & 1;
                MMA_F16(acc[mt][nt], afr[0], bfr[0][n2][j], bfr[0][n2][j + 2]);
                MMA_F16(acc[mt][nt], afr[0], bfr[1][n2][j], bfr[1][n2][j + 2]);
                MMA_F16(acc[mt][nt], afr[1], bfr[0][n2][j], bfr[0][n2][j + 2]);
            }
        }
    }

    __syncthreads();   // operands dead; smem becomes staging + argmax buffers

    // fp16 staging (conflict-free u32 stores, pitch 136)
#pragma unroll
    for (int mt = 0; mt < 4; mt++)
#pragma unroll
        for (int nt = 0; nt < 4; nt++)
#pragma unroll
            for (int hf = 0; hf < 2; hf++) {
                int row = wm + 16 * mt + q4 + 8 * hf;
                int col = wn + 8 * nt + 2 * l4;
                *(uint32_t*)&shS[row * SHP + col] =
                    pack_h2(acc[mt][nt][hf * 2], acc[mt][nt][hf * 2 + 1]);
            }

    // ---- row argmax in registers ----
    {
        float rbv[8]; int rbi[8];
#pragma unroll
        for (int mt = 0; mt < 4; mt++)
#pragma unroll
            for (int hf = 0; hf < 2; hf++) {
                float best = -3e38f; int bi = 0;
#pragma unroll
                for (int nt = 0; nt < 4; nt++)
#pragma unroll
                    for (int j = 0; j < 2; j++) {
                        float v = acc[mt][nt][hf * 2 + j];
                        int idx = wn + 8 * nt + 2 * l4 + j;
                        if (v > best) { best = v; bi = idx; }
                    }
                rbv[mt * 2 + hf] = best; rbi[mt * 2 + hf] = bi;
            }
#pragma unroll
        for (int o = 1; o < 4; o <<= 1)
#pragma unroll
            for (int r = 0; r < 8; r++) {
                float ov = __shfl_xor_sync(0xffffffffu, rbv[r], o);
                int   oi = __shfl_xor_sync(0xffffffffu, rbi[r], o);
                if (ov > rbv[r] || (ov == rbv[r] && oi < rbi[r])) { rbv[r] = ov; rbi[r] = oi; }
            }
        if (l4 == 0) {
#pragma unroll
            for (int r = 0; r < 8; r++) {
                int row = wm + 16 * (r >> 1) + q4 + 8 * (r & 1);
                rv[(w >> 1) * 128 + row] = rbv[r];
                ri[(w >> 1) * 128 + row] = rbi[r];
            }
        }
    }

    // ---- col argmax in registers ----
    {
        float cbv[8]; int cbi[8];
#pragma unroll
        for (int nt = 0; nt < 4; nt++)
#pragma unroll
            for (int j = 0; j < 2; j++) {
                float best = -3e38f; int bi = 0;
#pragma unroll
                for (int mt = 0; mt < 4; mt++)
#pragma unroll
                    for (int hf = 0; hf < 2; hf++) {
                        float v = acc[mt][nt][hf * 2 + j];
                        int row = wm + 16 * mt + q4 + 8 * hf;
                        if (v > best) { best = v; bi = row; }
                    }
                cbv[nt * 2 + j] = best; cbi[nt * 2 + j] = bi;
            }
#pragma unroll
        for (int o = 4; o < 32; o <<= 1)
#pragma unroll
            for (int cc = 0; cc < 8; cc++) {
                float ov = __shfl_xor_sync(0xffffffffu, cbv[cc], o);
                int   oi = __shfl_xor_sync(0xffffffffu, cbi[cc], o);
                if (ov > cbv[cc] || (ov == cbv[cc] && oi < cbi[cc])) { cbv[cc] = ov; cbi[cc] = oi; }
            }
        if (lane < 4) {
#pragma unroll
            for (int cc = 0; cc < 8; cc++) {
                int col = wn + 8 * (cc >> 1) + 2 * lane + (cc & 1);
                cv[(w & 1) * 128 + col] = cbv[cc];
                ci[(w & 1) * 128 + col] = cbi[cc];
            }
        }
    }
    __syncthreads();

    // coalesced fp16 S store
    __half* Sp = g_S + (size_t)bh * SEQ * SEQ;
    {
        int row = tid >> 1, cb = (tid & 1) * 64;
#pragma unroll
        for (int i = 0; i < 8; i++)
            *(uint4*)&Sp[(size_t)(r0 + row) * SEQ + c0 + cb + 8 * i] =
                *(const uint4*)&shS[row * SHP + cb + 8 * i];
    }

    // final partial writes
    if (tid < 128) {
        float best = rv[tid]; int bi = ri[tid];
#pragma unroll
        for (int g = 1; g < 4; g++) {
            float ov = rv[g * 128 + tid]; int oi = ri[g * 128 + tid];
            if (ov > best || (ov == best && oi < bi)) { best = ov; bi = oi; }
        }
        size_t p = (size_t)(bh * 16 + blockIdx.x) * SEQ + r0 + tid;
        g_rpv[p] = best; g_rpi[p] = c0 + bi;
    } else {
        int c = tid - 128;
        float best = cv[c]; int bi = ci[c];
        float ov = cv[128 + c]; int oi = ci[128 + c];
        if (ov > best || (ov == best && oi < bi)) { best = ov; bi = oi; }
        size_t p = (size_t)(bh * 16 + blockIdx.y) * SEQ + c0 + c;
        g_cpv[p] = best; g_cpi[p] = r0 + bi;
    }
}

// ---------------- reduce 16 partials -> q2k and k2q ----------------------
__global__ void argmax_reduce_kernel()
{
    int gid = blockIdx.x * blockDim.x + threadIdx.x;
    int which = gid >= NBH * SEQ;
    int i = gid & (NBH * SEQ - 1);
    int bh = i >> 11, n = i & 2047;
    const float* pv = which ? g_cpv : g_rpv;
    const int*   pi = which ? g_cpi : g_rpi;
    float v = -3e38f; int idx = 0;
#pragma unroll
    for (int t = 0; t < 16; t++) {
        size_t p = (size_t)(bh * 16 + t) * SEQ + n;
        float ov = pv[p];
        if (ov > v) { v = ov; idx = pi[p]; }
    }
    (which ? g_k2q : g_q2k)[i] = idx;
}

// ---------------- cycle consistency -> additive mask ---------------------
__global__ void asso_kernel(const int* __restrict__ smask,
                            const float* __restrict__ svalid)
{
    int i = blockIdx.x * blockDim.x + threadIdx.x;
    int bh = i >> 11, m = i & 2047;
    int b = bh >> 3;
    int kq = g_k2q[i];
    int remap = g_q2k[(bh << 11) + kq];
    float valid = (smask[(b << 11) + m] == smask[(b << 11) + remap])
                      ? svalid[(b << 11) + m] : 1.0f;
    g_madd[i] = valid * -10000.0f;
}

// ---- fused exp + online row-sum + P@V, single fp16 P and V --------------
__global__ void __launch_bounds__(256, 2) av_mma_kernel()
{
    __shared__ __align__(16) __half sAB[2 * AV_BUF];   // 18432 B
    __shared__ float sL[128];

    const int bh = blockIdx.y;
    const int n0 = blockIdx.x << 7;
    const int b = bh >> 3, h = bh & 7;
    const int tid = threadIdx.x, lane = tid & 31, w = tid >> 5;
    const int wm = (w & 3) << 5;       // 4 warps over 128 rows
    const int wn = (w >> 2) << 5;      // 2 warps over 64 cols

    const __half* Sp = g_S + (size_t)bh * SEQ * SEQ
                     + (size_t)(n0 + (tid >> 1)) * SEQ + (tid & 1) * 8;
    const float* mp = g_madd + bh * SEQ + (tid & 1) * 8;
    // V load: threads 0..127, row = tid>>1 (0..63), colhalf = tid&1
    const __half* Vp = g_Vt + (size_t)bh * HDIM * SEQ
                     + (size_t)(tid >> 1) * SEQ + (tid & 1) * 8;
    const int stsP = (tid >> 1) * KP + (tid & 1) * 8;
    const int stsV = AV_P + (tid >> 1) * KP + (tid & 1) * 8;

    uint32_t sbase = (uint32_t)__cvta_generic_to_shared(sAB);
    const int lrow = (lane & 7) + ((lane >> 3) & 1) * 8;
    const int lk = (lane >> 4) * 8;
    uint32_t adA[2], adB[2];
#pragma unroll
    for (int t = 0; t < 2; t++) {
        adA[t] = sbase + 2 * ((wm + 16 * t + lrow) * KP + lk);
        adB[t] = sbase + 2 * (AV_P + (wn + 16 * t + lrow) * KP + lk);
    }
    const uint32_t bufB = AV_BUF * 2;

    float acc[2][4][4] = {};
    float runL = 0.0f;

#pragma unroll 1
    for (int ks = 0; ks < 128; ks++) {
        const int buf = ks & 1;
        uint4 sv = *(const uint4*)(Sp + ks * 16);
        float4 m0 = *(const float4*)(mp + ks * 16);
        float4 m1 = *(const float4*)(mp + ks * 16 + 4);
        uint4 vv;
        if (tid < 128) vv = *(const uint4*)(Vp + ks * 16);

        float2 s01 = __half22float2(*(__half2*)&sv.x);
        float2 s23 = __half22float2(*(__half2*)&sv.y);
        float2 s45 = __half22float2(*(__half2*)&sv.z);
        float2 s67 = __half22float2(*(__half2*)&sv.w);

        float pv[8];
        pv[0] = fexp(s01.x + m0.x); pv[1] = fexp(s01.y + m0.y);
        pv[2] = fexp(s23.x + m0.z); pv[3] = fexp(s23.y + m0.w);
        pv[4] = fexp(s45.x + m1.x); pv[5] = fexp(s45.y + m1.y);
        pv[6] = fexp(s67.x + m1.z); pv[7] = fexp(s67.y + m1.w);
        runL += ((pv[0] + pv[1]) + (pv[2] + pv[3])) + ((pv[4] + pv[5]) + (pv[6] + pv[7]));

        uint4 ph;
        ph.x = pack_h2(pv[0], pv[1]); ph.y = pack_h2(pv[2], pv[3]);
        ph.z = pack_h2(pv[4], pv[5]); ph.w = pack_h2(pv[6], pv[7]);

        __half* sbuf = sAB + buf * AV_BUF;
        *(uint4*)&sbuf[stsP] = ph;
        if (tid < 128) *(uint4*)&sbuf[stsV] = vv;
        __syncthreads();

        uint32_t afr[2][4], bfr[2][4];
#pragma unroll
        for (int t = 0; t < 2; t++) {
            LDM4(afr[t], adA[t] + buf * bufB);
            LDM4(bfr[t], adB[t] + buf * bufB);
        }

#pragma unroll
        for (int mt = 0; mt < 2; mt++)
#pragma unroll
            for (int nt = 0; nt < 4; nt++) {
                int n2 = nt >> 1, j = nt & 1;
                MMA_F16(acc[mt][nt], afr[mt], bfr[n2][j], bfr[n2][j + 2]);
            }
    }

    runL += __shfl_xor_sync(0xffffffffu, runL, 1);
    if (!(tid & 1)) sL[tid >> 1] = runL;
    __syncthreads();

#pragma unroll
    for (int mt = 0; mt < 2; mt++) {
        int row0 = wm + 16 * mt + (lane >> 2);
        float inv0 = 1.0f / sL[row0];
        float inv1 = 1.0f / sL[row0 + 8];
#pragma unroll
        for (int nt = 0; nt < 4; nt++) {
            int col = wn + 8 * nt + 2 * (lane & 3);
            int n = n0 + row0;
            *(float2*)&g_X[(size_t)(b * SEQ + n) * CDIM + h * HDIM + col] =
                make_float2(acc[mt][nt][0] * inv0, acc[mt][nt][1] * inv0);
            *(float2*)&g_X[(size_t)(b * SEQ + n + 8) * CDIM + h * HDIM + col] =
                make_float2(acc[mt][nt][2] * inv1, acc[mt][nt][3] * inv1);
        }
    }
}

// ---------------- launcher ------------------------------------------------
extern "C" void kernel_launch(void* const* d_in, const int* in_sizes, int n_in,
                              void* d_out, int out_size)
{
    const float* q   = (const float*)d_in[0];
    const float* k   = (const float*)d_in[1];
    const float* v   = (const float*)d_in[2];
    const float* svm = (const float*)d_in[3];
    const int*   sm  = (const int*)d_in[4];
    const float* Wq  = (const float*)d_in[5];
    const float* Wk  = (const float*)d_in[6];
    const float* Wv  = (const float*)d_in[7];
    const float* Wp  = (const float*)d_in[8];
    float* out = (float*)d_out;

    float* X;
    cudaGetSymbolAddress((void**)&X, g_X);

    cudaFuncSetAttribute(qk_mma_kernel,
                         cudaFuncAttributeMaxDynamicSharedMemorySize, QK_SMEM);

    dim3 gp(CDIM / 128, (2 * SEQ) / 128);   // (4, 32)
    proj_mma_kernel<<<gp, 256>>>(q, Wq, nullptr, 0);
    proj_mma_kernel<<<gp, 256>>>(k, Wk, nullptr, 1);
    proj_mma_kernel<<<gp, 256>>>(v, Wv, nullptr, 2);

    qk_mma_kernel<<<dim3(SEQ / 128, SEQ / 128, NBH), 256, QK_SMEM>>>();

    argmax_reduce_kernel<<<(2 * NBH * SEQ) / 256, 256>>>();
    asso_kernel<<<(NBH * SEQ) / 256, 256>>>(sm, svm);

    av_mma_kernel<<<dim3(SEQ / 128, NBH), 256>>>();

    proj_mma_kernel<<<gp, 256>>>(X, Wp, out, 3);
}

// round 15
// speedup vs baseline: 2.2529x; 1.0187x over previous
#include <cuda_runtime.h>
#include <cuda_fp16.h>
#include <cstdint>

#define SEQ   2048
#define HDIM  64
#define NHEAD 8
#define CDIM  512
#define NBH   16            // B*H
#define QKSCALE 0.125f
#define KP    24            // smem tile pitch in halfs (48B, ldmatrix conflict-free)
#define KP2   72            // qk128 operand pitch in halfs (144B)
#define OPSZ  (128 * KP2)   // halfs per operand array (9216)
#define QK_SMEM (4 * OPSZ * 2)   // 73728 B (argmax buffers overlay after sync)
#define PKP   24            // proj smem pitch (halfs)
#define PPLANE (128 * PKP)  // 3072 halfs per 128x16 plane
// av smem: single P plane (128x16) + single V plane (64x16) per buffer
#define AV_P  (128 * KP)    // 3072 halfs
#define AV_V  (64 * KP)     // 1536 halfs
#define AV_BUF (AV_P + AV_V)   // 4608 halfs = 9216 B

constexpr int NQe = NBH * SEQ * HDIM;   // 2,097,152 elements per plane

// ---------------- scratch (device globals; no allocation) ----------------
__device__ __half g_Qh2[2 * NBH * SEQ * HDIM];    // hi/lo fp16 planes (Q pre-scaled)
__device__ __half g_Kh2[2 * NBH * SEQ * HDIM];
__device__ __half g_Vt[NBH * HDIM * SEQ];         // V transposed, single fp16 plane
__device__ float g_X[2 * SEQ * CDIM];             // attention output fp32
// S: tiled fp16 layout [bh][row/8][col/8][row%8][8 halfs]
__device__ __half g_S[(size_t)NBH * SEQ * SEQ];
__device__ int   g_q2k[NBH * SEQ];
__device__ int   g_k2q[NBH * SEQ];
__device__ float g_madd[NBH * SEQ];
__device__ float g_rpv[NBH * 16 * SEQ];
__device__ int   g_rpi[NBH * 16 * SEQ];
__device__ float g_cpv[NBH * 16 * SEQ];
__device__ int   g_cpi[NBH * 16 * SEQ];

#define MMA_F16(d, a, b0, b1)                                               \
    asm volatile("mma.sync.aligned.m16n8k16.row.col.f32.f16.f16.f32 "        \
                 "{%0,%1,%2,%3}, {%4,%5,%6,%7}, {%8,%9}, {%0,%1,%2,%3};"     \
                 : "+f"((d)[0]), "+f"((d)[1]), "+f"((d)[2]), "+f"((d)[3])    \
                 : "r"((a)[0]), "r"((a)[1]), "r"((a)[2]), "r"((a)[3]),       \
                   "r"(b0), "r"(b1))

#define LDM4(r, addr)                                                        \
    asm volatile("ldmatrix.sync.aligned.m8n8.x4.shared.b16 {%0,%1,%2,%3}, [%4];" \
                 : "=r"((r)[0]), "=r"((r)[1]), "=r"((r)[2]), "=r"((r)[3])    \
                 : "r"(addr))

__device__ __forceinline__ uint32_t pack_h2(float a, float b) {
    __half2 t;
    t.x = __float2half_rn(a);
    t.y = __float2half_rn(b);
    return *(uint32_t*)&t;
}

// split 8 fp32 values into hi/lo fp16 packs
__device__ __forceinline__ void split8(const float4& v0, const float4& v1,
                                       uint4& hi, uint4& lo) {
    float f[8] = { v0.x, v0.y, v0.z, v0.w, v1.x, v1.y, v1.z, v1.w };
    float h[8];
#pragma unroll
    for (int i = 0; i < 8; i++) h[i] = __half2float(__float2half_rn(f[i]));
    hi.x = pack_h2(f[0], f[1]); hi.y = pack_h2(f[2], f[3]);
    hi.z = pack_h2(f[4], f[5]); hi.w = pack_h2(f[6], f[7]);
    lo.x = pack_h2(f[0] - h[0], f[1] - h[1]);
    lo.y = pack_h2(f[2] - h[2], f[3] - h[3]);
    lo.z = pack_h2(f[4] - h[4], f[5] - h[5]);
    lo.w = pack_h2(f[6] - h[6], f[7] - h[7]);
}

// ---- projection GEMM via fp16 split-2 mma, 128x128 tile, fused cvt ------
// mode 0 folds QKSCALE into Q (exact: power-of-two scale).
// mode 2 writes single-plane fp16 V (transposed).
__global__ void __launch_bounds__(256, 2) proj_mma_kernel(
    const float* __restrict__ A, const float* __restrict__ W,
    float* __restrict__ outPlain, int mode)
{
    __shared__ __align__(16) __half sP[2 * 4 * PPLANE];   // 49152 B
    const int tid = threadIdx.x, lane = tid & 31, w = tid >> 5;
    const int r0 = blockIdx.y << 7, c0 = blockIdx.x << 7;
    const int wm = (w & 1) << 6, wn = (w >> 1) << 5;

    const float* Ap = A + (size_t)(r0 + (tid >> 1)) * CDIM + (tid & 1) * 8;
    const float* Wp = W + (size_t)(c0 + (tid >> 1)) * CDIM + (tid & 1) * 8;
    const int sts = (tid >> 1) * PKP + (tid & 1) * 8;

    uint32_t sb = (uint32_t)__cvta_generic_to_shared(sP);
    const int lrow = (lane & 7) + ((lane >> 3) & 1) * 8;
    const int lk = (lane >> 4) * 8;
    uint32_t adA[2][4], adB[2][2];
#pragma unroll
    for (int p = 0; p < 2; p++) {
#pragma unroll
        for (int mt = 0; mt < 4; mt++)
            adA[p][mt] = sb + 2 * (p * PPLANE + (wm + 16 * mt + lrow) * PKP + lk);
#pragma unroll
        for (int g = 0; g < 2; g++)
            adB[p][g] = sb + 2 * ((2 + p) * PPLANE + (wn + 16 * g + lrow) * PKP + lk);
    }
    const uint32_t bufB = 4 * PPLANE * 2;

    float acc[4][4][4] = {};

#pragma unroll 1
    for (int ks = 0; ks < 32; ks++) {
        const int buf = ks & 1;
        float4 a0 = *(const float4*)(Ap + ks * 16);
        float4 a1 = *(const float4*)(Ap + ks * 16 + 4);
        float4 w0 = *(const float4*)(Wp + ks * 16);
        float4 w1 = *(const float4*)(Wp + ks * 16 + 4);
        uint4 ahi, alo, whi, wlo;
        split8(a0, a1, ahi, alo);
        split8(w0, w1, whi, wlo);

        __half* sbuf = sP + buf * 4 * PPLANE;
        *(uint4*)&sbuf[0 * PPLANE + sts] = ahi;
        *(uint4*)&sbuf[1 * PPLANE + sts] = alo;
        *(uint4*)&sbuf[2 * PPLANE + sts] = whi;
        *(uint4*)&sbuf[3 * PPLANE + sts] = wlo;
        __syncthreads();

        uint32_t bfr[2][2][4];
#pragma unroll
        for (int p = 0; p < 2; p++)
#pragma unroll
            for (int g = 0; g < 2; g++) LDM4(bfr[p][g], adB[p][g] + buf * bufB);
#pragma unroll
        for (int mt = 0; mt < 4; mt++) {
            uint32_t afr[2][4];
#pragma unroll
            for (int p = 0; p < 2; p++) LDM4(afr[p], adA[p][mt] + buf * bufB);
#pragma unroll
            for (int nt = 0; nt < 4; nt++) {
                int n2 = nt >> 1, j = nt & 1;
                MMA_F16(acc[mt][nt], afr[0], bfr[0][n2][j], bfr[0][n2][j + 2]); // hh
                MMA_F16(acc[mt][nt], afr[0], bfr[1][n2][j], bfr[1][n2][j + 2]); // hl
                MMA_F16(acc[mt][nt], afr[1], bfr[0][n2][j], bfr[0][n2][j + 2]); // lh
            }
        }
    }

    if (mode == 0) {
#pragma unroll
        for (int mt = 0; mt < 4; mt++)
#pragma unroll
            for (int nt = 0; nt < 4; nt++)
#pragma unroll
                for (int e = 0; e < 4; e++) acc[mt][nt][e] *= QKSCALE;
    }

    // epilogue
#pragma unroll
    for (int mt = 0; mt < 4; mt++)
#pragma unroll
        for (int nt = 0; nt < 4; nt++)
#pragma unroll
            for (int hf = 0; hf < 2; hf++) {
                int row = r0 + wm + 16 * mt + (lane >> 2) + hf * 8;
                int col = c0 + wn + 8 * nt + 2 * (lane & 3);
                float v0 = acc[mt][nt][hf * 2];
                float v1 = acc[mt][nt][hf * 2 + 1];
                if (mode == 3) {
                    *(float2*)&outPlain[(size_t)row * CDIM + col] = make_float2(v0, v1);
                } else if (mode == 2) {
                    int b = row >> 11, n = row & 2047;
                    int hh = col >> 6, d = col & 63;
                    size_t idx = ((size_t)((b << 3) + hh) * HDIM + d) * SEQ + n;
                    g_Vt[idx] = __float2half_rn(v0);
                    g_Vt[idx + SEQ] = __float2half_rn(v1);
                } else {
                    int b = row >> 11, n = row & 2047;
                    int hh = col >> 6, d = col & 63;
                    __half h0 = __float2half_rn(v0), h1 = __float2half_rn(v1);
                    __half l0 = __float2half_rn(v0 - __half2float(h0));
                    __half l1 = __float2half_rn(v1 - __half2float(h1));
                    __half* OH = (mode == 0) ? g_Qh2 : g_Kh2;
                    size_t idx = ((size_t)((b << 3) + hh) * SEQ + n) * HDIM + d;
                    __half2 hv; hv.x = h0; hv.y = h1;
                    __half2 lv; lv.x = l0; lv.y = l1;
                    *(__half2*)&OH[idx] = hv;
                    *(__half2*)&OH[NQe + idx] = lv;
                }
            }
}

// ---- S = Qh @ Kh^T: 128x128 tile, register argmax, direct tiled S store -
__global__ void __launch_bounds__(256, 2) qk_mma_kernel()
{
    extern __shared__ __align__(16) unsigned char smraw[];
    __half* sOp = (__half*)smraw;
    float* rv = (float*)smraw;                       // overlays operands post-sync
    int*   ri = (int*)(smraw + 2048);
    float* cv = (float*)(smraw + 4096);
    int*   ci = (int*)(smraw + 5120);

    const int tid = threadIdx.x, lane = tid & 31, w = tid >> 5;
    const int bh = blockIdx.z;
    const int r0 = blockIdx.y << 7, c0 = blockIdx.x << 7;
    const int wm = (w & 1) << 6;
    const int wn = (w >> 1) << 5;
    const int q4 = lane >> 2, l4 = lane & 3;

    const __half* bases[4] = {
        g_Qh2 + (size_t)bh * SEQ * HDIM, g_Qh2 + (size_t)NQe + (size_t)bh * SEQ * HDIM,
        g_Kh2 + (size_t)bh * SEQ * HDIM, g_Kh2 + (size_t)NQe + (size_t)bh * SEQ * HDIM };
#pragma unroll
    for (int idx = tid; idx < 4096; idx += 256) {
        int arr = idx >> 10, rem = idx & 1023, row = rem >> 3, c = rem & 7;
        int gr = ((arr < 2) ? r0 : c0) + row;
        uint4 v = *(const uint4*)(bases[arr] + (size_t)gr * HDIM + c * 8);
        *(uint4*)(sOp + arr * OPSZ + row * KP2 + c * 8) = v;
    }
    __syncthreads();

    uint32_t sb = (uint32_t)__cvta_generic_to_shared(sOp);
    const int lrow = (lane & 7) + ((lane >> 3) & 1) * 8;
    const int lk = (lane >> 4) * 8;
    uint32_t adA[2][4], adB[2][2];
#pragma unroll
    for (int p = 0; p < 2; p++) {
#pragma unroll
        for (int mt = 0; mt < 4; mt++)
            adA[p][mt] = sb + 2 * (p * OPSZ + (wm + 16 * mt + lrow) * KP2 + lk);
#pragma unroll
        for (int g = 0; g < 2; g++)
            adB[p][g] = sb + 2 * ((2 + p) * OPSZ + (wn + 16 * g + lrow) * KP2 + lk);
    }

    float acc[4][4][4] = {};
#pragma unroll
    for (int ks = 0; ks < 4; ks++) {
        uint32_t bfr[2][2][4];
#pragma unroll
        for (int p = 0; p < 2; p++)
#pragma unroll
            for (int g = 0; g < 2; g++) LDM4(bfr[p][g], adB[p][g] + ks * 32);
#pragma unroll
        for (int mt = 0; mt < 4; mt++) {
            uint32_t afr[2][4];
#pragma unroll
            for (int p = 0; p < 2; p++) LDM4(afr[p], adA[p][mt] + ks * 32);
#pragma unroll
            for (int nt = 0; nt < 4; nt++) {
                int n2 = nt >> 1, j = nt & 1;
                MMA_F16(acc[mt][nt], afr[0], bfr[0][n2][j], bfr[0][n2][j + 2]);
                MMA_F16(acc[mt][nt], afr[0], bfr[1][n2][j], bfr[1][n2][j + 2]);
                MMA_F16(acc[mt][nt], afr[1], bfr[0][n2][j], bfr[0][n2][j + 2]);
            }
        }
    }

    // ---- direct tiled fp16 S store from fragments (coalesced 4B/lane) ----
    // layout: [row/8][col/8][row%8][8 halfs]; addr = rowAligned*SEQ + colAligned*8
    {
        __half* Sp = g_S + (size_t)bh * SEQ * SEQ + q4 * 8 + 2 * l4;
#pragma unroll
        for (int mt = 0; mt < 4; mt++)
#pragma unroll
            for (int hf = 0; hf < 2; hf++) {
                size_t rb = (size_t)(r0 + wm + 16 * mt + 8 * hf) * SEQ;
#pragma unroll
                for (int nt = 0; nt < 4; nt++) {
                    size_t off = rb + (size_t)(c0 + wn + 8 * nt) * 8;
                    *(uint32_t*)&Sp[off] =
                        pack_h2(acc[mt][nt][hf * 2], acc[mt][nt][hf * 2 + 1]);
                }
            }
    }

    // ---- row argmax in registers ----
    float rbv[8]; int rbi[8];
#pragma unroll
    for (int mt = 0; mt < 4; mt++)
#pragma unroll
        for (int hf = 0; hf < 2; hf++) {
            float best = -3e38f; int bi = 0;
#pragma unroll
            for (int nt = 0; nt < 4; nt++)
#pragma unroll
                for (int j = 0; j < 2; j++) {
                    float v = acc[mt][nt][hf * 2 + j];
                    int idx = wn + 8 * nt + 2 * l4 + j;
                    if (v > best) { best = v; bi = idx; }
                }
            rbv[mt * 2 + hf] = best; rbi[mt * 2 + hf] = bi;
        }
#pragma unroll
    for (int o = 1; o < 4; o <<= 1)
#pragma unroll
        for (int r = 0; r < 8; r++) {
            float ov = __shfl_xor_sync(0xffffffffu, rbv[r], o);
            int   oi = __shfl_xor_sync(0xffffffffu, rbi[r], o);
            if (ov > rbv[r] || (ov == rbv[r] && oi < rbi[r])) { rbv[r] = ov; rbi[r] = oi; }
        }

    // ---- col argmax in registers ----
    float cbv[8]; int cbi[8];
#pragma unroll
    for (int nt = 0; nt < 4; nt++)
#pragma unroll
        for (int j = 0; j < 2; j++) {
            float best = -3e38f; int bi = 0;
#pragma unroll
            for (int mt = 0; mt < 4; mt++)
#pragma unroll
                for (int hf = 0; hf < 2; hf++) {
                    float v = acc[mt][nt][hf * 2 + j];
                    int row = wm + 16 * mt + q4 + 8 * hf;
                    if (v > best) { best = v; bi = row; }
                }
            cbv[nt * 2 + j] = best; cbi[nt * 2 + j] = bi;
        }
#pragma unroll
    for (int o = 4; o < 32; o <<= 1)
#pragma unroll
        for (int cc = 0; cc < 8; cc++) {
            float ov = __shfl_xor_sync(0xffffffffu, cbv[cc], o);
            int   oi = __shfl_xor_sync(0xffffffffu, cbi[cc], o);
            if (ov > cbv[cc] || (ov == cbv[cc] && oi < cbi[cc])) { cbv[cc] = ov; cbi[cc] = oi; }
        }

    __syncthreads();   // operands fully consumed; overlay argmax buffers

    if (l4 == 0) {
#pragma unroll
        for (int r = 0; r < 8; r++) {
            int row = wm + 16 * (r >> 1) + q4 + 8 * (r & 1);
            rv[(w >> 1) * 128 + row] = rbv[r];
            ri[(w >> 1) * 128 + row] = rbi[r];
        }
    }
    if (lane < 4) {
#pragma unroll
        for (int cc = 0; cc < 8; cc++) {
            int col = wn + 8 * (cc >> 1) + 2 * lane + (cc & 1);
            cv[(w & 1) * 128 + col] = cbv[cc];
            ci[(w & 1) * 128 + col] = cbi[cc];
        }
    }
    __syncthreads();

    if (tid < 128) {
        float best = rv[tid]; int bi = ri[tid];
#pragma unroll
        for (int g = 1; g < 4; g++) {
            float ov = rv[g * 128 + tid]; int oi = ri[g * 128 + tid];
            if (ov > best || (ov == best && oi < bi)) { best = ov; bi = oi; }
        }
        size_t p = (size_t)(bh * 16 + blockIdx.x) * SEQ + r0 + tid;
        g_rpv[p] = best; g_rpi[p] = c0 + bi;
    } else {
        int c = tid - 128;
        float best = cv[c]; int bi = ci[c];
        float ov = cv[128 + c]; int oi = ci[128 + c];
        if (ov > best || (ov == best && oi < bi)) { best = ov; bi = oi; }
        size_t p = (size_t)(bh * 16 + blockIdx.y) * SEQ + c0 + c;
        g_cpv[p] = best; g_cpi[p] = r0 + bi;
    }
}

// ---------------- reduce 16 partials -> q2k and k2q ----------------------
__global__ void argmax_reduce_kernel()
{
    int gid = blockIdx.x * blockDim.x + threadIdx.x;
    int which = gid >= NBH * SEQ;
    int i = gid & (NBH * SEQ - 1);
    int bh = i >> 11, n = i & 2047;
    const float* pv = which ? g_cpv : g_rpv;
    const int*   pi = which ? g_cpi : g_rpi;
    float v = -3e38f; int idx = 0;
#pragma unroll
    for (int t = 0; t < 16; t++) {
        size_t p = (size_t)(bh * 16 + t) * SEQ + n;
        float ov = pv[p];
        if (ov > v) { v = ov; idx = pi[p]; }
    }
    (which ? g_k2q : g_q2k)[i] = idx;
}

// ---------------- cycle consistency -> additive mask ---------------------
__global__ void asso_kernel(const int* __restrict__ smask,
                            const float* __restrict__ svalid)
{
    int i = blockIdx.x * blockDim.x + threadIdx.x;
    int bh = i >> 11, m = i & 2047;
    int b = bh >> 3;
    int kq = g_k2q[i];
    int remap = g_q2k[(bh << 11) + kq];
    float valid = (smask[(b << 11) + m] == smask[(b << 11) + remap])
                      ? svalid[(b << 11) + m] : 1.0f;
    g_madd[i] = valid * -10000.0f;
}

// ---- fused exp (MUFU) + online row-sum + P@V, tiled S read --------------
__global__ void __launch_bounds__(256, 2) av_mma_kernel()
{
    __shared__ __align__(16) __half sAB[2 * AV_BUF];   // 18432 B
    __shared__ float sL[128];

    const int bh = blockIdx.y;
    const int n0 = blockIdx.x << 7;
    const int b = bh >> 3, h = bh & 7;
    const int tid = threadIdx.x, lane = tid & 31, w = tid >> 5;
    const int wm = (w & 3) << 5;       // 4 warps over 128 rows
    const int wn = (w >> 2) << 5;      // 2 warps over 64 cols

    // tiled S read: n = n0 + tid>>1; per ks chunk c8 = 2ks + (tid&1)
    const int n = n0 + (tid >> 1);
    const __half* Sp = g_S + (size_t)bh * SEQ * SEQ
                     + (size_t)(n & ~7) * SEQ + (tid & 1) * 64 + (n & 7) * 8;
    const float* mp = g_madd + bh * SEQ + (tid & 1) * 8;
    const __half* Vp = g_Vt + (size_t)bh * HDIM * SEQ
                     + (size_t)(tid >> 1) * SEQ + (tid & 1) * 8;
    const int stsP = (tid >> 1) * KP + (tid & 1) * 8;
    const int stsV = AV_P + (tid >> 1) * KP + (tid & 1) * 8;

    uint32_t sbase = (uint32_t)__cvta_generic_to_shared(sAB);
    const int lrow = (lane & 7) + ((lane >> 3) & 1) * 8;
    const int lk = (lane >> 4) * 8;
    uint32_t adA[2], adB[2];
#pragma unroll
    for (int t = 0; t < 2; t++) {
        adA[t] = sbase + 2 * ((wm + 16 * t + lrow) * KP + lk);
        adB[t] = sbase + 2 * (AV_P + (wn + 16 * t + lrow) * KP + lk);
    }
    const uint32_t bufB = AV_BUF * 2;

    float acc[2][4][4] = {};
    float runL = 0.0f;

#pragma unroll 1
    for (int ks = 0; ks < 128; ks++) {
        const int buf = ks & 1;
        uint4 sv = *(const uint4*)(Sp + ks * 128);
        float4 m0 = *(const float4*)(mp + ks * 16);
        float4 m1 = *(const float4*)(mp + ks * 16 + 4);
        uint4 vv;
        if (tid < 128) vv = *(const uint4*)(Vp + ks * 16);

        float2 s01 = __half22float2(*(__half2*)&sv.x);
        float2 s23 = __half22float2(*(__half2*)&sv.y);
        float2 s45 = __half22float2(*(__half2*)&sv.z);
        float2 s67 = __half22float2(*(__half2*)&sv.w);

        float pv[8];
        pv[0] = __expf(s01.x + m0.x); pv[1] = __expf(s01.y + m0.y);
        pv[2] = __expf(s23.x + m0.z); pv[3] = __expf(s23.y + m0.w);
        pv[4] = __expf(s45.x + m1.x); pv[5] = __expf(s45.y + m1.y);
        pv[6] = __expf(s67.x + m1.z); pv[7] = __expf(s67.y + m1.w);
        runL += ((pv[0] + pv[1]) + (pv[2] + pv[3])) + ((pv[4] + pv[5]) + (pv[6] + pv[7]));

        uint4 ph;
        ph.x = pack_h2(pv[0], pv[1]); ph.y = pack_h2(pv[2], pv[3]);
        ph.z = pack_h2(pv[4], pv[5]); ph.w = pack_h2(pv[6], pv[7]);

        __half* sbuf = sAB + buf * AV_BUF;
        *(uint4*)&sbuf[stsP] = ph;
        if (tid < 128) *(uint4*)&sbuf[stsV] = vv;
        __syncthreads();

        uint32_t afr[2][4], bfr[2][4];
#pragma unroll
        for (int t = 0; t < 2; t++) {
            LDM4(afr[t], adA[t] + buf * bufB);
            LDM4(bfr[t], adB[t] + buf * bufB);
        }

#pragma unroll
        for (int mt = 0; mt < 2; mt++)
#pragma unroll
            for (int nt = 0; nt < 4; nt++) {
                int n2 = nt >> 1, j = nt & 1;
                MMA_F16(acc[mt][nt], afr[mt], bfr[n2][j], bfr[n2][j + 2]);
            }
    }

    runL += __shfl_xor_sync(0xffffffffu, runL, 1);
    if (!(tid & 1)) sL[tid >> 1] = runL;
    __syncthreads();

#pragma unroll
    for (int mt = 0; mt < 2; mt++) {
        int row0 = wm + 16 * mt + (lane >> 2);
        float inv0 = 1.0f / sL[row0];
        float inv1 = 1.0f / sL[row0 + 8];
#pragma unroll
        for (int nt = 0; nt < 4; nt++) {
            int col = wn + 8 * nt + 2 * (lane & 3);
            int nn = n0 + row0;
            *(float2*)&g_X[(size_t)(b * SEQ + nn) * CDIM + h * HDIM + col] =
                make_float2(acc[mt][nt][0] * inv0, acc[mt][nt][1] * inv0);
            *(float2*)&g_X[(size_t)(b * SEQ + nn + 8) * CDIM + h * HDIM + col] =
                make_float2(acc[mt][nt][2] * inv1, acc[mt][nt][3] * inv1);
        }
    }
}

// ---------------- launcher ------------------------------------------------
extern "C" void kernel_launch(void* const* d_in, const int* in_sizes, int n_in,
                              void* d_out, int out_size)
{
    const float* q   = (const float*)d_in[0];
    const float* k   = (const float*)d_in[1];
    const float* v   = (const float*)d_in[2];
    const float* svm = (const float*)d_in[3];
    const int*   sm  = (const int*)d_in[4];
    const float* Wq  = (const float*)d_in[5];
    const float* Wk  = (const float*)d_in[6];
    const float* Wv  = (const float*)d_in[7];
    const float* Wp  = (const float*)d_in[8];
    float* out = (float*)d_out;

    float* X;
    cudaGetSymbolAddress((void**)&X, g_X);

    cudaFuncSetAttribute(qk_mma_kernel,
                         cudaFuncAttributeMaxDynamicSharedMemorySize, QK_SMEM);

    dim3 gp(CDIM / 128, (2 * SEQ) / 128);   // (4, 32)
    proj_mma_kernel<<<gp, 256>>>(q, Wq, nullptr, 0);
    proj_mma_kernel<<<gp, 256>>>(k, Wk, nullptr, 1);
    proj_mma_kernel<<<gp, 256>>>(v, Wv, nullptr, 2);

    qk_mma_kernel<<<dim3(SEQ / 128, SEQ / 128, NBH), 256, QK_SMEM>>>();

    argmax_reduce_kernel<<<(2 * NBH * SEQ) / 256, 256>>>();
    asso_kernel<<<(NBH * SEQ) / 256, 256>>>(sm, svm);

    av_mma_kernel<<<dim3(SEQ / 128, NBH), 256>>>();

    proj_mma_kernel<<<gp, 256>>>(X, Wp, out, 3);
}

// round 16
// speedup vs baseline: 2.9959x; 1.3298x over previous
#include <cuda_runtime.h>
#include <cuda_fp16.h>
#include <cstdint>

#define SEQ   2048
#define HDIM  64
#define NHEAD 8
#define CDIM  512
#define NBH   16            // B*H
#define QKSCALE 0.125f
#define KP    24            // smem tile pitch in halfs (48B, ldmatrix conflict-free)
#define KP2   72            // qk128 operand pitch in halfs (144B)
#define OPSZ  (128 * KP2)   // halfs per operand array (9216)
#define QK_SMEM (4 * OPSZ * 2)   // 73728 B (argmax buffers overlay after sync)
#define PKP   24            // proj smem pitch (halfs)
#define PPLANE (128 * PKP)  // 3072 halfs per 128x16 plane
// av smem: single P plane (128x16) + single V plane (64x16) per buffer
#define AV_P  (128 * KP)    // 3072 halfs
#define AV_V  (64 * KP)     // 1536 halfs
#define AV_BUF (AV_P + AV_V)   // 4608 halfs = 9216 B

constexpr int NQe = NBH * SEQ * HDIM;   // 2,097,152 elements per plane

// ---------------- scratch (device globals; no allocation) ----------------
__device__ __half g_Qh2[2 * NBH * SEQ * HDIM];    // hi/lo fp16 planes (Q pre-scaled)
__device__ __half g_Kh2[2 * NBH * SEQ * HDIM];
__device__ __half g_Vt[NBH * HDIM * SEQ];         // V transposed, single fp16 plane
__device__ float g_X[2 * SEQ * CDIM];             // attention output fp32
// S: tiled fp16 layout [bh][row/8][col/8][row%8][8 halfs]
__device__ __half g_S[(size_t)NBH * SEQ * SEQ];
__device__ int   g_q2k[NBH * SEQ];
__device__ int   g_k2q[NBH * SEQ];
__device__ float g_madd[NBH * SEQ];
__device__ float g_rpv[NBH * 16 * SEQ];
__device__ int   g_rpi[NBH * 16 * SEQ];
__device__ float g_cpv[NBH * 16 * SEQ];
__device__ int   g_cpi[NBH * 16 * SEQ];

#define MMA_F16(d, a, b0, b1)                                               \
    asm volatile("mma.sync.aligned.m16n8k16.row.col.f32.f16.f16.f32 "        \
                 "{%0,%1,%2,%3}, {%4,%5,%6,%7}, {%8,%9}, {%0,%1,%2,%3};"     \
                 : "+f"((d)[0]), "+f"((d)[1]), "+f"((d)[2]), "+f"((d)[3])    \
                 : "r"((a)[0]), "r"((a)[1]), "r"((a)[2]), "r"((a)[3]),       \
                   "r"(b0), "r"(b1))

#define LDM4(r, addr)                                                        \
    asm volatile("ldmatrix.sync.aligned.m8n8.x4.shared.b16 {%0,%1,%2,%3}, [%4];" \
                 : "=r"((r)[0]), "=r"((r)[1]), "=r"((r)[2]), "=r"((r)[3])    \
                 : "r"(addr))

__device__ __forceinline__ uint32_t pack_h2(float a, float b) {
    __half2 t;
    t.x = __float2half_rn(a);
    t.y = __float2half_rn(b);
    return *(uint32_t*)&t;
}

// split 8 fp32 values into hi/lo fp16 packs
__device__ __forceinline__ void split8(const float4& v0, const float4& v1,
                                       uint4& hi, uint4& lo) {
    float f[8] = { v0.x, v0.y, v0.z, v0.w, v1.x, v1.y, v1.z, v1.w };
    float h[8];
#pragma unroll
    for (int i = 0; i < 8; i++) h[i] = __half2float(__float2half_rn(f[i]));
    hi.x = pack_h2(f[0], f[1]); hi.y = pack_h2(f[2], f[3]);
    hi.z = pack_h2(f[4], f[5]); hi.w = pack_h2(f[6], f[7]);
    lo.x = pack_h2(f[0] - h[0], f[1] - h[1]);
    lo.y = pack_h2(f[2] - h[2], f[3] - h[3]);
    lo.z = pack_h2(f[4] - h[4], f[5] - h[5]);
    lo.w = pack_h2(f[6] - h[6], f[7] - h[7]);
}

// ---- projection GEMM via fp16 split-2 mma, 128x128 tile, fused cvt ------
// mode -1: fused q/k/v — blockIdx.z in {0,1,2} selects projection.
// mode  3: out-proj (A0/W0, fp32 outPlain).
// mode 0 folds QKSCALE into Q (exact: power-of-two scale).
__global__ void __launch_bounds__(256, 2) proj_mma_kernel(
    const float* __restrict__ A0, const float* __restrict__ A1,
    const float* __restrict__ A2,
    const float* __restrict__ W0, const float* __restrict__ W1,
    const float* __restrict__ W2,
    float* __restrict__ outPlain, int mode)
{
    __shared__ __align__(16) __half sP[2 * 4 * PPLANE];   // 49152 B
    const int tid = threadIdx.x, lane = tid & 31, w = tid >> 5;
    const int r0 = blockIdx.y << 7, c0 = blockIdx.x << 7;
    const int wm = (w & 1) << 6, wn = (w >> 1) << 5;
    const int m = (mode < 0) ? (int)blockIdx.z : mode;

    const float* A = (m == 1) ? A1 : ((m == 2) ? A2 : A0);
    const float* W = (m == 1) ? W1 : ((m == 2) ? W2 : W0);

    const float* Ap = A + (size_t)(r0 + (tid >> 1)) * CDIM + (tid & 1) * 8;
    const float* Wp = W + (size_t)(c0 + (tid >> 1)) * CDIM + (tid & 1) * 8;
    const int sts = (tid >> 1) * PKP + (tid & 1) * 8;

    uint32_t sb = (uint32_t)__cvta_generic_to_shared(sP);
    const int lrow = (lane & 7) + ((lane >> 3) & 1) * 8;
    const int lk = (lane >> 4) * 8;
    uint32_t adA[2][4], adB[2][2];
#pragma unroll
    for (int p = 0; p < 2; p++) {
#pragma unroll
        for (int mt = 0; mt < 4; mt++)
            adA[p][mt] = sb + 2 * (p * PPLANE + (wm + 16 * mt + lrow) * PKP + lk);
#pragma unroll
        for (int g = 0; g < 2; g++)
            adB[p][g] = sb + 2 * ((2 + p) * PPLANE + (wn + 16 * g + lrow) * PKP + lk);
    }
    const uint32_t bufB = 4 * PPLANE * 2;

    float acc[4][4][4] = {};
    float4 a0 = *(const float4*)Ap;
    float4 a1 = *(const float4*)(Ap + 4);
    float4 w0 = *(const float4*)Wp;
    float4 w1 = *(const float4*)(Wp + 4);

#pragma unroll 1
    for (int ks = 0; ks < 32; ks++) {
        const int buf = ks & 1;
        uint4 ahi, alo, whi, wlo;
        split8(a0, a1, ahi, alo);
        split8(w0, w1, whi, wlo);

        __half* sbuf = sP + buf * 4 * PPLANE;
        *(uint4*)&sbuf[0 * PPLANE + sts] = ahi;
        *(uint4*)&sbuf[1 * PPLANE + sts] = alo;
        *(uint4*)&sbuf[2 * PPLANE + sts] = whi;
        *(uint4*)&sbuf[3 * PPLANE + sts] = wlo;

        if (ks < 31) {   // prefetch next k-chunk before the barrier
            a0 = *(const float4*)(Ap + (ks + 1) * 16);
            a1 = *(const float4*)(Ap + (ks + 1) * 16 + 4);
            w0 = *(const float4*)(Wp + (ks + 1) * 16);
            w1 = *(const float4*)(Wp + (ks + 1) * 16 + 4);
        }
        __syncthreads();

        uint32_t bfr[2][2][4];
#pragma unroll
        for (int p = 0; p < 2; p++)
#pragma unroll
            for (int g = 0; g < 2; g++) LDM4(bfr[p][g], adB[p][g] + buf * bufB);
#pragma unroll
        for (int mt = 0; mt < 4; mt++) {
            uint32_t afr[2][4];
#pragma unroll
            for (int p = 0; p < 2; p++) LDM4(afr[p], adA[p][mt] + buf * bufB);
#pragma unroll
            for (int nt = 0; nt < 4; nt++) {
                int n2 = nt >> 1, j = nt & 1;
                MMA_F16(acc[mt][nt], afr[0], bfr[0][n2][j], bfr[0][n2][j + 2]); // hh
                MMA_F16(acc[mt][nt], afr[0], bfr[1][n2][j], bfr[1][n2][j + 2]); // hl
                MMA_F16(acc[mt][nt], afr[1], bfr[0][n2][j], bfr[0][n2][j + 2]); // lh
            }
        }
    }

    if (m == 0) {
#pragma unroll
        for (int mt = 0; mt < 4; mt++)
#pragma unroll
            for (int nt = 0; nt < 4; nt++)
#pragma unroll
                for (int e = 0; e < 4; e++) acc[mt][nt][e] *= QKSCALE;
    }

    // epilogue
#pragma unroll
    for (int mt = 0; mt < 4; mt++)
#pragma unroll
        for (int nt = 0; nt < 4; nt++)
#pragma unroll
            for (int hf = 0; hf < 2; hf++) {
                int row = r0 + wm + 16 * mt + (lane >> 2) + hf * 8;
                int col = c0 + wn + 8 * nt + 2 * (lane & 3);
                float v0 = acc[mt][nt][hf * 2];
                float v1 = acc[mt][nt][hf * 2 + 1];
                if (m == 3) {
                    *(float2*)&outPlain[(size_t)row * CDIM + col] = make_float2(v0, v1);
                } else if (m == 2) {
                    int b = row >> 11, n = row & 2047;
                    int hh = col >> 6, d = col & 63;
                    size_t idx = ((size_t)((b << 3) + hh) * HDIM + d) * SEQ + n;
                    g_Vt[idx] = __float2half_rn(v0);
                    g_Vt[idx + SEQ] = __float2half_rn(v1);
                } else {
                    int b = row >> 11, n = row & 2047;
                    int hh = col >> 6, d = col & 63;
                    __half h0 = __float2half_rn(v0), h1 = __float2half_rn(v1);
                    __half l0 = __float2half_rn(v0 - __half2float(h0));
                    __half l1 = __float2half_rn(v1 - __half2float(h1));
                    __half* OH = (m == 0) ? g_Qh2 : g_Kh2;
                    size_t idx = ((size_t)((b << 3) + hh) * SEQ + n) * HDIM + d;
                    __half2 hv; hv.x = h0; hv.y = h1;
                    __half2 lv; lv.x = l0; lv.y = l1;
                    *(__half2*)&OH[idx] = hv;
                    *(__half2*)&OH[NQe + idx] = lv;
                }
            }
}

// ---- S = Qh @ Kh^T: 128x128 tile, register argmax, direct tiled S store -
__global__ void __launch_bounds__(256, 2) qk_mma_kernel()
{
    extern __shared__ __align__(16) unsigned char smraw[];
    __half* sOp = (__half*)smraw;
    float* rv = (float*)smraw;                       // overlays operands post-sync
    int*   ri = (int*)(smraw + 2048);
    float* cv = (float*)(smraw + 4096);
    int*   ci = (int*)(smraw + 5120);

    const int tid = threadIdx.x, lane = tid & 31, w = tid >> 5;
    const int bh = blockIdx.z;
    const int r0 = blockIdx.y << 7, c0 = blockIdx.x << 7;
    const int wm = (w & 1) << 6;
    const int wn = (w >> 1) << 5;
    const int q4 = lane >> 2, l4 = lane & 3;

    const __half* bases[4] = {
        g_Qh2 + (size_t)bh * SEQ * HDIM, g_Qh2 + (size_t)NQe + (size_t)bh * SEQ * HDIM,
        g_Kh2 + (size_t)bh * SEQ * HDIM, g_Kh2 + (size_t)NQe + (size_t)bh * SEQ * HDIM };
#pragma unroll
    for (int idx = tid; idx < 4096; idx += 256) {
        int arr = idx >> 10, rem = idx & 1023, row = rem >> 3, c = rem & 7;
        int gr = ((arr < 2) ? r0 : c0) + row;
        uint4 v = *(const uint4*)(bases[arr] + (size_t)gr * HDIM + c * 8);
        *(uint4*)(sOp + arr * OPSZ + row * KP2 + c * 8) = v;
    }
    __syncthreads();

    uint32_t sb = (uint32_t)__cvta_generic_to_shared(sOp);
    const int lrow = (lane & 7) + ((lane >> 3) & 1) * 8;
    const int lk = (lane >> 4) * 8;
    uint32_t adA[2][4], adB[2][2];
#pragma unroll
    for (int p = 0; p < 2; p++) {
#pragma unroll
        for (int mt = 0; mt < 4; mt++)
            adA[p][mt] = sb + 2 * (p * OPSZ + (wm + 16 * mt + lrow) * KP2 + lk);
#pragma unroll
        for (int g = 0; g < 2; g++)
            adB[p][g] = sb + 2 * ((2 + p) * OPSZ + (wn + 16 * g + lrow) * KP2 + lk);
    }

    float acc[4][4][4] = {};
#pragma unroll
    for (int ks = 0; ks < 4; ks++) {
        uint32_t bfr[2][2][4];
#pragma unroll
        for (int p = 0; p < 2; p++)
#pragma unroll
            for (int g = 0; g < 2; g++) LDM4(bfr[p][g], adB[p][g] + ks * 32);
#pragma unroll
        for (int mt = 0; mt < 4; mt++) {
            uint32_t afr[2][4];
#pragma unroll
            for (int p = 0; p < 2; p++) LDM4(afr[p], adA[p][mt] + ks * 32);
#pragma unroll
            for (int nt = 0; nt < 4; nt++) {
                int n2 = nt >> 1, j = nt & 1;
                MMA_F16(acc[mt][nt], afr[0], bfr[0][n2][j], bfr[0][n2][j + 2]);
                MMA_F16(acc[mt][nt], afr[0], bfr[1][n2][j], bfr[1][n2][j + 2]);
                MMA_F16(acc[mt][nt], afr[1], bfr[0][n2][j], bfr[0][n2][j + 2]);
            }
        }
    }

    // ---- direct tiled fp16 S store from fragments (coalesced 4B/lane) ----
    {
        __half* Sp = g_S + (size_t)bh * SEQ * SEQ + q4 * 8 + 2 * l4;
#pragma unroll
        for (int mt = 0; mt < 4; mt++)
#pragma unroll
            for (int hf = 0; hf < 2; hf++) {
                size_t rb = (size_t)(r0 + wm + 16 * mt + 8 * hf) * SEQ;
#pragma unroll
                for (int nt = 0; nt < 4; nt++) {
                    size_t off = rb + (size_t)(c0 + wn + 8 * nt) * 8;
                    *(uint32_t*)&Sp[off] =
                        pack_h2(acc[mt][nt][hf * 2], acc[mt][nt][hf * 2 + 1]);
                }
            }
    }

    // ---- row argmax in registers ----
    float rbv[8]; int rbi[8];
#pragma unroll
    for (int mt = 0; mt < 4; mt++)
#pragma unroll
        for (int hf = 0; hf < 2; hf++) {
            float best = -3e38f; int bi = 0;
#pragma unroll
            for (int nt = 0; nt < 4; nt++)
#pragma unroll
                for (int j = 0; j < 2; j++) {
                    float v = acc[mt][nt][hf * 2 + j];
                    int idx = wn + 8 * nt + 2 * l4 + j;
                    if (v > best) { best = v; bi = idx; }
                }
            rbv[mt * 2 + hf] = best; rbi[mt * 2 + hf] = bi;
        }
#pragma unroll
    for (int o = 1; o < 4; o <<= 1)
#pragma unroll
        for (int r = 0; r < 8; r++) {
            float ov = __shfl_xor_sync(0xffffffffu, rbv[r], o);
            int   oi = __shfl_xor_sync(0xffffffffu, rbi[r], o);
            if (ov > rbv[r] || (ov == rbv[r] && oi < rbi[r])) { rbv[r] = ov; rbi[r] = oi; }
        }

    // ---- col argmax in registers ----
    float cbv[8]; int cbi[8];
#pragma unroll
    for (int nt = 0; nt < 4; nt++)
#pragma unroll
        for (int j = 0; j < 2; j++) {
            float best = -3e38f; int bi = 0;
#pragma unroll
            for (int mt = 0; mt < 4; mt++)
#pragma unroll
                for (int hf = 0; hf < 2; hf++) {
                    float v = acc[mt][nt][hf * 2 + j];
                    int row = wm + 16 * mt + q4 + 8 * hf;
                    if (v > best) { best = v; bi = row; }
                }
            cbv[nt * 2 + j] = best; cbi[nt * 2 + j] = bi;
        }
#pragma unroll
    for (int o = 4; o < 32; o <<= 1)
#pragma unroll
        for (int cc = 0; cc < 8; cc++) {
            float ov = __shfl_xor_sync(0xffffffffu, cbv[cc], o);
            int   oi = __shfl_xor_sync(0xffffffffu, cbi[cc], o);
            if (ov > cbv[cc] || (ov == cbv[cc] && oi < cbi[cc])) { cbv[cc] = ov; cbi[cc] = oi; }
        }

    __syncthreads();   // operands fully consumed; overlay argmax buffers

    if (l4 == 0) {
#pragma unroll
        for (int r = 0; r < 8; r++) {
            int row = wm + 16 * (r >> 1) + q4 + 8 * (r & 1);
            rv[(w >> 1) * 128 + row] = rbv[r];
            ri[(w >> 1) * 128 + row] = rbi[r];
        }
    }
    if (lane < 4) {
#pragma unroll
        for (int cc = 0; cc < 8; cc++) {
            int col = wn + 8 * (cc >> 1) + 2 * lane + (cc & 1);
            cv[(w & 1) * 128 + col] = cbv[cc];
            ci[(w & 1) * 128 + col] = cbi[cc];
        }
    }
    __syncthreads();

    if (tid < 128) {
        float best = rv[tid]; int bi = ri[tid];
#pragma unroll
        for (int g = 1; g < 4; g++) {
            float ov = rv[g * 128 + tid]; int oi = ri[g * 128 + tid];
            if (ov > best || (ov == best && oi < bi)) { best = ov; bi = oi; }
        }
        size_t p = (size_t)(bh * 16 + blockIdx.x) * SEQ + r0 + tid;
        g_rpv[p] = best; g_rpi[p] = c0 + bi;
    } else {
        int c = tid - 128;
        float best = cv[c]; int bi = ci[c];
        float ov = cv[128 + c]; int oi = ci[128 + c];
        if (ov > best || (ov == best && oi < bi)) { best = ov; bi = oi; }
        size_t p = (size_t)(bh * 16 + blockIdx.y) * SEQ + c0 + c;
        g_cpv[p] = best; g_cpi[p] = r0 + bi;
    }
}

// ---------------- reduce 16 partials -> q2k and k2q ----------------------
__global__ void argmax_reduce_kernel()
{
    int gid = blockIdx.x * blockDim.x + threadIdx.x;
    int which = gid >= NBH * SEQ;
    int i = gid & (NBH * SEQ - 1);
    int bh = i >> 11, n = i & 2047;
    const float* pv = which ? g_cpv : g_rpv;
    const int*   pi = which ? g_cpi : g_rpi;
    float v = -3e38f; int idx = 0;
#pragma unroll
    for (int t = 0; t < 16; t++) {
        size_t p = (size_t)(bh * 16 + t) * SEQ + n;
        float ov = pv[p];
        if (ov > v) { v = ov; idx = pi[p]; }
    }
    (which ? g_k2q : g_q2k)[i] = idx;
}

// ---------------- cycle consistency -> additive mask ---------------------
__global__ void asso_kernel(const int* __restrict__ smask,
                            const float* __restrict__ svalid)
{
    int i = blockIdx.x * blockDim.x + threadIdx.x;
    int bh = i >> 11, m = i & 2047;
    int b = bh >> 3;
    int kq = g_k2q[i];
    int remap = g_q2k[(bh << 11) + kq];
    float valid = (smask[(b << 11) + m] == smask[(b << 11) + remap])
                      ? svalid[(b << 11) + m] : 1.0f;
    g_madd[i] = valid * -10000.0f;
}

// ---- fused exp (MUFU) + online row-sum + P@V, prefetched tiled S read ---
__global__ void __launch_bounds__(256, 2) av_mma_kernel()
{
    __shared__ __align__(16) __half sAB[2 * AV_BUF];   // 18432 B
    __shared__ float sL[128];

    const int bh = blockIdx.y;
    const int n0 = blockIdx.x << 7;
    const int b = bh >> 3, h = bh & 7;
    const int tid = threadIdx.x, lane = tid & 31, w = tid >> 5;
    const int wm = (w & 3) << 5;       // 4 warps over 128 rows
    const int wn = (w >> 2) << 5;      // 2 warps over 64 cols

    const int n = n0 + (tid >> 1);
    const __half* Sp = g_S + (size_t)bh * SEQ * SEQ
                     + (size_t)(n & ~7) * SEQ + (tid & 1) * 64 + (n & 7) * 8;
    const float* mp = g_madd + bh * SEQ + (tid & 1) * 8;
    const __half* Vp = g_Vt + (size_t)bh * HDIM * SEQ
                     + (size_t)(tid >> 1) * SEQ + (tid & 1) * 8;
    const int stsP = (tid >> 1) * KP + (tid & 1) * 8;
    const int stsV = AV_P + (tid >> 1) * KP + (tid & 1) * 8;

    uint32_t sbase = (uint32_t)__cvta_generic_to_shared(sAB);
    const int lrow = (lane & 7) + ((lane >> 3) & 1) * 8;
    const int lk = (lane >> 4) * 8;
    uint32_t adA[2], adB[2];
#pragma unroll
    for (int t = 0; t < 2; t++) {
        adA[t] = sbase + 2 * ((wm + 16 * t + lrow) * KP + lk);
        adB[t] = sbase + 2 * (AV_P + (wn + 16 * t + lrow) * KP + lk);
    }
    const uint32_t bufB = AV_BUF * 2;

    float acc[2][4][4] = {};
    float runL = 0.0f;

    uint4 sv = *(const uint4*)Sp;
    float4 m0 = *(const float4*)mp;
    float4 m1 = *(const float4*)(mp + 4);
    uint4 vv;
    if (tid < 128) vv = *(const uint4*)Vp;

#pragma unroll 1
    for (int ks = 0; ks < 128; ks++) {
        const int buf = ks & 1;
        float2 s01 = __half22float2(*(__half2*)&sv.x);
        float2 s23 = __half22float2(*(__half2*)&sv.y);
        float2 s45 = __half22float2(*(__half2*)&sv.z);
        float2 s67 = __half22float2(*(__half2*)&sv.w);

        float pv[8];
        pv[0] = __expf(s01.x + m0.x); pv[1] = __expf(s01.y + m0.y);
        pv[2] = __expf(s23.x + m0.z); pv[3] = __expf(s23.y + m0.w);
        pv[4] = __expf(s45.x + m1.x); pv[5] = __expf(s45.y + m1.y);
        pv[6] = __expf(s67.x + m1.z); pv[7] = __expf(s67.y + m1.w);
        runL += ((pv[0] + pv[1]) + (pv[2] + pv[3])) + ((pv[4] + pv[5]) + (pv[6] + pv[7]));

        uint4 ph;
        ph.x = pack_h2(pv[0], pv[1]); ph.y = pack_h2(pv[2], pv[3]);
        ph.z = pack_h2(pv[4], pv[5]); ph.w = pack_h2(pv[6], pv[7]);

        __half* sbuf = sAB + buf * AV_BUF;
        *(uint4*)&sbuf[stsP] = ph;
        if (tid < 128) *(uint4*)&sbuf[stsV] = vv;

        if (ks < 127) {   // prefetch next iteration before the barrier
            sv = *(const uint4*)(Sp + (ks + 1) * 128);
            m0 = *(const float4*)(mp + (ks + 1) * 16);
            m1 = *(const float4*)(mp + (ks + 1) * 16 + 4);
            if (tid < 128) vv = *(const uint4*)(Vp + (ks + 1) * 16);
        }
        __syncthreads();

        uint32_t afr[2][4], bfr[2][4];
#pragma unroll
        for (int t = 0; t < 2; t++) {
            LDM4(afr[t], adA[t] + buf * bufB);
            LDM4(bfr[t], adB[t] + buf * bufB);
        }

#pragma unroll
        for (int mt = 0; mt < 2; mt++)
#pragma unroll
            for (int nt = 0; nt < 4; nt++) {
                int n2 = nt >> 1, j = nt & 1;
                MMA_F16(acc[mt][nt], afr[mt], bfr[n2][j], bfr[n2][j + 2]);
            }
    }

    runL += __shfl_xor_sync(0xffffffffu, runL, 1);
    if (!(tid & 1)) sL[tid >> 1] = runL;
    __syncthreads();

#pragma unroll
    for (int mt = 0; mt < 2; mt++) {
        int row0 = wm + 16 * mt + (lane >> 2);
        float inv0 = 1.0f / sL[row0];
        float inv1 = 1.0f / sL[row0 + 8];
#pragma unroll
        for (int nt = 0; nt < 4; nt++) {
            int col = wn + 8 * nt + 2 * (lane & 3);
            int nn = n0 + row0;
            *(float2*)&g_X[(size_t)(b * SEQ + nn) * CDIM + h * HDIM + col] =
                make_float2(acc[mt][nt][0] * inv0, acc[mt][nt][1] * inv0);
            *(float2*)&g_X[(size_t)(b * SEQ + nn + 8) * CDIM + h * HDIM + col] =
                make_float2(acc[mt][nt][2] * inv1, acc[mt][nt][3] * inv1);
        }
    }
}

// ---------------- launcher ------------------------------------------------
extern "C" void kernel_launch(void* const* d_in, const int* in_sizes, int n_in,
                              void* d_out, int out_size)
{
    const float* q   = (const float*)d_in[0];
    const float* k   = (const float*)d_in[1];
    const float* v   = (const float*)d_in[2];
    const float* svm = (const float*)d_in[3];
    const int*   sm  = (const int*)d_in[4];
    const float* Wq  = (const float*)d_in[5];
    const float* Wk  = (const float*)d_in[6];
    const float* Wv  = (const float*)d_in[7];
    const float* Wp  = (const float*)d_in[8];
    float* out = (float*)d_out;

    float* X;
    cudaGetSymbolAddress((void**)&X, g_X);

    cudaFuncSetAttribute(qk_mma_kernel,
                         cudaFuncAttributeMaxDynamicSharedMemorySize, QK_SMEM);

    // fused q/k/v projections: blockIdx.z selects projection
    proj_mma_kernel<<<dim3(CDIM / 128, (2 * SEQ) / 128, 3), 256>>>(
        q, k, v, Wq, Wk, Wv, nullptr, -1);

    qk_mma_kernel<<<dim3(SEQ / 128, SEQ / 128, NBH), 256, QK_SMEM>>>();

    argmax_reduce_kernel<<<(2 * NBH * SEQ) / 256, 256>>>();
    asso_kernel<<<(NBH * SEQ) / 256, 256>>>(sm, svm);

    av_mma_kernel<<<dim3(SEQ / 128, NBH), 256>>>();

    proj_mma_kernel<<<dim3(CDIM / 128, (2 * SEQ) / 128, 1), 256>>>(
        X, nullptr, nullptr, Wp, nullptr, nullptr, out, 3);
}

// round 17
// speedup vs baseline: 3.0544x; 1.0195x over previous
#include <cuda_runtime.h>
#include <cuda_fp16.h>
#include <cstdint>

#define SEQ   2048
#define HDIM  64
#define NHEAD 8
#define CDIM  512
#define NBH   16            // B*H
#define QKSCALE 0.125f
#define KP    24            // smem tile pitch in halfs (48B, ldmatrix conflict-free)
#define KP2   72            // qk128 operand pitch in halfs (144B)
#define OPSZ  (128 * KP2)   // halfs per operand array (9216)
#define QK_SMEM (4 * OPSZ * 2)   // 73728 B (argmax buffers overlay after sync)
#define PKP   24            // proj smem pitch (halfs)
#define PPLANE (128 * PKP)  // 3072 halfs per 128x16 plane
// av smem: single P plane (128x16) + single V plane (64x16) per buffer
#define AV_P  (128 * KP)    // 3072 halfs
#define AV_V  (64 * KP)     // 1536 halfs
#define AV_BUF (AV_P + AV_V)   // 4608 halfs = 9216 B

constexpr int NQe = NBH * SEQ * HDIM;   // 2,097,152 elements per plane

// ---------------- scratch (device globals; no allocation) ----------------
__device__ __half g_Qh2[2 * NBH * SEQ * HDIM];    // hi/lo fp16 planes (Q pre-scaled)
__device__ __half g_Kh2[2 * NBH * SEQ * HDIM];
__device__ __half g_Vt[NBH * HDIM * SEQ];         // V transposed, single fp16 plane
__device__ float g_X[2 * SEQ * CDIM];             // attention output fp32
// S now holds P = exp(s), fp16, tiled layout [bh][row/8][col/8][row%8][8 halfs]
__device__ __half g_S[(size_t)NBH * SEQ * SEQ];
__device__ int   g_q2k[NBH * SEQ];
__device__ int   g_k2q[NBH * SEQ];
__device__ __half g_mask[NBH * SEQ];              // softmax column mask {1,0}
__device__ float g_rpv[NBH * 16 * SEQ];
__device__ int   g_rpi[NBH * 16 * SEQ];
__device__ float g_cpv[NBH * 16 * SEQ];
__device__ int   g_cpi[NBH * 16 * SEQ];

#define MMA_F16(d, a, b0, b1)                                               \
    asm volatile("mma.sync.aligned.m16n8k16.row.col.f32.f16.f16.f32 "        \
                 "{%0,%1,%2,%3}, {%4,%5,%6,%7}, {%8,%9}, {%0,%1,%2,%3};"     \
                 : "+f"((d)[0]), "+f"((d)[1]), "+f"((d)[2]), "+f"((d)[3])    \
                 : "r"((a)[0]), "r"((a)[1]), "r"((a)[2]), "r"((a)[3]),       \
                   "r"(b0), "r"(b1))

#define LDM4(r, addr)                                                        \
    asm volatile("ldmatrix.sync.aligned.m8n8.x4.shared.b16 {%0,%1,%2,%3}, [%4];" \
                 : "=r"((r)[0]), "=r"((r)[1]), "=r"((r)[2]), "=r"((r)[3])    \
                 : "r"(addr))

__device__ __forceinline__ uint32_t pack_h2(float a, float b) {
    __half2 t;
    t.x = __float2half_rn(a);
    t.y = __float2half_rn(b);
    return *(uint32_t*)&t;
}

// split 8 fp32 values into hi/lo fp16 packs
__device__ __forceinline__ void split8(const float4& v0, const float4& v1,
                                       uint4& hi, uint4& lo) {
    float f[8] = { v0.x, v0.y, v0.z, v0.w, v1.x, v1.y, v1.z, v1.w };
    float h[8];
#pragma unroll
    for (int i = 0; i < 8; i++) h[i] = __half2float(__float2half_rn(f[i]));
    hi.x = pack_h2(f[0], f[1]); hi.y = pack_h2(f[2], f[3]);
    hi.z = pack_h2(f[4], f[5]); hi.w = pack_h2(f[6], f[7]);
    lo.x = pack_h2(f[0] - h[0], f[1] - h[1]);
    lo.y = pack_h2(f[2] - h[2], f[3] - h[3]);
    lo.z = pack_h2(f[4] - h[4], f[5] - h[5]);
    lo.w = pack_h2(f[6] - h[6], f[7] - h[7]);
}

// ---- projection GEMM via fp16 split-2 mma, 128x128 tile, fused cvt ------
// mode -1: fused q/k/v — blockIdx.z selects projection; mode 3: out-proj.
__global__ void __launch_bounds__(256, 2) proj_mma_kernel(
    const float* __restrict__ A0, const float* __restrict__ A1,
    const float* __restrict__ A2,
    const float* __restrict__ W0, const float* __restrict__ W1,
    const float* __restrict__ W2,
    float* __restrict__ outPlain, int mode)
{
    __shared__ __align__(16) __half sP[2 * 4 * PPLANE];   // 49152 B
    const int tid = threadIdx.x, lane = tid & 31, w = tid >> 5;
    const int r0 = blockIdx.y << 7, c0 = blockIdx.x << 7;
    const int wm = (w & 1) << 6, wn = (w >> 1) << 5;
    const int m = (mode < 0) ? (int)blockIdx.z : mode;

    const float* A = (m == 1) ? A1 : ((m == 2) ? A2 : A0);
    const float* W = (m == 1) ? W1 : ((m == 2) ? W2 : W0);

    const float* Ap = A + (size_t)(r0 + (tid >> 1)) * CDIM + (tid & 1) * 8;
    const float* Wp = W + (size_t)(c0 + (tid >> 1)) * CDIM + (tid & 1) * 8;
    const int sts = (tid >> 1) * PKP + (tid & 1) * 8;

    uint32_t sb = (uint32_t)__cvta_generic_to_shared(sP);
    const int lrow = (lane & 7) + ((lane >> 3) & 1) * 8;
    const int lk = (lane >> 4) * 8;
    uint32_t adA[2][4], adB[2][2];
#pragma unroll
    for (int p = 0; p < 2; p++) {
#pragma unroll
        for (int mt = 0; mt < 4; mt++)
            adA[p][mt] = sb + 2 * (p * PPLANE + (wm + 16 * mt + lrow) * PKP + lk);
#pragma unroll
        for (int g = 0; g < 2; g++)
            adB[p][g] = sb + 2 * ((2 + p) * PPLANE + (wn + 16 * g + lrow) * PKP + lk);
    }
    const uint32_t bufB = 4 * PPLANE * 2;

    float acc[4][4][4] = {};
    float4 a0 = *(const float4*)Ap;
    float4 a1 = *(const float4*)(Ap + 4);
    float4 w0 = *(const float4*)Wp;
    float4 w1 = *(const float4*)(Wp + 4);

#pragma unroll 1
    for (int ks = 0; ks < 32; ks++) {
        const int buf = ks & 1;
        uint4 ahi, alo, whi, wlo;
        split8(a0, a1, ahi, alo);
        split8(w0, w1, whi, wlo);

        __half* sbuf = sP + buf * 4 * PPLANE;
        *(uint4*)&sbuf[0 * PPLANE + sts] = ahi;
        *(uint4*)&sbuf[1 * PPLANE + sts] = alo;
        *(uint4*)&sbuf[2 * PPLANE + sts] = whi;
        *(uint4*)&sbuf[3 * PPLANE + sts] = wlo;

        if (ks < 31) {
            a0 = *(const float4*)(Ap + (ks + 1) * 16);
            a1 = *(const float4*)(Ap + (ks + 1) * 16 + 4);
            w0 = *(const float4*)(Wp + (ks + 1) * 16);
            w1 = *(const float4*)(Wp + (ks + 1) * 16 + 4);
        }
        __syncthreads();

        uint32_t bfr[2][2][4];
#pragma unroll
        for (int p = 0; p < 2; p++)
#pragma unroll
            for (int g = 0; g < 2; g++) LDM4(bfr[p][g], adB[p][g] + buf * bufB);
#pragma unroll
        for (int mt = 0; mt < 4; mt++) {
            uint32_t afr[2][4];
#pragma unroll
            for (int p = 0; p < 2; p++) LDM4(afr[p], adA[p][mt] + buf * bufB);
#pragma unroll
            for (int nt = 0; nt < 4; nt++) {
                int n2 = nt >> 1, j = nt & 1;
                MMA_F16(acc[mt][nt], afr[0], bfr[0][n2][j], bfr[0][n2][j + 2]); // hh
                MMA_F16(acc[mt][nt], afr[0], bfr[1][n2][j], bfr[1][n2][j + 2]); // hl
                MMA_F16(acc[mt][nt], afr[1], bfr[0][n2][j], bfr[0][n2][j + 2]); // lh
            }
        }
    }

    if (m == 0) {
#pragma unroll
        for (int mt = 0; mt < 4; mt++)
#pragma unroll
            for (int nt = 0; nt < 4; nt++)
#pragma unroll
                for (int e = 0; e < 4; e++) acc[mt][nt][e] *= QKSCALE;
    }

    // epilogue
#pragma unroll
    for (int mt = 0; mt < 4; mt++)
#pragma unroll
        for (int nt = 0; nt < 4; nt++)
#pragma unroll
            for (int hf = 0; hf < 2; hf++) {
                int row = r0 + wm + 16 * mt + (lane >> 2) + hf * 8;
                int col = c0 + wn + 8 * nt + 2 * (lane & 3);
                float v0 = acc[mt][nt][hf * 2];
                float v1 = acc[mt][nt][hf * 2 + 1];
                if (m == 3) {
                    *(float2*)&outPlain[(size_t)row * CDIM + col] = make_float2(v0, v1);
                } else if (m == 2) {
                    int b = row >> 11, n = row & 2047;
                    int hh = col >> 6, d = col & 63;
                    size_t idx = ((size_t)((b << 3) + hh) * HDIM + d) * SEQ + n;
                    g_Vt[idx] = __float2half_rn(v0);
                    g_Vt[idx + SEQ] = __float2half_rn(v1);
                } else {
                    int b = row >> 11, n = row & 2047;
                    int hh = col >> 6, d = col & 63;
                    __half h0 = __float2half_rn(v0), h1 = __float2half_rn(v1);
                    __half l0 = __float2half_rn(v0 - __half2float(h0));
                    __half l1 = __float2half_rn(v1 - __half2float(h1));
                    __half* OH = (m == 0) ? g_Qh2 : g_Kh2;
                    size_t idx = ((size_t)((b << 3) + hh) * SEQ + n) * HDIM + d;
                    __half2 hv; hv.x = h0; hv.y = h1;
                    __half2 lv; lv.x = l0; lv.y = l1;
                    *(__half2*)&OH[idx] = hv;
                    *(__half2*)&OH[NQe + idx] = lv;
                }
            }
}

// ---- P = exp(Qh @ Kh^T): 128x128 tile, register argmax, tiled P store ---
__global__ void __launch_bounds__(256, 2) qk_mma_kernel()
{
    extern __shared__ __align__(16) unsigned char smraw[];
    __half* sOp = (__half*)smraw;
    float* rv = (float*)smraw;                       // overlays operands post-sync
    int*   ri = (int*)(smraw + 2048);
    float* cv = (float*)(smraw + 4096);
    int*   ci = (int*)(smraw + 5120);

    const int tid = threadIdx.x, lane = tid & 31, w = tid >> 5;
    const int bh = blockIdx.z;
    const int r0 = blockIdx.y << 7, c0 = blockIdx.x << 7;
    const int wm = (w & 1) << 6;
    const int wn = (w >> 1) << 5;
    const int q4 = lane >> 2, l4 = lane & 3;

    const __half* bases[4] = {
        g_Qh2 + (size_t)bh * SEQ * HDIM, g_Qh2 + (size_t)NQe + (size_t)bh * SEQ * HDIM,
        g_Kh2 + (size_t)bh * SEQ * HDIM, g_Kh2 + (size_t)NQe + (size_t)bh * SEQ * HDIM };
#pragma unroll
    for (int idx = tid; idx < 4096; idx += 256) {
        int arr = idx >> 10, rem = idx & 1023, row = rem >> 3, c = rem & 7;
        int gr = ((arr < 2) ? r0 : c0) + row;
        uint4 v = *(const uint4*)(bases[arr] + (size_t)gr * HDIM + c * 8);
        *(uint4*)(sOp + arr * OPSZ + row * KP2 + c * 8) = v;
    }
    __syncthreads();

    uint32_t sb = (uint32_t)__cvta_generic_to_shared(sOp);
    const int lrow = (lane & 7) + ((lane >> 3) & 1) * 8;
    const int lk = (lane >> 4) * 8;
    uint32_t adA[2][4], adB[2][2];
#pragma unroll
    for (int p = 0; p < 2; p++) {
#pragma unroll
        for (int mt = 0; mt < 4; mt++)
            adA[p][mt] = sb + 2 * (p * OPSZ + (wm + 16 * mt + lrow) * KP2 + lk);
#pragma unroll
        for (int g = 0; g < 2; g++)
            adB[p][g] = sb + 2 * ((2 + p) * OPSZ + (wn + 16 * g + lrow) * KP2 + lk);
    }

    float acc[4][4][4] = {};
#pragma unroll
    for (int ks = 0; ks < 4; ks++) {
        uint32_t bfr[2][2][4];
#pragma unroll
        for (int p = 0; p < 2; p++)
#pragma unroll
            for (int g = 0; g < 2; g++) LDM4(bfr[p][g], adB[p][g] + ks * 32);
#pragma unroll
        for (int mt = 0; mt < 4; mt++) {
            uint32_t afr[2][4];
#pragma unroll
            for (int p = 0; p < 2; p++) LDM4(afr[p], adA[p][mt] + ks * 32);
#pragma unroll
            for (int nt = 0; nt < 4; nt++) {
                int n2 = nt >> 1, j = nt & 1;
                MMA_F16(acc[mt][nt], afr[0], bfr[0][n2][j], bfr[0][n2][j + 2]);
                MMA_F16(acc[mt][nt], afr[0], bfr[1][n2][j], bfr[1][n2][j + 2]);
                MMA_F16(acc[mt][nt], afr[1], bfr[0][n2][j], bfr[0][n2][j + 2]);
            }
        }
    }

    // ---- direct tiled fp16 P = exp(s) store (coalesced 4B/lane; MUFU) ----
    {
        __half* Sp = g_S + (size_t)bh * SEQ * SEQ + q4 * 8 + 2 * l4;
#pragma unroll
        for (int mt = 0; mt < 4; mt++)
#pragma unroll
            for (int hf = 0; hf < 2; hf++) {
                size_t rb = (size_t)(r0 + wm + 16 * mt + 8 * hf) * SEQ;
#pragma unroll
                for (int nt = 0; nt < 4; nt++) {
                    size_t off = rb + (size_t)(c0 + wn + 8 * nt) * 8;
                    *(uint32_t*)&Sp[off] =
                        pack_h2(__expf(acc[mt][nt][hf * 2]),
                                __expf(acc[mt][nt][hf * 2 + 1]));
                }
            }
    }

    // ---- row argmax in registers (exact fp32 s; first occurrence) ----
    float rbv[8]; int rbi[8];
#pragma unroll
    for (int mt = 0; mt < 4; mt++)
#pragma unroll
        for (int hf = 0; hf < 2; hf++) {
            float best = -3e38f; int bi = 0;
#pragma unroll
            for (int nt = 0; nt < 4; nt++)
#pragma unroll
                for (int j = 0; j < 2; j++) {
                    float v = acc[mt][nt][hf * 2 + j];
                    int idx = wn + 8 * nt + 2 * l4 + j;
                    if (v > best) { best = v; bi = idx; }
                }
            rbv[mt * 2 + hf] = best; rbi[mt * 2 + hf] = bi;
        }
#pragma unroll
    for (int o = 1; o < 4; o <<= 1)
#pragma unroll
        for (int r = 0; r < 8; r++) {
            float ov = __shfl_xor_sync(0xffffffffu, rbv[r], o);
            int   oi = __shfl_xor_sync(0xffffffffu, rbi[r], o);
            if (ov > rbv[r] || (ov == rbv[r] && oi < rbi[r])) { rbv[r] = ov; rbi[r] = oi; }
        }

    // ---- col argmax in registers ----
    float cbv[8]; int cbi[8];
#pragma unroll
    for (int nt = 0; nt < 4; nt++)
#pragma unroll
        for (int j = 0; j < 2; j++) {
            float best = -3e38f; int bi = 0;
#pragma unroll
            for (int mt = 0; mt < 4; mt++)
#pragma unroll
                for (int hf = 0; hf < 2; hf++) {
                    float v = acc[mt][nt][hf * 2 + j];
                    int row = wm + 16 * mt + q4 + 8 * hf;
                    if (v > best) { best = v; bi = row; }
                }
            cbv[nt * 2 + j] = best; cbi[nt * 2 + j] = bi;
        }
#pragma unroll
    for (int o = 4; o < 32; o <<= 1)
#pragma unroll
        for (int cc = 0; cc < 8; cc++) {
            float ov = __shfl_xor_sync(0xffffffffu, cbv[cc], o);
            int   oi = __shfl_xor_sync(0xffffffffu, cbi[cc], o);
            if (ov > cbv[cc] || (ov == cbv[cc] && oi < cbi[cc])) { cbv[cc] = ov; cbi[cc] = oi; }
        }

    __syncthreads();   // operands fully consumed; overlay argmax buffers

    if (l4 == 0) {
#pragma unroll
        for (int r = 0; r < 8; r++) {
            int row = wm + 16 * (r >> 1) + q4 + 8 * (r & 1);
            rv[(w >> 1) * 128 + row] = rbv[r];
            ri[(w >> 1) * 128 + row] = rbi[r];
        }
    }
    if (lane < 4) {
#pragma unroll
        for (int cc = 0; cc < 8; cc++) {
            int col = wn + 8 * (cc >> 1) + 2 * lane + (cc & 1);
            cv[(w & 1) * 128 + col] = cbv[cc];
            ci[(w & 1) * 128 + col] = cbi[cc];
        }
    }
    __syncthreads();

    if (tid < 128) {
        float best = rv[tid]; int bi = ri[tid];
#pragma unroll
        for (int g = 1; g < 4; g++) {
            float ov = rv[g * 128 + tid]; int oi = ri[g * 128 + tid];
            if (ov > best || (ov == best && oi < bi)) { best = ov; bi = oi; }
        }
        size_t p = (size_t)(bh * 16 + blockIdx.x) * SEQ + r0 + tid;
        g_rpv[p] = best; g_rpi[p] = c0 + bi;
    } else {
        int c = tid - 128;
        float best = cv[c]; int bi = ci[c];
        float ov = cv[128 + c]; int oi = ci[128 + c];
        if (ov > best || (ov == best && oi < bi)) { best = ov; bi = oi; }
        size_t p = (size_t)(bh * 16 + blockIdx.y) * SEQ + c0 + c;
        g_cpv[p] = best; g_cpi[p] = r0 + bi;
    }
}

// ---------------- reduce 16 partials -> q2k and k2q ----------------------
__global__ void argmax_reduce_kernel()
{
    int gid = blockIdx.x * blockDim.x + threadIdx.x;
    int which = gid >= NBH * SEQ;
    int i = gid & (NBH * SEQ - 1);
    int bh = i >> 11, n = i & 2047;
    const float* pv = which ? g_cpv : g_rpv;
    const int*   pi = which ? g_cpi : g_rpi;
    float v = -3e38f; int idx = 0;
#pragma unroll
    for (int t = 0; t < 16; t++) {
        size_t p = (size_t)(bh * 16 + t) * SEQ + n;
        float ov = pv[p];
        if (ov > v) { v = ov; idx = pi[p]; }
    }
    (which ? g_k2q : g_q2k)[i] = idx;
}

// ---------------- cycle consistency -> fp16 column mask {1,0} ------------
__global__ void asso_kernel(const int* __restrict__ smask,
                            const float* __restrict__ svalid)
{
    int i = blockIdx.x * blockDim.x + threadIdx.x;
    int bh = i >> 11, m = i & 2047;
    int b = bh >> 3;
    int kq = g_k2q[i];
    int remap = g_q2k[(bh << 11) + kq];
    float valid = (smask[(b << 11) + m] == smask[(b << 11) + remap])
                      ? svalid[(b << 11) + m] : 1.0f;
    // exp(valid * -10000): 1.0 when valid==0, 0.0 (underflow) when valid==1
    g_mask[i] = __float2half_rn(__expf(valid * -10000.0f));
}

// ---- masked P @ V + online row-sum, prefetched tiled P read -------------
__global__ void __launch_bounds__(256, 2) av_mma_kernel()
{
    __shared__ __align__(16) __half sAB[2 * AV_BUF];   // 18432 B
    __shared__ float sL[128];

    const int bh = blockIdx.y;
    const int n0 = blockIdx.x << 7;
    const int b = bh >> 3, h = bh & 7;
    const int tid = threadIdx.x, lane = tid & 31, w = tid >> 5;
    const int wm = (w & 3) << 5;       // 4 warps over 128 rows
    const int wn = (w >> 2) << 5;      // 2 warps over 64 cols

    const int n = n0 + (tid >> 1);
    const __half* Sp = g_S + (size_t)bh * SEQ * SEQ
                     + (size_t)(n & ~7) * SEQ + (tid & 1) * 64 + (n & 7) * 8;
    const __half* mp = g_mask + bh * SEQ + (tid & 1) * 8;
    const __half* Vp = g_Vt + (size_t)bh * HDIM * SEQ
                     + (size_t)(tid >> 1) * SEQ + (tid & 1) * 8;
    const int stsP = (tid >> 1) * KP + (tid & 1) * 8;
    const int stsV = AV_P + (tid >> 1) * KP + (tid & 1) * 8;

    uint32_t sbase = (uint32_t)__cvta_generic_to_shared(sAB);
    const int lrow = (lane & 7) + ((lane >> 3) & 1) * 8;
    const int lk = (lane >> 4) * 8;
    uint32_t adA[2], adB[2];
#pragma unroll
    for (int t = 0; t < 2; t++) {
        adA[t] = sbase + 2 * ((wm + 16 * t + lrow) * KP + lk);
        adB[t] = sbase + 2 * (AV_P + (wn + 16 * t + lrow) * KP + lk);
    }
    const uint32_t bufB = AV_BUF * 2;

    float acc[2][4][4] = {};
    float runL = 0.0f;

    uint4 sv = *(const uint4*)Sp;
    uint4 mv = *(const uint4*)mp;
    uint4 vv;
    if (tid < 128) vv = *(const uint4*)Vp;

#pragma unroll 1
    for (int ks = 0; ks < 128; ks++) {
        const int buf = ks & 1;
        // apply binary mask in half2 (exact: x*1 or x*0)
        __half2 pm0 = __hmul2(*(__half2*)&sv.x, *(__half2*)&mv.x);
        __half2 pm1 = __hmul2(*(__half2*)&sv.y, *(__half2*)&mv.y);
        __half2 pm2 = __hmul2(*(__half2*)&sv.z, *(__half2*)&mv.z);
        __half2 pm3 = __hmul2(*(__half2*)&sv.w, *(__half2*)&mv.w);

        float2 f0 = __half22float2(pm0);
        float2 f1 = __half22float2(pm1);
        float2 f2 = __half22float2(pm2);
        float2 f3 = __half22float2(pm3);
        runL += ((f0.x + f0.y) + (f1.x + f1.y)) + ((f2.x + f2.y) + (f3.x + f3.y));

        uint4 ph;
        ph.x = *(uint32_t*)&pm0; ph.y = *(uint32_t*)&pm1;
        ph.z = *(uint32_t*)&pm2; ph.w = *(uint32_t*)&pm3;

        __half* sbuf = sAB + buf * AV_BUF;
        *(uint4*)&sbuf[stsP] = ph;
        if (tid < 128) *(uint4*)&sbuf[stsV] = vv;

        if (ks < 127) {   // prefetch next iteration before the barrier
            sv = *(const uint4*)(Sp + (ks + 1) * 128);
            mv = *(const uint4*)(mp + (ks + 1) * 16);
            if (tid < 128) vv = *(const uint4*)(Vp + (ks + 1) * 16);
        }
        __syncthreads();

        uint32_t afr[2][4], bfr[2][4];
#pragma unroll
        for (int t = 0; t < 2; t++) {
            LDM4(afr[t], adA[t] + buf * bufB);
            LDM4(bfr[t], adB[t] + buf * bufB);
        }

#pragma unroll
        for (int mt = 0; mt < 2; mt++)
#pragma unroll
            for (int nt = 0; nt < 4; nt++) {
                int n2 = nt >> 1, j = nt & 1;
                MMA_F16(acc[mt][nt], afr[mt], bfr[n2][j], bfr[n2][j + 2]);
            }
    }

    runL += __shfl_xor_sync(0xffffffffu, runL, 1);
    if (!(tid & 1)) sL[tid >> 1] = runL;
    __syncthreads();

#pragma unroll
    for (int mt = 0; mt < 2; mt++) {
        int row0 = wm + 16 * mt + (lane >> 2);
        float inv0 = 1.0f / sL[row0];
        float inv1 = 1.0f / sL[row0 + 8];
#pragma unroll
        for (int nt = 0; nt < 4; nt++) {
            int col = wn + 8 * nt + 2 * (lane & 3);
            int nn = n0 + row0;
            *(float2*)&g_X[(size_t)(b * SEQ + nn) * CDIM + h * HDIM + col] =
                make_float2(acc[mt][nt][0] * inv0, acc[mt][nt][1] * inv0);
            *(float2*)&g_X[(size_t)(b * SEQ + nn + 8) * CDIM + h * HDIM + col] =
                make_float2(acc[mt][nt][2] * inv1, acc[mt][nt][3] * inv1);
        }
    }
}

// ---------------- launcher ------------------------------------------------
extern "C" void kernel_launch(void* const* d_in, const int* in_sizes, int n_in,
                              void* d_out, int out_size)
{
    const float* q   = (const float*)d_in[0];
    const float* k   = (const float*)d_in[1];
    const float* v   = (const float*)d_in[2];
    const float* svm = (const float*)d_in[3];
    const int*   sm  = (const int*)d_in[4];
    const float* Wq  = (const float*)d_in[5];
    const float* Wk  = (const float*)d_in[6];
    const float* Wv  = (const float*)d_in[7];
    const float* Wp  = (const float*)d_in[8];
    float* out = (float*)d_out;

    float* X;
    cudaGetSymbolAddress((void**)&X, g_X);

    cudaFuncSetAttribute(qk_mma_kernel,
                         cudaFuncAttributeMaxDynamicSharedMemorySize, QK_SMEM);

    proj_mma_kernel<<<dim3(CDIM / 128, (2 * SEQ) / 128, 3), 256>>>(
        q, k, v, Wq, Wk, Wv, nullptr, -1);

    qk_mma_kernel<<<dim3(SEQ / 128, SEQ / 128, NBH), 256, QK_SMEM>>>();

    argmax_reduce_kernel<<<(2 * NBH * SEQ) / 256, 256>>>();
    asso_kernel<<<(NBH * SEQ) / 256, 256>>>(sm, svm);

    av_mma_kernel<<<dim3(SEQ / 128, NBH), 256>>>();

    proj_mma_kernel<<<dim3(CDIM / 128, (2 * SEQ) / 128, 1), 256>>>(
        X, nullptr, nullptr, Wp, nullptr, nullptr, out, 3);
}